// round 5
// baseline (speedup 1.0000x reference)
#include <cuda_runtime.h>
#include <cuda_bf16.h>
#include <cstdint>

// ---------------------------------------------------------------------------
// Problem constants
// ---------------------------------------------------------------------------
constexpr int Bsz = 8;
constexpr int S   = 768;
constexpr int Hd  = 768;
constexpr int NH  = 12;
constexpr int NL  = 5;
constexpr int BS  = Bsz * S;                 // 6144 rows
constexpr long long HH = (long long)Hd * Hd; // 589824

typedef __nv_bfloat16 bf16;

// ---------------------------------------------------------------------------
// Scratch (static device globals)
// ---------------------------------------------------------------------------
__device__ float g_Q  [BS * Hd];
__device__ float g_K  [BS * Hd];
__device__ float g_V  [BS * Hd];
__device__ float g_ctx[BS * Hd];
__device__ float g_o  [BS * Hd];

__device__ bf16 g_hs_h [BS * Hd], g_hs_l [BS * Hd];
__device__ bf16 g_ctx_h[BS * Hd], g_ctx_l[BS * Hd];

__device__ bf16 g_inw_h[3 * Hd * Hd], g_inw_l[3 * Hd * Hd];
__device__ bf16 g_pw_h [Hd * Hd],     g_pw_l [Hd * Hd];
__device__ bf16 g_owT_h[Hd * Hd],     g_owT_l[Hd * Hd];

__device__ bf16 g_WqT_h[NL * Hd * Hd], g_WqT_l[NL * Hd * Hd];
__device__ bf16 g_WkT_h[NL * Hd * Hd], g_WkT_l[NL * Hd * Hd];
__device__ bf16 g_Wqc_h[NL * Hd * Hd], g_Wqc_l[NL * Hd * Hd];
__device__ bf16 g_Wkc_h[NL * Hd * Hd], g_Wkc_l[NL * Hd * Hd];
__device__ bf16 g_GT_h [NL * Hd * Hd], g_GT_l [NL * Hd * Hd];
__device__ bf16 g_WfT_h[NL * Hd * Hd], g_WfT_l[NL * Hd * Hd];
__device__ bf16 g_scr_h[NL * Hd * Hd], g_scr_l[NL * Hd * Hd];

__device__ float g_bqc [NL * Hd];
__device__ float g_bkc [NL * Hd];
__device__ float g_bfin[NL * Hd];

// chain nodes: normal + transposed, hi + lo
__device__ bf16 g_F_h [NL * 8 * Hd * Hd], g_F_l [NL * 8 * Hd * Hd];
__device__ bf16 g_FT_h[NL * 8 * Hd * Hd], g_FT_l[NL * 8 * Hd * Hd];
__device__ bf16 g_P1_h[NL * 4 * Hd * Hd], g_P1_l[NL * 4 * Hd * Hd];
__device__ bf16 g_QT1_h[NL * 4 * Hd * Hd], g_QT1_l[NL * 4 * Hd * Hd];
__device__ bf16 g_P2_h[NL * 2 * Hd * Hd], g_P2_l[NL * 2 * Hd * Hd];
__device__ bf16 g_QT2_h[NL * 2 * Hd * Hd], g_QT2_l[NL * 2 * Hd * Hd];
__device__ bf16 g_M_h [NL * Hd * Hd],     g_M_l [NL * Hd * Hd];
__device__ bf16 g_MT_h[NL * Hd * Hd],     g_MT_l[NL * Hd * Hd];

__device__ unsigned char g_fF [NL * 8];
__device__ unsigned char g_fP1[NL * 4];
__device__ unsigned char g_fP2[NL * 2];

// ---------------------------------------------------------------------------
// Small PTX helpers
// ---------------------------------------------------------------------------
__device__ __forceinline__ uint32_t smem_u32(const void* p) {
    return (uint32_t)__cvta_generic_to_shared(p);
}
__device__ __forceinline__ void cp16(uint32_t d, const void* s) {
    asm volatile("cp.async.cg.shared.global [%0], [%1], 16;"
                 :: "r"(d), "l"(s) : "memory");
}
__device__ __forceinline__ void cp_commit() {
    asm volatile("cp.async.commit_group;" ::: "memory");
}
template <int N>
__device__ __forceinline__ void cp_wait() {
    asm volatile("cp.async.wait_group %0;" :: "n"(N) : "memory");
}
__device__ __forceinline__ void ldsm4(uint32_t* r, uint32_t addr) {
    asm volatile("ldmatrix.sync.aligned.m8n8.x4.shared.b16 {%0,%1,%2,%3}, [%4];"
                 : "=r"(r[0]), "=r"(r[1]), "=r"(r[2]), "=r"(r[3]) : "r"(addr));
}
__device__ __forceinline__ void mma_bf16(float* d, const uint32_t* a,
                                         uint32_t b0, uint32_t b1) {
    asm volatile(
        "mma.sync.aligned.m16n8k16.row.col.f32.bf16.bf16.f32 "
        "{%0,%1,%2,%3}, {%4,%5,%6,%7}, {%8,%9}, {%0,%1,%2,%3};"
        : "+f"(d[0]), "+f"(d[1]), "+f"(d[2]), "+f"(d[3])
        : "r"(a[0]), "r"(a[1]), "r"(a[2]), "r"(a[3]), "r"(b0), "r"(b1));
}
__device__ __forceinline__ uint32_t pack_bf(bf16 a, bf16 b) {
    return (uint32_t)__bfloat16_as_ushort(a) |
           ((uint32_t)__bfloat16_as_ushort(b) << 16);
}

// ---------------------------------------------------------------------------
// GEMM config: 128x128 tile, BLK_K=32, 8 warps, 4-stage cp.async pipeline
// ---------------------------------------------------------------------------
constexpr int SKP     = 40;
constexpr int TILE_B  = 128 * SKP * 2;       // 10240 B per operand tile
constexpr int STAGE_B = 4 * TILE_B;          // 40960 B (Ah Al Wh Wl)
constexpr int NSTAGE  = 4;
constexpr int GEMM_SMEM = NSTAGE * STAGE_B;  // 163840 B

__device__ __forceinline__ void gemm_issue(
    const bf16* __restrict__ base, int lw, uint32_t sdst0, int kc)
{
    const bf16* g0 = base + kc * 32;
#pragma unroll
    for (int i = 0; i < 8; i++) {
        const int chunk = i * 64 + lw;
        const int row = chunk >> 2, cs = chunk & 3;
        cp16(sdst0 + row * (SKP * 2) + cs * 16,
             g0 + (long long)row * Hd + cs * 8);
    }
}

// MODE 0: fp32 out (+bias). MODE 1: bf16 hi/lo out. MODE 2: bf16 + transposed.
template <int MODE>
__device__ void gemm_core(
    const bf16* __restrict__ Ah, const bf16* __restrict__ Al,
    const bf16* __restrict__ Wh, const bf16* __restrict__ Wl,
    const float* __restrict__ bias,
    float* __restrict__ C,
    bf16* __restrict__ Ch, bf16* __restrict__ Cl,
    bf16* __restrict__ Th, bf16* __restrict__ Tl,
    int m0, int n0)
{
    extern __shared__ char dsm[];
    const int tid = threadIdx.x;
    const int wid = tid >> 5, lane = tid & 31;
    const int m_off = (wid & 3) * 32;
    const int n_off = (wid >> 2) * 64;
    const uint32_t sbase = smem_u32(dsm);

    const int ltile = tid >> 6;
    const int lw = tid & 63;
    const bf16* gbase =
        (ltile == 0) ? Ah + (long long)m0 * Hd :
        (ltile == 1) ? Al + (long long)m0 * Hd :
        (ltile == 2) ? Wh + (long long)n0 * Hd :
                       Wl + (long long)n0 * Hd;
    const uint32_t sdst_tile = ltile * TILE_B;

    // prologue: stages 0..2 in flight
#pragma unroll
    for (int p = 0; p < NSTAGE - 1; p++) {
        gemm_issue(gbase, lw, sbase + p * STAGE_B + sdst_tile, p);
        cp_commit();
    }

    float acc[2][8][4];
#pragma unroll
    for (int mi = 0; mi < 2; mi++)
#pragma unroll
        for (int j = 0; j < 8; j++)
#pragma unroll
            for (int e = 0; e < 4; e++) acc[mi][j][e] = 0.f;

    const int r_off = ((lane >> 3) & 1) * 8 + (lane & 7);
    const int c_off = (lane >> 4) * 8;

    for (int kc = 0; kc < 24; kc++) {
        cp_wait<NSTAGE - 2>();          // group kc complete (uniform commits)
        __syncthreads();
        const uint32_t sb = sbase + (kc & (NSTAGE - 1)) * STAGE_B;
        const uint32_t aAh = sb + (m_off + r_off) * (SKP * 2) + c_off * 2;
        const uint32_t aAl = aAh + TILE_B;
        const uint32_t aWh = sb + 2 * TILE_B + (n_off + r_off) * (SKP * 2) + c_off * 2;
        const uint32_t aWl = aWh + TILE_B;

#pragma unroll
        for (int kk = 0; kk < 2; kk++) {
            uint32_t ah[2][4], alr[2][4];
#pragma unroll
            for (int t = 0; t < 2; t++) {
                ldsm4(ah[t],  aAh + t * 16 * (SKP * 2) + kk * 32);
                ldsm4(alr[t], aAl + t * 16 * (SKP * 2) + kk * 32);
            }
#pragma unroll
            for (int u = 0; u < 4; u++) {
                uint32_t bh[4];
                ldsm4(bh, aWh + u * 16 * (SKP * 2) + kk * 32);
#pragma unroll
                for (int mi = 0; mi < 2; mi++) {
                    mma_bf16(acc[mi][2 * u],     ah[mi],  bh[0], bh[2]);
                    mma_bf16(acc[mi][2 * u + 1], ah[mi],  bh[1], bh[3]);
                    mma_bf16(acc[mi][2 * u],     alr[mi], bh[0], bh[2]);
                    mma_bf16(acc[mi][2 * u + 1], alr[mi], bh[1], bh[3]);
                }
                uint32_t bl[4];
                ldsm4(bl, aWl + u * 16 * (SKP * 2) + kk * 32);
#pragma unroll
                for (int mi = 0; mi < 2; mi++) {
                    mma_bf16(acc[mi][2 * u],     ah[mi], bl[0], bl[2]);
                    mma_bf16(acc[mi][2 * u + 1], ah[mi], bl[1], bl[3]);
                }
            }
        }
        // issue stage kc+3 (overwrites stage (kc-1)%4: all warps past top barrier)
        if (kc + NSTAGE - 1 < 24)
            gemm_issue(gbase, lw,
                       sbase + ((kc + NSTAGE - 1) & (NSTAGE - 1)) * STAGE_B + sdst_tile,
                       kc + NSTAGE - 1);
        cp_commit();                    // uniform commit keeps group count exact
    }
    __syncthreads();

    // stage accumulators through SMEM (f32 [128][132]); overlaps stages 0-1
    // whose groups are complete; in-flight tail groups target stages 2-3.
    float* sf = (float*)dsm;
    const int g = lane >> 2, t2 = (lane & 3) * 2;
#pragma unroll
    for (int mi = 0; mi < 2; mi++)
#pragma unroll
        for (int j = 0; j < 8; j++) {
            const int r = m_off + mi * 16 + g;
            const int c = n_off + j * 8 + t2;
            sf[r * 132 + c]           = acc[mi][j][0];
            sf[r * 132 + c + 1]       = acc[mi][j][1];
            sf[(r + 8) * 132 + c]     = acc[mi][j][2];
            sf[(r + 8) * 132 + c + 1] = acc[mi][j][3];
        }
    __syncthreads();

    if (MODE == 0) {
#pragma unroll 4
        for (int i = 0; i < 16; i++) {
            const int task = i * 256 + tid;
            const int row = task >> 5, c4 = (task & 31) * 4;
            float4 v = *(float4*)&sf[row * 132 + c4];
            v.x += bias[n0 + c4 + 0];
            v.y += bias[n0 + c4 + 1];
            v.z += bias[n0 + c4 + 2];
            v.w += bias[n0 + c4 + 3];
            *(float4*)(C + (long long)(m0 + row) * Hd + n0 + c4) = v;
        }
    } else {
#pragma unroll 4
        for (int i = 0; i < 16; i++) {
            const int task = i * 256 + tid;
            const int row = task >> 5, c4 = (task & 31) * 4;
            float4 v = *(float4*)&sf[row * 132 + c4];
            bf16 h0 = __float2bfloat16(v.x), h1 = __float2bfloat16(v.y);
            bf16 h2 = __float2bfloat16(v.z), h3 = __float2bfloat16(v.w);
            bf16 l0 = __float2bfloat16(v.x - __bfloat162float(h0));
            bf16 l1 = __float2bfloat16(v.y - __bfloat162float(h1));
            bf16 l2 = __float2bfloat16(v.z - __bfloat162float(h2));
            bf16 l3 = __float2bfloat16(v.w - __bfloat162float(h3));
            const long long off = (long long)(m0 + row) * Hd + n0 + c4;
            *(uint2*)(Ch + off) = make_uint2(pack_bf(h0, h1), pack_bf(h2, h3));
            *(uint2*)(Cl + off) = make_uint2(pack_bf(l0, l1), pack_bf(l2, l3));
        }
        if (MODE == 2) {
            const int c = tid & 127;
            const int half = tid >> 7;
#pragma unroll 4
            for (int i = 0; i < 16; i++) {
                const int r4 = half * 64 + i * 4;
                float v0 = sf[(r4 + 0) * 132 + c];
                float v1 = sf[(r4 + 1) * 132 + c];
                float v2 = sf[(r4 + 2) * 132 + c];
                float v3 = sf[(r4 + 3) * 132 + c];
                bf16 h0 = __float2bfloat16(v0), h1 = __float2bfloat16(v1);
                bf16 h2 = __float2bfloat16(v2), h3 = __float2bfloat16(v3);
                bf16 l0 = __float2bfloat16(v0 - __bfloat162float(h0));
                bf16 l1 = __float2bfloat16(v1 - __bfloat162float(h1));
                bf16 l2 = __float2bfloat16(v2 - __bfloat162float(h2));
                bf16 l3 = __float2bfloat16(v3 - __bfloat162float(h3));
                const long long off = (long long)(n0 + c) * Hd + m0 + r4;
                *(uint2*)(Th + off) = make_uint2(pack_bf(h0, h1), pack_bf(h2, h3));
                *(uint2*)(Tl + off) = make_uint2(pack_bf(l0, l1), pack_bf(l2, l3));
            }
        }
    }
}

// ---------------------------------------------------------------------------
// GEMM wrappers (NO forced min-blocks: avoid register spills)
// ---------------------------------------------------------------------------
__global__ __launch_bounds__(256) void k_final(
    const bf16* __restrict__ Ah, const bf16* __restrict__ Al,
    const bf16* __restrict__ WTh, const bf16* __restrict__ WTl,
    const float* __restrict__ bias, const int* __restrict__ lang,
    float* __restrict__ C)
{
    const int z = blockIdx.z;
    const int lg = __ldg(&lang[z]);
    const long long ao = (long long)z * S * Hd;
    gemm_core<0>(Ah + ao, Al + ao, WTh + (long long)lg * HH, WTl + (long long)lg * HH,
                 bias + lg * Hd, C + ao, nullptr, nullptr, nullptr, nullptr,
                 blockIdx.y * 128, blockIdx.x * 128);
}

__global__ __launch_bounds__(256) void k_qkv(
    const bf16* __restrict__ hs_h, const bf16* __restrict__ hs_l,
    const bf16* __restrict__ Wqc_h, const bf16* __restrict__ Wqc_l,
    const float* __restrict__ bqc,
    const bf16* __restrict__ Wkc_h, const bf16* __restrict__ Wkc_l,
    const float* __restrict__ bkc,
    const bf16* __restrict__ wv_h, const bf16* __restrict__ wv_l,
    const float* __restrict__ bv,
    const int* __restrict__ lang,
    float* __restrict__ Q, float* __restrict__ K, float* __restrict__ V)
{
    const int z = blockIdx.z;
    const int kind = z >> 3, b = z & 7;
    const int lg = __ldg(&lang[b]);
    const long long ao = (long long)b * S * Hd;
    const bf16 *wh, *wl;
    const float* bias;
    float* C;
    if (kind == 0) {
        wh = Wqc_h + (long long)lg * HH; wl = Wqc_l + (long long)lg * HH;
        bias = bqc + lg * Hd; C = Q;
    } else if (kind == 1) {
        wh = Wkc_h + (long long)lg * HH; wl = Wkc_l + (long long)lg * HH;
        bias = bkc + lg * Hd; C = K;
    } else {
        wh = wv_h; wl = wv_l; bias = bv; C = V;
    }
    gemm_core<0>(hs_h + ao, hs_l + ao, wh, wl, bias, C + ao,
                 nullptr, nullptr, nullptr, nullptr,
                 blockIdx.y * 128, blockIdx.x * 128);
}

__global__ __launch_bounds__(256) void k_wcomb(
    const bf16* __restrict__ inw_h, const bf16* __restrict__ inw_l,
    const bf16* __restrict__ WqT_h, const bf16* __restrict__ WqT_l,
    const bf16* __restrict__ WkT_h, const bf16* __restrict__ WkT_l,
    bf16* __restrict__ Wqc_h, bf16* __restrict__ Wqc_l,
    bf16* __restrict__ Wkc_h, bf16* __restrict__ Wkc_l)
{
    const int z = blockIdx.z;
    const int fam = z / NL, l = z % NL;
    const long long lo = (long long)l * HH;
    const bf16* Ah = inw_h + (long long)fam * HH;
    const bf16* Al = inw_l + (long long)fam * HH;
    const bf16* Wh = (fam ? WkT_h : WqT_h) + lo;
    const bf16* Wl = (fam ? WkT_l : WqT_l) + lo;
    bf16* Ch = (fam ? Wkc_h : Wqc_h) + lo;
    bf16* Cl = (fam ? Wkc_l : Wqc_l) + lo;
    gemm_core<1>(Ah, Al, Wh, Wl, nullptr, nullptr, Ch, Cl, nullptr, nullptr,
                 blockIdx.y * 128, blockIdx.x * 128);
}

__global__ __launch_bounds__(256) void k_G(
    const bf16* __restrict__ M_h, const bf16* __restrict__ M_l,
    const bf16* __restrict__ pw_h, const bf16* __restrict__ pw_l,
    bf16* __restrict__ scr_h, bf16* __restrict__ scr_l,
    bf16* __restrict__ GT_h, bf16* __restrict__ GT_l)
{
    const long long lo = (long long)blockIdx.z * HH;
    gemm_core<2>(M_h + lo, M_l + lo, pw_h, pw_l, nullptr, nullptr,
                 scr_h + lo, scr_l + lo, GT_h + lo, GT_l + lo,
                 blockIdx.y * 128, blockIdx.x * 128);
}

__global__ __launch_bounds__(256) void k_Wfin(
    const bf16* __restrict__ owT_h, const bf16* __restrict__ owT_l,
    const bf16* __restrict__ GT_h, const bf16* __restrict__ GT_l,
    bf16* __restrict__ scr_h, bf16* __restrict__ scr_l,
    bf16* __restrict__ WfT_h, bf16* __restrict__ WfT_l)
{
    const long long lo = (long long)blockIdx.z * HH;
    gemm_core<2>(owT_h, owT_l, GT_h + lo, GT_l + lo, nullptr, nullptr,
                 scr_h + lo, scr_l + lo, WfT_h + lo, WfT_l + lo,
                 blockIdx.y * 128, blockIdx.x * 128);
}

__global__ __launch_bounds__(256) void tc_chain(
    const bf16* __restrict__ sN_h, const bf16* __restrict__ sN_l,
    const bf16* __restrict__ sT_h, const bf16* __restrict__ sT_l,
    const unsigned char* __restrict__ fs,
    bf16* __restrict__ dN_h, bf16* __restrict__ dN_l,
    bf16* __restrict__ dT_h, bf16* __restrict__ dT_l,
    int spa, int dpa)
{
    const int z = blockIdx.z;
    const int a = z / dpa, p = z - a * dpa;
    const int li = a * spa + 2 * p;
    const unsigned char f1 = fs[li], f2 = fs[li + 1];
    const long long zo = (long long)z * HH;
    const int m0 = blockIdx.y * 128, n0 = blockIdx.x * 128;
    const int tid = threadIdx.x;

    if (f1 & f2) {
#pragma unroll 4
        for (int i = 0; i < 16; i++) {
            const int task = i * 256 + tid;
            const int row = task >> 5, c4 = (task & 31) * 4;
            const int gr = m0 + row, gc = n0 + c4;
            bf16 one = __float2bfloat16(1.f), zero = __float2bfloat16(0.f);
            bf16 h0 = (gc + 0 == gr) ? one : zero;
            bf16 h1 = (gc + 1 == gr) ? one : zero;
            bf16 h2 = (gc + 2 == gr) ? one : zero;
            bf16 h3 = (gc + 3 == gr) ? one : zero;
            const long long off = zo + (long long)gr * Hd + gc;
            uint2 hv = make_uint2(pack_bf(h0, h1), pack_bf(h2, h3));
            uint2 lv = make_uint2(0u, 0u);
            *(uint2*)(dN_h + off) = hv; *(uint2*)(dN_l + off) = lv;
            *(uint2*)(dT_h + off) = hv; *(uint2*)(dT_l + off) = lv;
        }
        return;
    }
    if (f1 | f2) {
        const long long so = (long long)(f1 ? li + 1 : li) * HH;
#pragma unroll 4
        for (int i = 0; i < 8; i++) {
            const int idx = i * 256 + tid;
            const int row = idx >> 4, c8 = (idx & 15) * 8;
            const long long doff = zo + (long long)(m0 + row) * Hd + n0 + c8;
            const long long soff = so + (long long)(m0 + row) * Hd + n0 + c8;
            *(uint4*)(dN_h + doff) = *(const uint4*)(sN_h + soff);
            *(uint4*)(dN_l + doff) = *(const uint4*)(sN_l + soff);
            *(uint4*)(dT_h + doff) = *(const uint4*)(sT_h + soff);
            *(uint4*)(dT_l + doff) = *(const uint4*)(sT_l + soff);
        }
        return;
    }
    gemm_core<2>(sN_h + (long long)li * HH, sN_l + (long long)li * HH,
                 sT_h + (long long)(li + 1) * HH, sT_l + (long long)(li + 1) * HH,
                 nullptr, nullptr,
                 dN_h + zo, dN_l + zo, dT_h + zo, dT_l + zo, m0, n0);
}

// ---------------------------------------------------------------------------
// conversions
// ---------------------------------------------------------------------------
__global__ __launch_bounds__(256) void k_conv(
    const float* __restrict__ src, bf16* __restrict__ dh, bf16* __restrict__ dl)
{
    const long long i4 = ((long long)blockIdx.x * 256 + threadIdx.x) * 4;
    float4 v = *(const float4*)(src + i4);
    bf16 h0 = __float2bfloat16(v.x), h1 = __float2bfloat16(v.y);
    bf16 h2 = __float2bfloat16(v.z), h3 = __float2bfloat16(v.w);
    bf16 l0 = __float2bfloat16(v.x - __bfloat162float(h0));
    bf16 l1 = __float2bfloat16(v.y - __bfloat162float(h1));
    bf16 l2 = __float2bfloat16(v.z - __bfloat162float(h2));
    bf16 l3 = __float2bfloat16(v.w - __bfloat162float(h3));
    *(uint2*)(dh + i4) = make_uint2(pack_bf(h0, h1), pack_bf(h2, h3));
    *(uint2*)(dl + i4) = make_uint2(pack_bf(l0, l1), pack_bf(l2, l3));
}

__device__ __forceinline__ void split_store4(
    bf16* dh, bf16* dl, long long off, float x, float y, float z, float w)
{
    bf16 h0 = __float2bfloat16(x), h1 = __float2bfloat16(y);
    bf16 h2 = __float2bfloat16(z), h3 = __float2bfloat16(w);
    bf16 l0 = __float2bfloat16(x - __bfloat162float(h0));
    bf16 l1 = __float2bfloat16(y - __bfloat162float(h1));
    bf16 l2 = __float2bfloat16(z - __bfloat162float(h2));
    bf16 l3 = __float2bfloat16(w - __bfloat162float(h3));
    *(uint2*)(dh + off) = make_uint2(pack_bf(h0, h1), pack_bf(h2, h3));
    *(uint2*)(dl + off) = make_uint2(pack_bf(l0, l1), pack_bf(l2, l3));
}

__global__ __launch_bounds__(256) void k_convT(
    const float* __restrict__ src, bf16* __restrict__ dh, bf16* __restrict__ dl)
{
    const int node = blockIdx.y;
    const float* sm = src + (long long)node * HH;
    const long long i4 = ((long long)blockIdx.x * 256 + threadIdx.x) * 4;
    const int r = (int)(i4 / Hd), c = (int)(i4 % Hd);
    float t0 = sm[(long long)(c + 0) * Hd + r];
    float t1 = sm[(long long)(c + 1) * Hd + r];
    float t2 = sm[(long long)(c + 2) * Hd + r];
    float t3 = sm[(long long)(c + 3) * Hd + r];
    split_store4(dh, dl, (long long)node * HH + i4, t0, t1, t2, t3);
}

// ---------------------------------------------------------------------------
// chain flags + leaf factors
// ---------------------------------------------------------------------------
__global__ void k_flags(const int* __restrict__ lang,
                        unsigned char* fF, unsigned char* fP1, unsigned char* fP2)
{
    if (threadIdx.x == 0 && blockIdx.x == 0) {
        for (int a = 0; a < NL; a++) {
            for (int j = 0; j < 8; j++) fF[a * 8 + j] = (lang[j] == a) ? 1 : 0;
            for (int p = 0; p < 4; p++)
                fP1[a * 4 + p] = fF[a * 8 + 2 * p] & fF[a * 8 + 2 * p + 1];
            for (int p = 0; p < 2; p++)
                fP2[a * 2 + p] = fP1[a * 4 + 2 * p] & fP1[a * 4 + 2 * p + 1];
        }
    }
}

__global__ __launch_bounds__(256) void k_factors(
    const float* __restrict__ alignT, const int* __restrict__ lang,
    bf16* __restrict__ Fh, bf16* __restrict__ Fl,
    bf16* __restrict__ FTh, bf16* __restrict__ FTl)
{
    const int node = blockIdx.y;
    const int a = node >> 3, j = node & 7;
    const int c = __ldg(&lang[j]);
    const long long nb = (long long)node * HH;
    const long long i4 = ((long long)blockIdx.x * 256 + threadIdx.x) * 4;
    const int r = (int)(i4 / Hd), col = (int)(i4 % Hd);

    if (c == a) {
        float v0 = (col + 0 == r) ? 1.f : 0.f;
        float v1 = (col + 1 == r) ? 1.f : 0.f;
        float v2 = (col + 2 == r) ? 1.f : 0.f;
        float v3 = (col + 3 == r) ? 1.f : 0.f;
        split_store4(Fh,  Fl,  nb + i4, v0, v1, v2, v3);
        split_store4(FTh, FTl, nb + i4, v0, v1, v2, v3);
    } else {
        const float* sm = alignT + (long long)(a * NL + c) * HH;
        float4 v = *(const float4*)(sm + i4);
        split_store4(Fh, Fl, nb + i4, v.x, v.y, v.z, v.w);
        float t0 = sm[(long long)(col + 0) * Hd + r];
        float t1 = sm[(long long)(col + 1) * Hd + r];
        float t2 = sm[(long long)(col + 2) * Hd + r];
        float t3 = sm[(long long)(col + 3) * Hd + r];
        split_store4(FTh, FTl, nb + i4, t0, t1, t2, t3);
    }
}

// ---------------------------------------------------------------------------
// bias precompute
// ---------------------------------------------------------------------------
__global__ void k_bias_qk(
    const float* __restrict__ in_w, const float* __restrict__ in_b,
    const float* __restrict__ bq_lang, const float* __restrict__ bk_lang,
    float* __restrict__ bqc, float* __restrict__ bkc)
{
    const int fam = blockIdx.x, l = blockIdx.y, o = threadIdx.x;
    const float* wrow = in_w + (long long)(fam * Hd + o) * Hd;
    const float* bl = (fam ? bk_lang : bq_lang) + l * Hd;
    float s = 0.f;
    for (int k = 0; k < Hd; k++) s += wrow[k] * bl[k];
    float* dst = fam ? bkc : bqc;
    dst[l * Hd + o] = s + in_b[fam * Hd + o];
}

__global__ void k_bias_fin(
    const bf16* __restrict__ GT_h, const bf16* __restrict__ GT_l,
    const float* __restrict__ out_b, const float* __restrict__ proj_b,
    float* __restrict__ bfin)
{
    const int l = blockIdx.x, n = threadIdx.x;
    const bf16* rh = GT_h + (long long)l * HH + (long long)n * Hd;
    const bf16* rl = GT_l + (long long)l * HH + (long long)n * Hd;
    float s = 0.f;
    for (int k = 0; k < Hd; k++)
        s += out_b[k] * (__bfloat162float(rh[k]) + __bfloat162float(rl[k]));
    bfin[l * Hd + n] = s + proj_b[n];
}

// ---------------------------------------------------------------------------
// Flash attention (fp32 SIMT)
// ---------------------------------------------------------------------------
__global__ __launch_bounds__(256) void k_attn(
    const float* __restrict__ Q, const float* __restrict__ K,
    const float* __restrict__ V, float* __restrict__ O)
{
    __shared__ float Qs[64 * 64];
    __shared__ float KP[64 * 64];
    __shared__ float Vs[64 * 64];

    const int qt = blockIdx.x, h = blockIdx.y, b = blockIdx.z;
    const int tid = threadIdx.x;
    const int ty = tid >> 4, tx = tid & 15;
    const long long qbase = ((long long)(b * S + qt * 64)) * Hd + h * 64;

#pragma unroll
    for (int u = 0; u < 4; u++) {
        const int fidx = u * 256 + tid;
        const int r = fidx >> 4;
        const int d = (fidx & 15) * 4;
        float4 v = *(const float4*)(Q + qbase + (long long)r * Hd + d);
        v.x *= 0.125f; v.y *= 0.125f; v.z *= 0.125f; v.w *= 0.125f;
        *(float4*)&Qs[r * 64 + d] = v;
    }

    float m[4], l[4], o[4][4];
#pragma unroll
    for (int i = 0; i < 4; i++) {
        m[i] = -1e30f; l[i] = 0.f;
#pragma unroll
        for (int j = 0; j < 4; j++) o[i][j] = 0.f;
    }

    for (int kt = 0; kt < S / 64; kt++) {
        const long long kbase = ((long long)(b * S + kt * 64)) * Hd + h * 64;
        __syncthreads();
#pragma unroll
        for (int u = 0; u < 4; u++) {
            const int fidx = u * 256 + tid;
            const int r = fidx >> 4;
            const int d = (fidx & 15) * 4;
            float4 kv = *(const float4*)(K + kbase + (long long)r * Hd + d);
            KP[(d + 0) * 64 + r] = kv.x;
            KP[(d + 1) * 64 + r] = kv.y;
            KP[(d + 2) * 64 + r] = kv.z;
            KP[(d + 3) * 64 + r] = kv.w;
            *(float4*)&Vs[r * 64 + d] =
                *(const float4*)(V + kbase + (long long)r * Hd + d);
        }
        __syncthreads();

        float s[4][4];
#pragma unroll
        for (int i = 0; i < 4; i++)
#pragma unroll
            for (int j = 0; j < 4; j++) s[i][j] = 0.f;

#pragma unroll
        for (int d0 = 0; d0 < 64; d0 += 4) {
            float a0[4], a1[4], a2[4], a3[4];
            *(float4*)a0 = *(const float4*)&Qs[(ty * 4 + 0) * 64 + d0];
            *(float4*)a1 = *(const float4*)&Qs[(ty * 4 + 1) * 64 + d0];
            *(float4*)a2 = *(const float4*)&Qs[(ty * 4 + 2) * 64 + d0];
            *(float4*)a3 = *(const float4*)&Qs[(ty * 4 + 3) * 64 + d0];
#pragma unroll
            for (int dd = 0; dd < 4; dd++) {
                const float b0 = KP[(d0 + dd) * 64 + tx];
                const float b1 = KP[(d0 + dd) * 64 + tx + 16];
                const float b2 = KP[(d0 + dd) * 64 + tx + 32];
                const float b3 = KP[(d0 + dd) * 64 + tx + 48];
                s[0][0] += a0[dd] * b0; s[0][1] += a0[dd] * b1;
                s[0][2] += a0[dd] * b2; s[0][3] += a0[dd] * b3;
                s[1][0] += a1[dd] * b0; s[1][1] += a1[dd] * b1;
                s[1][2] += a1[dd] * b2; s[1][3] += a1[dd] * b3;
                s[2][0] += a2[dd] * b0; s[2][1] += a2[dd] * b1;
                s[2][2] += a2[dd] * b2; s[2][3] += a2[dd] * b3;
                s[3][0] += a3[dd] * b0; s[3][1] += a3[dd] * b1;
                s[3][2] += a3[dd] * b2; s[3][3] += a3[dd] * b3;
            }
        }

        float p[4][4];
#pragma unroll
        for (int i = 0; i < 4; i++) {
            float mx = fmaxf(fmaxf(s[i][0], s[i][1]), fmaxf(s[i][2], s[i][3]));
#pragma unroll
            for (int off = 8; off >= 1; off >>= 1)
                mx = fmaxf(mx, __shfl_xor_sync(0xffffffffu, mx, off));
            const float mn = fmaxf(m[i], mx);
            const float alpha = __expf(m[i] - mn);
            m[i] = mn;
            float rs = 0.f;
#pragma unroll
            for (int j = 0; j < 4; j++) {
                p[i][j] = __expf(s[i][j] - mn);
                rs += p[i][j];
            }
#pragma unroll
            for (int off = 8; off >= 1; off >>= 1)
                rs += __shfl_xor_sync(0xffffffffu, rs, off);
            l[i] = l[i] * alpha + rs;
            o[i][0] *= alpha; o[i][1] *= alpha;
            o[i][2] *= alpha; o[i][3] *= alpha;
        }

        __syncthreads();
#pragma unroll
        for (int i = 0; i < 4; i++)
#pragma unroll
            for (int j = 0; j < 4; j++)
                KP[(ty * 4 + i) * 64 + tx + 16 * j] = p[i][j];
        __syncthreads();

#pragma unroll
        for (int k = 0; k < 64; k++) {
            const float4 v = *(const float4*)&Vs[k * 64 + tx * 4];
            const float p0 = KP[(ty * 4 + 0) * 64 + k];
            const float p1 = KP[(ty * 4 + 1) * 64 + k];
            const float p2 = KP[(ty * 4 + 2) * 64 + k];
            const float p3 = KP[(ty * 4 + 3) * 64 + k];
            o[0][0] += p0 * v.x; o[0][1] += p0 * v.y; o[0][2] += p0 * v.z; o[0][3] += p0 * v.w;
            o[1][0] += p1 * v.x; o[1][1] += p1 * v.y; o[1][2] += p1 * v.z; o[1][3] += p1 * v.w;
            o[2][0] += p2 * v.x; o[2][1] += p2 * v.y; o[2][2] += p2 * v.z; o[2][3] += p2 * v.w;
            o[3][0] += p3 * v.x; o[3][1] += p3 * v.y; o[3][2] += p3 * v.z; o[3][3] += p3 * v.w;
        }
    }

#pragma unroll
    for (int i = 0; i < 4; i++) {
        const float inv = 1.f / l[i];
        float4 v = make_float4(o[i][0] * inv, o[i][1] * inv,
                               o[i][2] * inv, o[i][3] * inv);
        *(float4*)(O + qbase + (long long)(ty * 4 + i) * Hd + tx * 4) = v;
    }
}

// ---------------------------------------------------------------------------
// Residual + LayerNorm
// ---------------------------------------------------------------------------
__global__ __launch_bounds__(256) void k_ln(
    const float* __restrict__ X, const float* __restrict__ Rres,
    const float* __restrict__ gam, const float* __restrict__ bet,
    float* __restrict__ out)
{
    const int row = blockIdx.x;
    const long long base = (long long)row * Hd;
    const int tid = threadIdx.x;

    float v[3];
    float s = 0.f, s2 = 0.f;
#pragma unroll
    for (int u = 0; u < 3; u++) {
        const int idx = tid + u * 256;
        const float val = X[base + idx] + Rres[base + idx];
        v[u] = val; s += val; s2 += val * val;
    }
#pragma unroll
    for (int off = 16; off >= 1; off >>= 1) {
        s  += __shfl_xor_sync(0xffffffffu, s, off);
        s2 += __shfl_xor_sync(0xffffffffu, s2, off);
    }
    __shared__ float ss[8], ss2[8], mv[2];
    const int wid = tid >> 5, lane = tid & 31;
    if (lane == 0) { ss[wid] = s; ss2[wid] = s2; }
    __syncthreads();
    if (tid == 0) {
        float S_ = 0.f, S2_ = 0.f;
        for (int w = 0; w < 8; w++) { S_ += ss[w]; S2_ += ss2[w]; }
        const float mean = S_ * (1.f / 768.f);
        const float var  = S2_ * (1.f / 768.f) - mean * mean;
        mv[0] = mean;
        mv[1] = rsqrtf(var + 1e-5f);
    }
    __syncthreads();
    const float mean = mv[0], rstd = mv[1];
#pragma unroll
    for (int u = 0; u < 3; u++) {
        const int idx = tid + u * 256;
        out[base + idx] = (v[u] - mean) * rstd * gam[idx] + bet[idx];
    }
}

// ---------------------------------------------------------------------------
// kernel_launch
// ---------------------------------------------------------------------------
#define SYM(v, s) cudaGetSymbolAddress((void**)&v, s)

extern "C" void kernel_launch(void* const* d_in, const int* in_sizes, int n_in,
                              void* d_out, int out_size)
{
    const float* hs      = (const float*)d_in[0];
    const int*   lang    = (const int*)  d_in[1];
    const float* Wq_lang = (const float*)d_in[3];
    const float* bq_lang = (const float*)d_in[4];
    const float* Wk_lang = (const float*)d_in[5];
    const float* bk_lang = (const float*)d_in[6];
    const float* in_w    = (const float*)d_in[7];
    const float* in_b    = (const float*)d_in[8];
    const float* out_w   = (const float*)d_in[9];
    const float* out_b   = (const float*)d_in[10];
    const float* alignT  = (const float*)d_in[11];
    const float* proj_w  = (const float*)d_in[12];
    const float* proj_b  = (const float*)d_in[13];
    const float* ln_g    = (const float*)d_in[14];
    const float* ln_b    = (const float*)d_in[15];
    float* out = (float*)d_out;

    float *Qp, *Kp, *Vp, *ctx, *obuf;
    SYM(Qp, g_Q); SYM(Kp, g_K); SYM(Vp, g_V); SYM(ctx, g_ctx); SYM(obuf, g_o);

    bf16 *hs_h, *hs_l, *ctx_h, *ctx_l;
    SYM(hs_h, g_hs_h);   SYM(hs_l, g_hs_l);
    SYM(ctx_h, g_ctx_h); SYM(ctx_l, g_ctx_l);

    bf16 *inw_h, *inw_l, *pw_h, *pw_l, *owT_h, *owT_l;
    SYM(inw_h, g_inw_h); SYM(inw_l, g_inw_l);
    SYM(pw_h, g_pw_h);   SYM(pw_l, g_pw_l);
    SYM(owT_h, g_owT_h); SYM(owT_l, g_owT_l);

    bf16 *WqT_h, *WqT_l, *WkT_h, *WkT_l, *Wqc_h, *Wqc_l, *Wkc_h, *Wkc_l;
    bf16 *GT_h, *GT_l, *WfT_h, *WfT_l, *scr_h, *scr_l;
    SYM(WqT_h, g_WqT_h); SYM(WqT_l, g_WqT_l);
    SYM(WkT_h, g_WkT_h); SYM(WkT_l, g_WkT_l);
    SYM(Wqc_h, g_Wqc_h); SYM(Wqc_l, g_Wqc_l);
    SYM(Wkc_h, g_Wkc_h); SYM(Wkc_l, g_Wkc_l);
    SYM(GT_h, g_GT_h);   SYM(GT_l, g_GT_l);
    SYM(WfT_h, g_WfT_h); SYM(WfT_l, g_WfT_l);
    SYM(scr_h, g_scr_h); SYM(scr_l, g_scr_l);

    float *bqc, *bkc, *bfin;
    SYM(bqc, g_bqc); SYM(bkc, g_bkc); SYM(bfin, g_bfin);

    bf16 *F_h, *F_l, *FT_h, *FT_l, *P1_h, *P1_l, *QT1_h, *QT1_l;
    bf16 *P2_h, *P2_l, *QT2_h, *QT2_l, *M_h, *M_l, *MT_h, *MT_l;
    SYM(F_h, g_F_h);   SYM(F_l, g_F_l);   SYM(FT_h, g_FT_h); SYM(FT_l, g_FT_l);
    SYM(P1_h, g_P1_h); SYM(P1_l, g_P1_l); SYM(QT1_h, g_QT1_h); SYM(QT1_l, g_QT1_l);
    SYM(P2_h, g_P2_h); SYM(P2_l, g_P2_l); SYM(QT2_h, g_QT2_h); SYM(QT2_l, g_QT2_l);
    SYM(M_h, g_M_h);   SYM(M_l, g_M_l);   SYM(MT_h, g_MT_h); SYM(MT_l, g_MT_l);

    unsigned char *fF, *fP1, *fP2;
    SYM(fF, g_fF); SYM(fP1, g_fP1); SYM(fP2, g_fP2);

    cudaFuncSetAttribute(k_final, cudaFuncAttributeMaxDynamicSharedMemorySize, GEMM_SMEM);
    cudaFuncSetAttribute(k_qkv,   cudaFuncAttributeMaxDynamicSharedMemorySize, GEMM_SMEM);
    cudaFuncSetAttribute(k_wcomb, cudaFuncAttributeMaxDynamicSharedMemorySize, GEMM_SMEM);
    cudaFuncSetAttribute(k_G,     cudaFuncAttributeMaxDynamicSharedMemorySize, GEMM_SMEM);
    cudaFuncSetAttribute(k_Wfin,  cudaFuncAttributeMaxDynamicSharedMemorySize, GEMM_SMEM);
    cudaFuncSetAttribute(tc_chain,cudaFuncAttributeMaxDynamicSharedMemorySize, GEMM_SMEM);

    const dim3 thr(256);

    // --- conversions ---
    k_conv<<<BS * Hd / 1024, thr>>>(hs, hs_h, hs_l);
    k_conv<<<(int)(3 * HH / 1024), thr>>>(in_w, inw_h, inw_l);
    k_conv<<<(int)(HH / 1024), thr>>>(proj_w, pw_h, pw_l);
    k_convT<<<dim3((int)(HH / 1024), 1), thr>>>(out_w, owT_h, owT_l);
    k_convT<<<dim3((int)(HH / 1024), NL), thr>>>(Wq_lang, WqT_h, WqT_l);
    k_convT<<<dim3((int)(HH / 1024), NL), thr>>>(Wk_lang, WkT_h, WkT_l);

    // --- weight combine (independent of hs) ---
    k_wcomb<<<dim3(6, 6, 2 * NL), thr, GEMM_SMEM>>>(
        inw_h, inw_l, WqT_h, WqT_l, WkT_h, WkT_l, Wqc_h, Wqc_l, Wkc_h, Wkc_l);
    k_bias_qk<<<dim3(2, NL), Hd>>>(in_w, in_b, bq_lang, bk_lang, bqc, bkc);

    // --- chain -> M ---
    k_flags<<<1, 32>>>(lang, fF, fP1, fP2);
    k_factors<<<dim3((int)(HH / 1024), NL * 8), thr>>>(alignT, lang, F_h, F_l, FT_h, FT_l);
    tc_chain<<<dim3(6, 6, NL * 4), thr, GEMM_SMEM>>>(F_h, F_l, FT_h, FT_l, fF,
                                                     P1_h, P1_l, QT1_h, QT1_l, 8, 4);
    tc_chain<<<dim3(6, 6, NL * 2), thr, GEMM_SMEM>>>(P1_h, P1_l, QT1_h, QT1_l, fP1,
                                                     P2_h, P2_l, QT2_h, QT2_l, 4, 2);
    tc_chain<<<dim3(6, 6, NL), thr, GEMM_SMEM>>>(P2_h, P2_l, QT2_h, QT2_l, fP2,
                                                 M_h, M_l, MT_h, MT_l, 2, 1);

    // --- G = M @ proj_w^T ; Wfin = out_w^T @ G ; bfin ---
    k_G<<<dim3(6, 6, NL), thr, GEMM_SMEM>>>(M_h, M_l, pw_h, pw_l,
                                            scr_h, scr_l, GT_h, GT_l);
    k_Wfin<<<dim3(6, 6, NL), thr, GEMM_SMEM>>>(owT_h, owT_l, GT_h, GT_l,
                                               scr_h, scr_l, WfT_h, WfT_l);
    k_bias_fin<<<NL, Hd>>>(GT_h, GT_l, out_b, proj_b, bfin);

    // --- fused QKV ---
    k_qkv<<<dim3(6, 6, 24), thr, GEMM_SMEM>>>(
        hs_h, hs_l, Wqc_h, Wqc_l, bqc, Wkc_h, Wkc_l, bkc,
        inw_h + 2 * HH, inw_l + 2 * HH, in_b + 2 * Hd, lang, Qp, Kp, Vp);

    // --- attention ---
    k_attn<<<dim3(S / 64, NH, Bsz), thr>>>(Qp, Kp, Vp, ctx);
    k_conv<<<BS * Hd / 1024, thr>>>(ctx, ctx_h, ctx_l);

    // --- fused out_proj @ M @ proj ---
    k_final<<<dim3(6, 6, Bsz), thr, GEMM_SMEM>>>(ctx_h, ctx_l, WfT_h, WfT_l,
                                                 bfin, lang, obuf);

    // --- residual + LayerNorm ---
    k_ln<<<BS, thr>>>(obuf, hs, ln_g, ln_b, out);
}

// round 6
// speedup vs baseline: 1.5555x; 1.5555x over previous
#include <cuda_runtime.h>
#include <cuda_bf16.h>
#include <cstdint>

// ---------------------------------------------------------------------------
// Problem constants
// ---------------------------------------------------------------------------
constexpr int Bsz = 8;
constexpr int S   = 768;
constexpr int Hd  = 768;
constexpr int NH  = 12;
constexpr int NL  = 5;
constexpr int BS  = Bsz * S;                 // 6144 rows
constexpr long long HH = (long long)Hd * Hd; // 589824

typedef __nv_bfloat16 bf16;

// ---------------------------------------------------------------------------
// Scratch (static device globals)
// ---------------------------------------------------------------------------
// fp32 activations
__device__ float g_Q  [BS * Hd];
__device__ float g_K  [BS * Hd];
__device__ float g_V  [BS * Hd];
__device__ float g_ctx[BS * Hd];
__device__ float g_o  [BS * Hd];

// bf16 hi/lo activations
__device__ bf16 g_hs_h [BS * Hd], g_hs_l [BS * Hd];
__device__ bf16 g_q_h  [BS * Hd], g_q_l  [BS * Hd];
__device__ bf16 g_k_h  [BS * Hd], g_k_l  [BS * Hd];
__device__ bf16 g_ctx_h[BS * Hd], g_ctx_l[BS * Hd];
__device__ bf16 g_al_h [BS * Hd], g_al_l [BS * Hd];
__device__ bf16 g_al2_h[BS * Hd], g_al2_l[BS * Hd];

// bf16 hi/lo weights
__device__ bf16 g_Wq_h [NL * Hd * Hd], g_Wq_l [NL * Hd * Hd];
__device__ bf16 g_Wk_h [NL * Hd * Hd], g_Wk_l [NL * Hd * Hd];
__device__ bf16 g_inw_h[3 * Hd * Hd],  g_inw_l[3 * Hd * Hd];
__device__ bf16 g_ow_h [Hd * Hd],      g_ow_l [Hd * Hd];
__device__ bf16 g_pw_h [Hd * Hd],      g_pw_l [Hd * Hd];

// chain nodes: normal + transposed, hi + lo
__device__ bf16 g_F_h [NL * 8 * Hd * Hd], g_F_l [NL * 8 * Hd * Hd];
__device__ bf16 g_FT_h[NL * 8 * Hd * Hd], g_FT_l[NL * 8 * Hd * Hd];
__device__ bf16 g_P1_h[NL * 4 * Hd * Hd], g_P1_l[NL * 4 * Hd * Hd];
__device__ bf16 g_QT1_h[NL * 4 * Hd * Hd], g_QT1_l[NL * 4 * Hd * Hd];
__device__ bf16 g_P2_h[NL * 2 * Hd * Hd], g_P2_l[NL * 2 * Hd * Hd];
__device__ bf16 g_QT2_h[NL * 2 * Hd * Hd], g_QT2_l[NL * 2 * Hd * Hd];
__device__ bf16 g_M_h [NL * Hd * Hd],     g_M_l [NL * Hd * Hd];
__device__ bf16 g_MT_h[NL * Hd * Hd],     g_MT_l[NL * Hd * Hd];

__device__ unsigned char g_fF [NL * 8];
__device__ unsigned char g_fP1[NL * 4];
__device__ unsigned char g_fP2[NL * 2];

// ---------------------------------------------------------------------------
// Small PTX helpers
// ---------------------------------------------------------------------------
__device__ __forceinline__ uint32_t smem_u32(const void* p) {
    return (uint32_t)__cvta_generic_to_shared(p);
}
__device__ __forceinline__ void cp16(uint32_t d, const void* s) {
    asm volatile("cp.async.cg.shared.global [%0], [%1], 16;"
                 :: "r"(d), "l"(s) : "memory");
}
__device__ __forceinline__ void cp_commit() {
    asm volatile("cp.async.commit_group;" ::: "memory");
}
template <int N>
__device__ __forceinline__ void cp_wait() {
    asm volatile("cp.async.wait_group %0;" :: "n"(N) : "memory");
}
__device__ __forceinline__ void ldsm4(uint32_t* r, uint32_t addr) {
    asm volatile("ldmatrix.sync.aligned.m8n8.x4.shared.b16 {%0,%1,%2,%3}, [%4];"
                 : "=r"(r[0]), "=r"(r[1]), "=r"(r[2]), "=r"(r[3]) : "r"(addr));
}
__device__ __forceinline__ void mma_bf16(float* d, const uint32_t* a,
                                         uint32_t b0, uint32_t b1) {
    asm volatile(
        "mma.sync.aligned.m16n8k16.row.col.f32.bf16.bf16.f32 "
        "{%0,%1,%2,%3}, {%4,%5,%6,%7}, {%8,%9}, {%0,%1,%2,%3};"
        : "+f"(d[0]), "+f"(d[1]), "+f"(d[2]), "+f"(d[3])
        : "r"(a[0]), "r"(a[1]), "r"(a[2]), "r"(a[3]), "r"(b0), "r"(b1));
}
__device__ __forceinline__ uint32_t pack_bf(bf16 a, bf16 b) {
    return (uint32_t)__bfloat16_as_ushort(a) |
           ((uint32_t)__bfloat16_as_ushort(b) << 16);
}

// ---------------------------------------------------------------------------
// GEMM config: 128x128 tile, BLK_K=32, 8 warps, 4-stage cp.async pipeline
// ---------------------------------------------------------------------------
constexpr int SKP     = 40;
constexpr int TILE_B  = 128 * SKP * 2;       // 10240 B per operand tile
constexpr int STAGE_B = 4 * TILE_B;          // 40960 B (Ah Al Wh Wl)
constexpr int NSTAGE  = 4;
constexpr int GEMM_SMEM = NSTAGE * STAGE_B;  // 163840 B

__device__ __forceinline__ void gemm_issue(
    const bf16* __restrict__ base, int lw, uint32_t sdst0, int kc)
{
    const bf16* g0 = base + kc * 32;
#pragma unroll
    for (int i = 0; i < 8; i++) {
        const int chunk = i * 64 + lw;
        const int row = chunk >> 2, cs = chunk & 3;
        cp16(sdst0 + row * (SKP * 2) + cs * 16,
             g0 + (long long)row * Hd + cs * 8);
    }
}

// MODE 0: fp32 out (+bias). MODE 1: bf16 hi/lo out (+bias if non-null).
// MODE 2: bf16 hi/lo out + transposed hi/lo out (no bias).
template <int MODE>
__device__ void gemm_core(
    const bf16* __restrict__ Ah, const bf16* __restrict__ Al,
    const bf16* __restrict__ Wh, const bf16* __restrict__ Wl,
    const float* __restrict__ bias,
    float* __restrict__ C,
    bf16* __restrict__ Ch, bf16* __restrict__ Cl,
    bf16* __restrict__ Th, bf16* __restrict__ Tl,
    int m0, int n0)
{
    extern __shared__ char dsm[];
    const int tid = threadIdx.x;
    const int wid = tid >> 5, lane = tid & 31;
    const int m_off = (wid & 3) * 32;
    const int n_off = (wid >> 2) * 64;
    const uint32_t sbase = smem_u32(dsm);

    const int ltile = tid >> 6;
    const int lw = tid & 63;
    const bf16* gbase =
        (ltile == 0) ? Ah + (long long)m0 * Hd :
        (ltile == 1) ? Al + (long long)m0 * Hd :
        (ltile == 2) ? Wh + (long long)n0 * Hd :
                       Wl + (long long)n0 * Hd;
    const uint32_t sdst_tile = ltile * TILE_B;

    // prologue: stages 0..2 in flight
#pragma unroll
    for (int p = 0; p < NSTAGE - 1; p++) {
        gemm_issue(gbase, lw, sbase + p * STAGE_B + sdst_tile, p);
        cp_commit();
    }

    float acc[2][8][4];
#pragma unroll
    for (int mi = 0; mi < 2; mi++)
#pragma unroll
        for (int j = 0; j < 8; j++)
#pragma unroll
            for (int e = 0; e < 4; e++) acc[mi][j][e] = 0.f;

    const int r_off = ((lane >> 3) & 1) * 8 + (lane & 7);
    const int c_off = (lane >> 4) * 8;

    for (int kc = 0; kc < 24; kc++) {
        cp_wait<NSTAGE - 2>();          // group kc complete (uniform commits)
        __syncthreads();
        const uint32_t sb = sbase + (kc & (NSTAGE - 1)) * STAGE_B;
        const uint32_t aAh = sb + (m_off + r_off) * (SKP * 2) + c_off * 2;
        const uint32_t aAl = aAh + TILE_B;
        const uint32_t aWh = sb + 2 * TILE_B + (n_off + r_off) * (SKP * 2) + c_off * 2;
        const uint32_t aWl = aWh + TILE_B;

#pragma unroll
        for (int kk = 0; kk < 2; kk++) {
            uint32_t ah[2][4], alr[2][4];
#pragma unroll
            for (int t = 0; t < 2; t++) {
                ldsm4(ah[t],  aAh + t * 16 * (SKP * 2) + kk * 32);
                ldsm4(alr[t], aAl + t * 16 * (SKP * 2) + kk * 32);
            }
#pragma unroll
            for (int u = 0; u < 4; u++) {
                uint32_t bh[4];
                ldsm4(bh, aWh + u * 16 * (SKP * 2) + kk * 32);
#pragma unroll
                for (int mi = 0; mi < 2; mi++) {
                    mma_bf16(acc[mi][2 * u],     ah[mi],  bh[0], bh[2]);
                    mma_bf16(acc[mi][2 * u + 1], ah[mi],  bh[1], bh[3]);
                    mma_bf16(acc[mi][2 * u],     alr[mi], bh[0], bh[2]);
                    mma_bf16(acc[mi][2 * u + 1], alr[mi], bh[1], bh[3]);
                }
                uint32_t bl[4];
                ldsm4(bl, aWl + u * 16 * (SKP * 2) + kk * 32);
#pragma unroll
                for (int mi = 0; mi < 2; mi++) {
                    mma_bf16(acc[mi][2 * u],     ah[mi], bl[0], bl[2]);
                    mma_bf16(acc[mi][2 * u + 1], ah[mi], bl[1], bl[3]);
                }
            }
        }
        // issue chunk kc+3 into stage (kc+3)%4 (its readers finished before
        // this iteration's top barrier)
        if (kc + NSTAGE - 1 < 24)
            gemm_issue(gbase, lw,
                       sbase + ((kc + NSTAGE - 1) & (NSTAGE - 1)) * STAGE_B + sdst_tile,
                       kc + NSTAGE - 1);
        cp_commit();                    // uniform commit keeps group count exact
    }
    __syncthreads();

    // stage accumulators through SMEM (f32 [128][132]); all data groups have
    // drained (wait<2> at kc=23 covers every real chunk group).
    float* sf = (float*)dsm;
    const int g = lane >> 2, t2 = (lane & 3) * 2;
#pragma unroll
    for (int mi = 0; mi < 2; mi++)
#pragma unroll
        for (int j = 0; j < 8; j++) {
            const int r = m_off + mi * 16 + g;
            const int c = n_off + j * 8 + t2;
            sf[r * 132 + c]           = acc[mi][j][0];
            sf[r * 132 + c + 1]       = acc[mi][j][1];
            sf[(r + 8) * 132 + c]     = acc[mi][j][2];
            sf[(r + 8) * 132 + c + 1] = acc[mi][j][3];
        }
    __syncthreads();

    if (MODE == 0) {
#pragma unroll 4
        for (int i = 0; i < 16; i++) {
            const int task = i * 256 + tid;
            const int row = task >> 5, c4 = (task & 31) * 4;
            float4 v = *(float4*)&sf[row * 132 + c4];
            v.x += bias[n0 + c4 + 0];
            v.y += bias[n0 + c4 + 1];
            v.z += bias[n0 + c4 + 2];
            v.w += bias[n0 + c4 + 3];
            *(float4*)(C + (long long)(m0 + row) * Hd + n0 + c4) = v;
        }
    } else {
#pragma unroll 4
        for (int i = 0; i < 16; i++) {
            const int task = i * 256 + tid;
            const int row = task >> 5, c4 = (task & 31) * 4;
            float4 v = *(float4*)&sf[row * 132 + c4];
            if (MODE == 1 && bias) {
                v.x += bias[n0 + c4 + 0];
                v.y += bias[n0 + c4 + 1];
                v.z += bias[n0 + c4 + 2];
                v.w += bias[n0 + c4 + 3];
            }
            bf16 h0 = __float2bfloat16(v.x), h1 = __float2bfloat16(v.y);
            bf16 h2 = __float2bfloat16(v.z), h3 = __float2bfloat16(v.w);
            bf16 l0 = __float2bfloat16(v.x - __bfloat162float(h0));
            bf16 l1 = __float2bfloat16(v.y - __bfloat162float(h1));
            bf16 l2 = __float2bfloat16(v.z - __bfloat162float(h2));
            bf16 l3 = __float2bfloat16(v.w - __bfloat162float(h3));
            const long long off = (long long)(m0 + row) * Hd + n0 + c4;
            *(uint2*)(Ch + off) = make_uint2(pack_bf(h0, h1), pack_bf(h2, h3));
            *(uint2*)(Cl + off) = make_uint2(pack_bf(l0, l1), pack_bf(l2, l3));
        }
        if (MODE == 2) {
            const int c = tid & 127;
            const int half = tid >> 7;
#pragma unroll 4
            for (int i = 0; i < 16; i++) {
                const int r4 = half * 64 + i * 4;
                float v0 = sf[(r4 + 0) * 132 + c];
                float v1 = sf[(r4 + 1) * 132 + c];
                float v2 = sf[(r4 + 2) * 132 + c];
                float v3 = sf[(r4 + 3) * 132 + c];
                bf16 h0 = __float2bfloat16(v0), h1 = __float2bfloat16(v1);
                bf16 h2 = __float2bfloat16(v2), h3 = __float2bfloat16(v3);
                bf16 l0 = __float2bfloat16(v0 - __bfloat162float(h0));
                bf16 l1 = __float2bfloat16(v1 - __bfloat162float(h1));
                bf16 l2 = __float2bfloat16(v2 - __bfloat162float(h2));
                bf16 l3 = __float2bfloat16(v3 - __bfloat162float(h3));
                const long long off = (long long)(n0 + c) * Hd + m0 + r4;
                *(uint2*)(Th + off) = make_uint2(pack_bf(h0, h1), pack_bf(h2, h3));
                *(uint2*)(Tl + off) = make_uint2(pack_bf(l0, l1), pack_bf(l2, l3));
            }
        }
    }
}

// ---------------------------------------------------------------------------
// GEMM wrappers (R3 structure, no forced min-blocks)
// ---------------------------------------------------------------------------
template <int MODE, int WSEL>
__global__ __launch_bounds__(256) void tc_gemm(
    const bf16* __restrict__ Ah, const bf16* __restrict__ Al, long long sAz,
    const bf16* __restrict__ Wh, const bf16* __restrict__ Wl,
    const float* __restrict__ bias, const int* __restrict__ lang,
    float* __restrict__ C, bf16* __restrict__ Ch, bf16* __restrict__ Cl,
    long long sCz)
{
    const int z = blockIdx.z;
    const bf16* wh = Wh;
    const bf16* wl = Wl;
    const float* bs = bias;
    if (WSEL) {
        const int lg = __ldg(&lang[z]);
        wh += (long long)lg * HH;
        wl += (long long)lg * HH;
        if (bias) bs += lg * Hd;
    }
    const long long ao = (long long)z * sAz;
    const long long co = (long long)z * sCz;
    gemm_core<MODE>(Ah + ao, Al + ao, wh, wl, bs,
                    (MODE == 0) ? C + co : nullptr,
                    (MODE != 0) ? Ch + co : nullptr,
                    (MODE != 0) ? Cl + co : nullptr,
                    nullptr, nullptr,
                    blockIdx.y * 128, blockIdx.x * 128);
}

// chain level: dst[z] = src[2p] @ src[2p+1], identity shortcuts, bf16 hi/lo
__global__ __launch_bounds__(256) void tc_chain(
    const bf16* __restrict__ sN_h, const bf16* __restrict__ sN_l,
    const bf16* __restrict__ sT_h, const bf16* __restrict__ sT_l,
    const unsigned char* __restrict__ fs,
    bf16* __restrict__ dN_h, bf16* __restrict__ dN_l,
    bf16* __restrict__ dT_h, bf16* __restrict__ dT_l,
    int spa, int dpa)
{
    const int z = blockIdx.z;
    const int a = z / dpa, p = z - a * dpa;
    const int li = a * spa + 2 * p;
    const unsigned char f1 = fs[li], f2 = fs[li + 1];
    const long long zo = (long long)z * HH;
    const int m0 = blockIdx.y * 128, n0 = blockIdx.x * 128;
    const int tid = threadIdx.x;

    if (f1 & f2) {   // identity
#pragma unroll 4
        for (int i = 0; i < 16; i++) {
            const int task = i * 256 + tid;
            const int row = task >> 5, c4 = (task & 31) * 4;
            const int gr = m0 + row, gc = n0 + c4;
            bf16 one = __float2bfloat16(1.f), zero = __float2bfloat16(0.f);
            bf16 h0 = (gc + 0 == gr) ? one : zero;
            bf16 h1 = (gc + 1 == gr) ? one : zero;
            bf16 h2 = (gc + 2 == gr) ? one : zero;
            bf16 h3 = (gc + 3 == gr) ? one : zero;
            const long long off = zo + (long long)gr * Hd + gc;
            uint2 hv = make_uint2(pack_bf(h0, h1), pack_bf(h2, h3));
            uint2 lv = make_uint2(0u, 0u);
            *(uint2*)(dN_h + off) = hv; *(uint2*)(dN_l + off) = lv;
            *(uint2*)(dT_h + off) = hv; *(uint2*)(dT_l + off) = lv;
        }
        return;
    }
    if (f1 | f2) {   // copy the non-identity factor (all 4 forms)
        const long long so = (long long)(f1 ? li + 1 : li) * HH;
#pragma unroll 4
        for (int i = 0; i < 8; i++) {
            const int idx = i * 256 + tid;
            const int row = idx >> 4, c8 = (idx & 15) * 8;
            const long long doff = zo + (long long)(m0 + row) * Hd + n0 + c8;
            const long long soff = so + (long long)(m0 + row) * Hd + n0 + c8;
            *(uint4*)(dN_h + doff) = *(const uint4*)(sN_h + soff);
            *(uint4*)(dN_l + doff) = *(const uint4*)(sN_l + soff);
            *(uint4*)(dT_h + doff) = *(const uint4*)(sT_h + soff);
            *(uint4*)(dT_l + doff) = *(const uint4*)(sT_l + soff);
        }
        return;
    }
    gemm_core<2>(sN_h + (long long)li * HH, sN_l + (long long)li * HH,
                 sT_h + (long long)(li + 1) * HH, sT_l + (long long)(li + 1) * HH,
                 nullptr, nullptr,
                 dN_h + zo, dN_l + zo, dT_h + zo, dT_l + zo, m0, n0);
}

// ---------------------------------------------------------------------------
// fp32 -> bf16 hi/lo conversion
// ---------------------------------------------------------------------------
__global__ __launch_bounds__(256) void k_conv(
    const float* __restrict__ src, bf16* __restrict__ dh,
    bf16* __restrict__ dl)
{
    const long long i4 = ((long long)blockIdx.x * 256 + threadIdx.x) * 4;
    float4 v = *(const float4*)(src + i4);
    bf16 h0 = __float2bfloat16(v.x), h1 = __float2bfloat16(v.y);
    bf16 h2 = __float2bfloat16(v.z), h3 = __float2bfloat16(v.w);
    bf16 l0 = __float2bfloat16(v.x - __bfloat162float(h0));
    bf16 l1 = __float2bfloat16(v.y - __bfloat162float(h1));
    bf16 l2 = __float2bfloat16(v.z - __bfloat162float(h2));
    bf16 l3 = __float2bfloat16(v.w - __bfloat162float(h3));
    *(uint2*)(dh + i4) = make_uint2(pack_bf(h0, h1), pack_bf(h2, h3));
    *(uint2*)(dl + i4) = make_uint2(pack_bf(l0, l1), pack_bf(l2, l3));
}

// ---------------------------------------------------------------------------
// Chain flags + leaf factors
// ---------------------------------------------------------------------------
__global__ void k_flags(const int* __restrict__ lang,
                        unsigned char* fF, unsigned char* fP1, unsigned char* fP2)
{
    if (threadIdx.x == 0 && blockIdx.x == 0) {
        for (int a = 0; a < NL; a++) {
            for (int j = 0; j < 8; j++) fF[a * 8 + j] = (lang[j] == a) ? 1 : 0;
            for (int p = 0; p < 4; p++)
                fP1[a * 4 + p] = fF[a * 8 + 2 * p] & fF[a * 8 + 2 * p + 1];
            for (int p = 0; p < 2; p++)
                fP2[a * 2 + p] = fP1[a * 4 + 2 * p] & fP1[a * 4 + 2 * p + 1];
        }
    }
}

__device__ __forceinline__ void split_store4(
    bf16* dh, bf16* dl, long long off, float x, float y, float z, float w)
{
    bf16 h0 = __float2bfloat16(x), h1 = __float2bfloat16(y);
    bf16 h2 = __float2bfloat16(z), h3 = __float2bfloat16(w);
    bf16 l0 = __float2bfloat16(x - __bfloat162float(h0));
    bf16 l1 = __float2bfloat16(y - __bfloat162float(h1));
    bf16 l2 = __float2bfloat16(z - __bfloat162float(h2));
    bf16 l3 = __float2bfloat16(w - __bfloat162float(h3));
    *(uint2*)(dh + off) = make_uint2(pack_bf(h0, h1), pack_bf(h2, h3));
    *(uint2*)(dl + off) = make_uint2(pack_bf(l0, l1), pack_bf(l2, l3));
}

__global__ __launch_bounds__(256) void k_factors(
    const float* __restrict__ alignT, const int* __restrict__ lang,
    bf16* __restrict__ Fh, bf16* __restrict__ Fl,
    bf16* __restrict__ FTh, bf16* __restrict__ FTl)
{
    const int node = blockIdx.y;
    const int a = node >> 3, j = node & 7;
    const int c = __ldg(&lang[j]);
    const long long nb = (long long)node * HH;
    const long long i4 = ((long long)blockIdx.x * 256 + threadIdx.x) * 4;
    const int r = (int)(i4 / Hd), col = (int)(i4 % Hd);

    if (c == a) {
        float v0 = (col + 0 == r) ? 1.f : 0.f;
        float v1 = (col + 1 == r) ? 1.f : 0.f;
        float v2 = (col + 2 == r) ? 1.f : 0.f;
        float v3 = (col + 3 == r) ? 1.f : 0.f;
        split_store4(Fh,  Fl,  nb + i4, v0, v1, v2, v3);
        split_store4(FTh, FTl, nb + i4, v0, v1, v2, v3);
    } else {
        const float* sm = alignT + (long long)(a * NL + c) * HH;
        float4 v = *(const float4*)(sm + i4);
        split_store4(Fh, Fl, nb + i4, v.x, v.y, v.z, v.w);
        float t0 = sm[(long long)(col + 0) * Hd + r];
        float t1 = sm[(long long)(col + 1) * Hd + r];
        float t2 = sm[(long long)(col + 2) * Hd + r];
        float t3 = sm[(long long)(col + 3) * Hd + r];
        split_store4(FTh, FTl, nb + i4, t0, t1, t2, t3);
    }
}

// ---------------------------------------------------------------------------
// Flash attention (fp32 SIMT)
// ---------------------------------------------------------------------------
__global__ __launch_bounds__(256) void k_attn(
    const float* __restrict__ Q, const float* __restrict__ K,
    const float* __restrict__ V, float* __restrict__ O)
{
    __shared__ float Qs[64 * 64];
    __shared__ float KP[64 * 64];
    __shared__ float Vs[64 * 64];

    const int qt = blockIdx.x, h = blockIdx.y, b = blockIdx.z;
    const int tid = threadIdx.x;
    const int ty = tid >> 4, tx = tid & 15;
    const long long qbase = ((long long)(b * S + qt * 64)) * Hd + h * 64;

#pragma unroll
    for (int u = 0; u < 4; u++) {
        const int fidx = u * 256 + tid;
        const int r = fidx >> 4;
        const int d = (fidx & 15) * 4;
        float4 v = *(const float4*)(Q + qbase + (long long)r * Hd + d);
        v.x *= 0.125f; v.y *= 0.125f; v.z *= 0.125f; v.w *= 0.125f;
        *(float4*)&Qs[r * 64 + d] = v;
    }

    float m[4], l[4], o[4][4];
#pragma unroll
    for (int i = 0; i < 4; i++) {
        m[i] = -1e30f; l[i] = 0.f;
#pragma unroll
        for (int j = 0; j < 4; j++) o[i][j] = 0.f;
    }

    for (int kt = 0; kt < S / 64; kt++) {
        const long long kbase = ((long long)(b * S + kt * 64)) * Hd + h * 64;
        __syncthreads();
#pragma unroll
        for (int u = 0; u < 4; u++) {
            const int fidx = u * 256 + tid;
            const int r = fidx >> 4;
            const int d = (fidx & 15) * 4;
            float4 kv = *(const float4*)(K + kbase + (long long)r * Hd + d);
            KP[(d + 0) * 64 + r] = kv.x;
            KP[(d + 1) * 64 + r] = kv.y;
            KP[(d + 2) * 64 + r] = kv.z;
            KP[(d + 3) * 64 + r] = kv.w;
            *(float4*)&Vs[r * 64 + d] =
                *(const float4*)(V + kbase + (long long)r * Hd + d);
        }
        __syncthreads();

        float s[4][4];
#pragma unroll
        for (int i = 0; i < 4; i++)
#pragma unroll
            for (int j = 0; j < 4; j++) s[i][j] = 0.f;

#pragma unroll
        for (int d0 = 0; d0 < 64; d0 += 4) {
            float a0[4], a1[4], a2[4], a3[4];
            *(float4*)a0 = *(const float4*)&Qs[(ty * 4 + 0) * 64 + d0];
            *(float4*)a1 = *(const float4*)&Qs[(ty * 4 + 1) * 64 + d0];
            *(float4*)a2 = *(const float4*)&Qs[(ty * 4 + 2) * 64 + d0];
            *(float4*)a3 = *(const float4*)&Qs[(ty * 4 + 3) * 64 + d0];
#pragma unroll
            for (int dd = 0; dd < 4; dd++) {
                const float b0 = KP[(d0 + dd) * 64 + tx];
                const float b1 = KP[(d0 + dd) * 64 + tx + 16];
                const float b2 = KP[(d0 + dd) * 64 + tx + 32];
                const float b3 = KP[(d0 + dd) * 64 + tx + 48];
                s[0][0] += a0[dd] * b0; s[0][1] += a0[dd] * b1;
                s[0][2] += a0[dd] * b2; s[0][3] += a0[dd] * b3;
                s[1][0] += a1[dd] * b0; s[1][1] += a1[dd] * b1;
                s[1][2] += a1[dd] * b2; s[1][3] += a1[dd] * b3;
                s[2][0] += a2[dd] * b0; s[2][1] += a2[dd] * b1;
                s[2][2] += a2[dd] * b2; s[2][3] += a2[dd] * b3;
                s[3][0] += a3[dd] * b0; s[3][1] += a3[dd] * b1;
                s[3][2] += a3[dd] * b2; s[3][3] += a3[dd] * b3;
            }
        }

        float p[4][4];
#pragma unroll
        for (int i = 0; i < 4; i++) {
            float mx = fmaxf(fmaxf(s[i][0], s[i][1]), fmaxf(s[i][2], s[i][3]));
#pragma unroll
            for (int off = 8; off >= 1; off >>= 1)
                mx = fmaxf(mx, __shfl_xor_sync(0xffffffffu, mx, off));
            const float mn = fmaxf(m[i], mx);
            const float alpha = __expf(m[i] - mn);
            m[i] = mn;
            float rs = 0.f;
#pragma unroll
            for (int j = 0; j < 4; j++) {
                p[i][j] = __expf(s[i][j] - mn);
                rs += p[i][j];
            }
#pragma unroll
            for (int off = 8; off >= 1; off >>= 1)
                rs += __shfl_xor_sync(0xffffffffu, rs, off);
            l[i] = l[i] * alpha + rs;
            o[i][0] *= alpha; o[i][1] *= alpha;
            o[i][2] *= alpha; o[i][3] *= alpha;
        }

        __syncthreads();
#pragma unroll
        for (int i = 0; i < 4; i++)
#pragma unroll
            for (int j = 0; j < 4; j++)
                KP[(ty * 4 + i) * 64 + tx + 16 * j] = p[i][j];
        __syncthreads();

#pragma unroll
        for (int k = 0; k < 64; k++) {
            const float4 v = *(const float4*)&Vs[k * 64 + tx * 4];
            const float p0 = KP[(ty * 4 + 0) * 64 + k];
            const float p1 = KP[(ty * 4 + 1) * 64 + k];
            const float p2 = KP[(ty * 4 + 2) * 64 + k];
            const float p3 = KP[(ty * 4 + 3) * 64 + k];
            o[0][0] += p0 * v.x; o[0][1] += p0 * v.y; o[0][2] += p0 * v.z; o[0][3] += p0 * v.w;
            o[1][0] += p1 * v.x; o[1][1] += p1 * v.y; o[1][2] += p1 * v.z; o[1][3] += p1 * v.w;
            o[2][0] += p2 * v.x; o[2][1] += p2 * v.y; o[2][2] += p2 * v.z; o[2][3] += p2 * v.w;
            o[3][0] += p3 * v.x; o[3][1] += p3 * v.y; o[3][2] += p3 * v.z; o[3][3] += p3 * v.w;
        }
    }

#pragma unroll
    for (int i = 0; i < 4; i++) {
        const float inv = 1.f / l[i];
        float4 v = make_float4(o[i][0] * inv, o[i][1] * inv,
                               o[i][2] * inv, o[i][3] * inv);
        *(float4*)(O + qbase + (long long)(ty * 4 + i) * Hd + tx * 4) = v;
    }
}

// ---------------------------------------------------------------------------
// Residual + LayerNorm
// ---------------------------------------------------------------------------
__global__ __launch_bounds__(256) void k_ln(
    const float* __restrict__ X, const float* __restrict__ Rres,
    const float* __restrict__ gam, const float* __restrict__ bet,
    float* __restrict__ out)
{
    const int row = blockIdx.x;
    const long long base = (long long)row * Hd;
    const int tid = threadIdx.x;

    float v[3];
    float s = 0.f, s2 = 0.f;
#pragma unroll
    for (int u = 0; u < 3; u++) {
        const int idx = tid + u * 256;
        const float val = X[base + idx] + Rres[base + idx];
        v[u] = val; s += val; s2 += val * val;
    }
#pragma unroll
    for (int off = 16; off >= 1; off >>= 1) {
        s  += __shfl_xor_sync(0xffffffffu, s, off);
        s2 += __shfl_xor_sync(0xffffffffu, s2, off);
    }
    __shared__ float ss[8], ss2[8], mv[2];
    const int wid = tid >> 5, lane = tid & 31;
    if (lane == 0) { ss[wid] = s; ss2[wid] = s2; }
    __syncthreads();
    if (tid == 0) {
        float S_ = 0.f, S2_ = 0.f;
        for (int w = 0; w < 8; w++) { S_ += ss[w]; S2_ += ss2[w]; }
        const float mean = S_ * (1.f / 768.f);
        const float var  = S2_ * (1.f / 768.f) - mean * mean;
        mv[0] = mean;
        mv[1] = rsqrtf(var + 1e-5f);
    }
    __syncthreads();
    const float mean = mv[0], rstd = mv[1];
#pragma unroll
    for (int u = 0; u < 3; u++) {
        const int idx = tid + u * 256;
        out[base + idx] = (v[u] - mean) * rstd * gam[idx] + bet[idx];
    }
}

// ---------------------------------------------------------------------------
// kernel_launch (exact R3 launch graph)
// ---------------------------------------------------------------------------
#define SYM(v, s) cudaGetSymbolAddress((void**)&v, s)

extern "C" void kernel_launch(void* const* d_in, const int* in_sizes, int n_in,
                              void* d_out, int out_size)
{
    const float* hs      = (const float*)d_in[0];
    const int*   lang    = (const int*)  d_in[1];
    const float* Wq_lang = (const float*)d_in[3];
    const float* bq_lang = (const float*)d_in[4];
    const float* Wk_lang = (const float*)d_in[5];
    const float* bk_lang = (const float*)d_in[6];
    const float* in_w    = (const float*)d_in[7];
    const float* in_b    = (const float*)d_in[8];
    const float* out_w   = (const float*)d_in[9];
    const float* out_b   = (const float*)d_in[10];
    const float* alignT  = (const float*)d_in[11];
    const float* proj_w  = (const float*)d_in[12];
    const float* proj_b  = (const float*)d_in[13];
    const float* ln_g    = (const float*)d_in[14];
    const float* ln_b    = (const float*)d_in[15];
    float* out = (float*)d_out;

    float *Qp, *Kp, *Vp, *ctx, *obuf;
    SYM(Qp, g_Q); SYM(Kp, g_K); SYM(Vp, g_V); SYM(ctx, g_ctx); SYM(obuf, g_o);

    bf16 *hs_h, *hs_l, *q_h, *q_l, *k_h, *k_l, *ctx_h, *ctx_l;
    bf16 *al_h, *al_l, *al2_h, *al2_l;
    SYM(hs_h, g_hs_h);   SYM(hs_l, g_hs_l);
    SYM(q_h, g_q_h);     SYM(q_l, g_q_l);
    SYM(k_h, g_k_h);     SYM(k_l, g_k_l);
    SYM(ctx_h, g_ctx_h); SYM(ctx_l, g_ctx_l);
    SYM(al_h, g_al_h);   SYM(al_l, g_al_l);
    SYM(al2_h, g_al2_h); SYM(al2_l, g_al2_l);

    bf16 *Wq_h, *Wq_l, *Wk_h, *Wk_l, *inw_h, *inw_l, *ow_h, *ow_l, *pw_h, *pw_l;
    SYM(Wq_h, g_Wq_h);   SYM(Wq_l, g_Wq_l);
    SYM(Wk_h, g_Wk_h);   SYM(Wk_l, g_Wk_l);
    SYM(inw_h, g_inw_h); SYM(inw_l, g_inw_l);
    SYM(ow_h, g_ow_h);   SYM(ow_l, g_ow_l);
    SYM(pw_h, g_pw_h);   SYM(pw_l, g_pw_l);

    bf16 *F_h, *F_l, *FT_h, *FT_l, *P1_h, *P1_l, *QT1_h, *QT1_l;
    bf16 *P2_h, *P2_l, *QT2_h, *QT2_l, *M_h, *M_l, *MT_h, *MT_l;
    SYM(F_h, g_F_h);   SYM(F_l, g_F_l);   SYM(FT_h, g_FT_h); SYM(FT_l, g_FT_l);
    SYM(P1_h, g_P1_h); SYM(P1_l, g_P1_l); SYM(QT1_h, g_QT1_h); SYM(QT1_l, g_QT1_l);
    SYM(P2_h, g_P2_h); SYM(P2_l, g_P2_l); SYM(QT2_h, g_QT2_h); SYM(QT2_l, g_QT2_l);
    SYM(M_h, g_M_h);   SYM(M_l, g_M_l);   SYM(MT_h, g_MT_h); SYM(MT_l, g_MT_l);

    unsigned char *fF, *fP1, *fP2;
    SYM(fF, g_fF); SYM(fP1, g_fP1); SYM(fP2, g_fP2);

    cudaFuncSetAttribute(tc_gemm<0, 0>, cudaFuncAttributeMaxDynamicSharedMemorySize, GEMM_SMEM);
    cudaFuncSetAttribute(tc_gemm<1, 0>, cudaFuncAttributeMaxDynamicSharedMemorySize, GEMM_SMEM);
    cudaFuncSetAttribute(tc_gemm<1, 1>, cudaFuncAttributeMaxDynamicSharedMemorySize, GEMM_SMEM);
    cudaFuncSetAttribute(tc_chain,      cudaFuncAttributeMaxDynamicSharedMemorySize, GEMM_SMEM);

    const long long sBH = (long long)S * Hd;
    const dim3 thr(256);

    // --- conversions (weights + hs) ---
    k_conv<<<BS * Hd / 1024, thr>>>(hs, hs_h, hs_l);
    k_conv<<<(int)(NL * HH / 1024), thr>>>(Wq_lang, Wq_h, Wq_l);
    k_conv<<<(int)(NL * HH / 1024), thr>>>(Wk_lang, Wk_h, Wk_l);
    k_conv<<<(int)(3 * HH / 1024), thr>>>(in_w, inw_h, inw_l);
    k_conv<<<(int)(HH / 1024), thr>>>(out_w, ow_h, ow_l);
    k_conv<<<(int)(HH / 1024), thr>>>(proj_w, pw_h, pw_l);

    // --- chain ---
    k_flags<<<1, 32>>>(lang, fF, fP1, fP2);
    k_factors<<<dim3((int)(HH / 1024), NL * 8), thr>>>(alignT, lang, F_h, F_l, FT_h, FT_l);
    tc_chain<<<dim3(6, 6, NL * 4), thr, GEMM_SMEM>>>(F_h, F_l, FT_h, FT_l, fF,
                                                     P1_h, P1_l, QT1_h, QT1_l, 8, 4);
    tc_chain<<<dim3(6, 6, NL * 2), thr, GEMM_SMEM>>>(P1_h, P1_l, QT1_h, QT1_l, fP1,
                                                     P2_h, P2_l, QT2_h, QT2_l, 4, 2);
    tc_chain<<<dim3(6, 6, NL), thr, GEMM_SMEM>>>(P2_h, P2_l, QT2_h, QT2_l, fP2,
                                                 M_h, M_l, MT_h, MT_l, 2, 1);

    // --- per-language q/k projections (bf16 out) ---
    tc_gemm<1, 1><<<dim3(6, 6, Bsz), thr, GEMM_SMEM>>>(
        hs_h, hs_l, sBH, Wq_h, Wq_l, bq_lang, lang, nullptr, q_h, q_l, sBH);
    tc_gemm<1, 1><<<dim3(6, 6, Bsz), thr, GEMM_SMEM>>>(
        hs_h, hs_l, sBH, Wk_h, Wk_l, bk_lang, lang, nullptr, k_h, k_l, sBH);

    // --- QKV (fp32 out) ---
    tc_gemm<0, 0><<<dim3(6, 48, 1), thr, GEMM_SMEM>>>(
        q_h, q_l, 0, inw_h, inw_l, in_b, nullptr, Qp, nullptr, nullptr, 0);
    tc_gemm<0, 0><<<dim3(6, 48, 1), thr, GEMM_SMEM>>>(
        k_h, k_l, 0, inw_h + HH, inw_l + HH, in_b + Hd, nullptr, Kp, nullptr, nullptr, 0);
    tc_gemm<0, 0><<<dim3(6, 48, 1), thr, GEMM_SMEM>>>(
        hs_h, hs_l, 0, inw_h + 2 * HH, inw_l + 2 * HH, in_b + 2 * Hd, nullptr,
        Vp, nullptr, nullptr, 0);

    // --- attention ---
    k_attn<<<dim3(S / 64, NH, Bsz), thr>>>(Qp, Kp, Vp, ctx);
    k_conv<<<BS * Hd / 1024, thr>>>(ctx, ctx_h, ctx_l);

    // --- out_proj (bf16 out) ---
    tc_gemm<1, 0><<<dim3(6, 48, 1), thr, GEMM_SMEM>>>(
        ctx_h, ctx_l, 0, ow_h, ow_l, out_b, nullptr, nullptr, al_h, al_l, 0);

    // --- aligned @ M[lang[b]] (bf16 out, W = M^T selected per batch) ---
    tc_gemm<1, 1><<<dim3(6, 6, Bsz), thr, GEMM_SMEM>>>(
        al_h, al_l, sBH, MT_h, MT_l, nullptr, lang, nullptr, al2_h, al2_l, sBH);

    // --- final proj (fp32 out) ---
    tc_gemm<0, 0><<<dim3(6, 48, 1), thr, GEMM_SMEM>>>(
        al2_h, al2_l, 0, pw_h, pw_l, proj_b, nullptr, obuf, nullptr, nullptr, 0);

    // --- residual + LayerNorm ---
    k_ln<<<BS, thr>>>(obuf, hs, ln_g, ln_b, out);
}

// round 7
// speedup vs baseline: 1.6256x; 1.0451x over previous
#include <cuda_runtime.h>
#include <cuda_bf16.h>
#include <cstdint>

// ---------------------------------------------------------------------------
// Problem constants
// ---------------------------------------------------------------------------
constexpr int Bsz = 8;
constexpr int S   = 768;
constexpr int Hd  = 768;
constexpr int NH  = 12;
constexpr int NL  = 5;
constexpr int BS  = Bsz * S;                 // 6144 rows
constexpr long long HH = (long long)Hd * Hd; // 589824

typedef __nv_bfloat16 bf16;

// ---------------------------------------------------------------------------
// Scratch (static device globals)
// ---------------------------------------------------------------------------
__device__ float g_Q  [BS * Hd];
__device__ float g_K  [BS * Hd];
__device__ float g_V  [BS * Hd];
__device__ float g_ctx[BS * Hd];
__device__ float g_o  [BS * Hd];

__device__ bf16 g_hs_h [BS * Hd], g_hs_l [BS * Hd];
__device__ bf16 g_q_h  [BS * Hd], g_q_l  [BS * Hd];
__device__ bf16 g_k_h  [BS * Hd], g_k_l  [BS * Hd];
__device__ bf16 g_ctx_h[BS * Hd], g_ctx_l[BS * Hd];
__device__ bf16 g_al_h [BS * Hd], g_al_l [BS * Hd];
__device__ bf16 g_al2_h[BS * Hd], g_al2_l[BS * Hd];

__device__ bf16 g_Wq_h [NL * Hd * Hd], g_Wq_l [NL * Hd * Hd];
__device__ bf16 g_Wk_h [NL * Hd * Hd], g_Wk_l [NL * Hd * Hd];
__device__ bf16 g_inw_h[3 * Hd * Hd],  g_inw_l[3 * Hd * Hd];
__device__ bf16 g_ow_h [Hd * Hd],      g_ow_l [Hd * Hd];
__device__ bf16 g_pw_h [Hd * Hd],      g_pw_l [Hd * Hd];

__device__ bf16 g_F_h [NL * 8 * Hd * Hd], g_F_l [NL * 8 * Hd * Hd];
__device__ bf16 g_FT_h[NL * 8 * Hd * Hd], g_FT_l[NL * 8 * Hd * Hd];
__device__ bf16 g_P1_h[NL * 4 * Hd * Hd], g_P1_l[NL * 4 * Hd * Hd];
__device__ bf16 g_QT1_h[NL * 4 * Hd * Hd], g_QT1_l[NL * 4 * Hd * Hd];
__device__ bf16 g_P2_h[NL * 2 * Hd * Hd], g_P2_l[NL * 2 * Hd * Hd];
__device__ bf16 g_QT2_h[NL * 2 * Hd * Hd], g_QT2_l[NL * 2 * Hd * Hd];
__device__ bf16 g_M_h [NL * Hd * Hd],     g_M_l [NL * Hd * Hd];
__device__ bf16 g_MT_h[NL * Hd * Hd],     g_MT_l[NL * Hd * Hd];

__device__ unsigned char g_fF [NL * 8];
__device__ unsigned char g_fP1[NL * 4];
__device__ unsigned char g_fP2[NL * 2];

// ---------------------------------------------------------------------------
// Small PTX helpers
// ---------------------------------------------------------------------------
__device__ __forceinline__ uint32_t smem_u32(const void* p) {
    return (uint32_t)__cvta_generic_to_shared(p);
}
__device__ __forceinline__ void cp16(uint32_t d, const void* s) {
    asm volatile("cp.async.cg.shared.global [%0], [%1], 16;"
                 :: "r"(d), "l"(s) : "memory");
}
__device__ __forceinline__ void cp_commit() {
    asm volatile("cp.async.commit_group;" ::: "memory");
}
template <int N>
__device__ __forceinline__ void cp_wait() {
    asm volatile("cp.async.wait_group %0;" :: "n"(N) : "memory");
}
__device__ __forceinline__ void ldsm4(uint32_t* r, uint32_t addr) {
    asm volatile("ldmatrix.sync.aligned.m8n8.x4.shared.b16 {%0,%1,%2,%3}, [%4];"
                 : "=r"(r[0]), "=r"(r[1]), "=r"(r[2]), "=r"(r[3]) : "r"(addr));
}
__device__ __forceinline__ void mma_bf16(float* d, const uint32_t* a,
                                         uint32_t b0, uint32_t b1) {
    asm volatile(
        "mma.sync.aligned.m16n8k16.row.col.f32.bf16.bf16.f32 "
        "{%0,%1,%2,%3}, {%4,%5,%6,%7}, {%8,%9}, {%0,%1,%2,%3};"
        : "+f"(d[0]), "+f"(d[1]), "+f"(d[2]), "+f"(d[3])
        : "r"(a[0]), "r"(a[1]), "r"(a[2]), "r"(a[3]), "r"(b0), "r"(b1));
}
__device__ __forceinline__ uint32_t pack_bf(bf16 a, bf16 b) {
    return (uint32_t)__bfloat16_as_ushort(a) |
           ((uint32_t)__bfloat16_as_ushort(b) << 16);
}

// ---------------------------------------------------------------------------
// GEMM config: 128x128 tile, BLK_K=32, 8 warps, 2-stage pipeline (R3 config)
// ---------------------------------------------------------------------------
constexpr int SKP     = 40;
constexpr int TILE_B  = 128 * SKP * 2;       // 10240 B
constexpr int STAGE_B = 4 * TILE_B;          // 40960 B (Ah Al Wh Wl)
constexpr int GEMM_SMEM = 2 * STAGE_B;       // 81920 B -> 2 CTAs/SM by smem

__device__ __forceinline__ void gemm_issue(
    const bf16* __restrict__ base, int lw, uint32_t sdst0, int kc)
{
    const bf16* g0 = base + kc * 32;
#pragma unroll
    for (int i = 0; i < 8; i++) {
        const int chunk = i * 64 + lw;
        const int row = chunk >> 2, cs = chunk & 3;
        cp16(sdst0 + row * (SKP * 2) + cs * 16,
             g0 + (long long)row * Hd + cs * 8);
    }
}

// MODE 0: fp32 out (+bias). MODE 1: bf16 hi/lo out (+bias if non-null).
// MODE 2: bf16 hi/lo out + transposed hi/lo out (no bias).
template <int MODE>
__device__ void gemm_core(
    const bf16* __restrict__ Ah, const bf16* __restrict__ Al,
    const bf16* __restrict__ Wh, const bf16* __restrict__ Wl,
    const float* __restrict__ bias,
    float* __restrict__ C,
    bf16* __restrict__ Ch, bf16* __restrict__ Cl,
    bf16* __restrict__ Th, bf16* __restrict__ Tl,
    int m0, int n0)
{
    extern __shared__ char dsm[];
    const int tid = threadIdx.x;
    const int wid = tid >> 5, lane = tid & 31;
    const int m_off = (wid & 3) * 32;
    const int n_off = (wid >> 2) * 64;
    const uint32_t sbase = smem_u32(dsm);

    const int ltile = tid >> 6;
    const int lw = tid & 63;
    const bf16* gbase =
        (ltile == 0) ? Ah + (long long)m0 * Hd :
        (ltile == 1) ? Al + (long long)m0 * Hd :
        (ltile == 2) ? Wh + (long long)n0 * Hd :
                       Wl + (long long)n0 * Hd;
    const uint32_t sdst_tile = ltile * TILE_B;

    gemm_issue(gbase, lw, sbase + sdst_tile, 0);             cp_commit();
    gemm_issue(gbase, lw, sbase + STAGE_B + sdst_tile, 1);   cp_commit();

    float acc[2][8][4];
#pragma unroll
    for (int mi = 0; mi < 2; mi++)
#pragma unroll
        for (int j = 0; j < 8; j++)
#pragma unroll
            for (int e = 0; e < 4; e++) acc[mi][j][e] = 0.f;

    const int r_off = ((lane >> 3) & 1) * 8 + (lane & 7);
    const int c_off = (lane >> 4) * 8;

    for (int kc = 0; kc < 24; kc++) {
        cp_wait<1>();
        __syncthreads();
        const uint32_t sb = sbase + (kc & 1) * STAGE_B;
        const uint32_t aAh = sb + (m_off + r_off) * (SKP * 2) + c_off * 2;
        const uint32_t aAl = aAh + TILE_B;
        const uint32_t aWh = sb + 2 * TILE_B + (n_off + r_off) * (SKP * 2) + c_off * 2;
        const uint32_t aWl = aWh + TILE_B;

#pragma unroll
        for (int kk = 0; kk < 2; kk++) {
            uint32_t ah[2][4], alr[2][4];
#pragma unroll
            for (int t = 0; t < 2; t++) {
                ldsm4(ah[t],  aAh + t * 16 * (SKP * 2) + kk * 32);
                ldsm4(alr[t], aAl + t * 16 * (SKP * 2) + kk * 32);
            }
#pragma unroll
            for (int u = 0; u < 4; u++) {
                uint32_t bh[4];
                ldsm4(bh, aWh + u * 16 * (SKP * 2) + kk * 32);
#pragma unroll
                for (int mi = 0; mi < 2; mi++) {
                    mma_bf16(acc[mi][2 * u],     ah[mi],  bh[0], bh[2]);
                    mma_bf16(acc[mi][2 * u + 1], ah[mi],  bh[1], bh[3]);
                    mma_bf16(acc[mi][2 * u],     alr[mi], bh[0], bh[2]);
                    mma_bf16(acc[mi][2 * u + 1], alr[mi], bh[1], bh[3]);
                }
                uint32_t bl[4];
                ldsm4(bl, aWl + u * 16 * (SKP * 2) + kk * 32);
#pragma unroll
                for (int mi = 0; mi < 2; mi++) {
                    mma_bf16(acc[mi][2 * u],     ah[mi], bl[0], bl[2]);
                    mma_bf16(acc[mi][2 * u + 1], ah[mi], bl[1], bl[3]);
                }
            }
        }
        __syncthreads();
        if (kc + 2 < 24)
            gemm_issue(gbase, lw, sbase + (kc & 1) * STAGE_B + sdst_tile, kc + 2);
        cp_commit();
    }

    // stage accumulators through SMEM (f32 [128][132])
    float* sf = (float*)dsm;
    const int g = lane >> 2, t2 = (lane & 3) * 2;
#pragma unroll
    for (int mi = 0; mi < 2; mi++)
#pragma unroll
        for (int j = 0; j < 8; j++) {
            const int r = m_off + mi * 16 + g;
            const int c = n_off + j * 8 + t2;
            sf[r * 132 + c]           = acc[mi][j][0];
            sf[r * 132 + c + 1]       = acc[mi][j][1];
            sf[(r + 8) * 132 + c]     = acc[mi][j][2];
            sf[(r + 8) * 132 + c + 1] = acc[mi][j][3];
        }
    __syncthreads();

    if (MODE == 0) {
#pragma unroll 4
        for (int i = 0; i < 16; i++) {
            const int task = i * 256 + tid;
            const int row = task >> 5, c4 = (task & 31) * 4;
            float4 v = *(float4*)&sf[row * 132 + c4];
            v.x += bias[n0 + c4 + 0];
            v.y += bias[n0 + c4 + 1];
            v.z += bias[n0 + c4 + 2];
            v.w += bias[n0 + c4 + 3];
            *(float4*)(C + (long long)(m0 + row) * Hd + n0 + c4) = v;
        }
    } else {
#pragma unroll 4
        for (int i = 0; i < 16; i++) {
            const int task = i * 256 + tid;
            const int row = task >> 5, c4 = (task & 31) * 4;
            float4 v = *(float4*)&sf[row * 132 + c4];
            if (MODE == 1 && bias) {
                v.x += bias[n0 + c4 + 0];
                v.y += bias[n0 + c4 + 1];
                v.z += bias[n0 + c4 + 2];
                v.w += bias[n0 + c4 + 3];
            }
            bf16 h0 = __float2bfloat16(v.x), h1 = __float2bfloat16(v.y);
            bf16 h2 = __float2bfloat16(v.z), h3 = __float2bfloat16(v.w);
            bf16 l0 = __float2bfloat16(v.x - __bfloat162float(h0));
            bf16 l1 = __float2bfloat16(v.y - __bfloat162float(h1));
            bf16 l2 = __float2bfloat16(v.z - __bfloat162float(h2));
            bf16 l3 = __float2bfloat16(v.w - __bfloat162float(h3));
            const long long off = (long long)(m0 + row) * Hd + n0 + c4;
            *(uint2*)(Ch + off) = make_uint2(pack_bf(h0, h1), pack_bf(h2, h3));
            *(uint2*)(Cl + off) = make_uint2(pack_bf(l0, l1), pack_bf(l2, l3));
        }
        if (MODE == 2) {
            const int c = tid & 127;
            const int half = tid >> 7;
#pragma unroll 4
            for (int i = 0; i < 16; i++) {
                const int r4 = half * 64 + i * 4;
                float v0 = sf[(r4 + 0) * 132 + c];
                float v1 = sf[(r4 + 1) * 132 + c];
                float v2 = sf[(r4 + 2) * 132 + c];
                float v3 = sf[(r4 + 3) * 132 + c];
                bf16 h0 = __float2bfloat16(v0), h1 = __float2bfloat16(v1);
                bf16 h2 = __float2bfloat16(v2), h3 = __float2bfloat16(v3);
                bf16 l0 = __float2bfloat16(v0 - __bfloat162float(h0));
                bf16 l1 = __float2bfloat16(v1 - __bfloat162float(h1));
                bf16 l2 = __float2bfloat16(v2 - __bfloat162float(h2));
                bf16 l3 = __float2bfloat16(v3 - __bfloat162float(h3));
                const long long off = (long long)(n0 + c) * Hd + m0 + r4;
                *(uint2*)(Th + off) = make_uint2(pack_bf(h0, h1), pack_bf(h2, h3));
                *(uint2*)(Tl + off) = make_uint2(pack_bf(l0, l1), pack_bf(l2, l3));
            }
        }
    }
}

// ---------------------------------------------------------------------------
// GEMM wrappers — SINGLE VARIABLE THIS ROUND: min 2 blocks/SM
// ---------------------------------------------------------------------------
template <int MODE, int WSEL>
__global__ __launch_bounds__(256, 2) void tc_gemm(
    const bf16* __restrict__ Ah, const bf16* __restrict__ Al, long long sAz,
    const bf16* __restrict__ Wh, const bf16* __restrict__ Wl,
    const float* __restrict__ bias, const int* __restrict__ lang,
    float* __restrict__ C, bf16* __restrict__ Ch, bf16* __restrict__ Cl,
    long long sCz)
{
    const int z = blockIdx.z;
    const bf16* wh = Wh;
    const bf16* wl = Wl;
    const float* bs = bias;
    if (WSEL) {
        const int lg = __ldg(&lang[z]);
        wh += (long long)lg * HH;
        wl += (long long)lg * HH;
        if (bias) bs += lg * Hd;
    }
    const long long ao = (long long)z * sAz;
    const long long co = (long long)z * sCz;
    gemm_core<MODE>(Ah + ao, Al + ao, wh, wl, bs,
                    (MODE == 0) ? C + co : nullptr,
                    (MODE != 0) ? Ch + co : nullptr,
                    (MODE != 0) ? Cl + co : nullptr,
                    nullptr, nullptr,
                    blockIdx.y * 128, blockIdx.x * 128);
}

__global__ __launch_bounds__(256, 2) void tc_chain(
    const bf16* __restrict__ sN_h, const bf16* __restrict__ sN_l,
    const bf16* __restrict__ sT_h, const bf16* __restrict__ sT_l,
    const unsigned char* __restrict__ fs,
    bf16* __restrict__ dN_h, bf16* __restrict__ dN_l,
    bf16* __restrict__ dT_h, bf16* __restrict__ dT_l,
    int spa, int dpa)
{
    const int z = blockIdx.z;
    const int a = z / dpa, p = z - a * dpa;
    const int li = a * spa + 2 * p;
    const unsigned char f1 = fs[li], f2 = fs[li + 1];
    const long long zo = (long long)z * HH;
    const int m0 = blockIdx.y * 128, n0 = blockIdx.x * 128;
    const int tid = threadIdx.x;

    if (f1 & f2) {
#pragma unroll 4
        for (int i = 0; i < 16; i++) {
            const int task = i * 256 + tid;
            const int row = task >> 5, c4 = (task & 31) * 4;
            const int gr = m0 + row, gc = n0 + c4;
            bf16 one = __float2bfloat16(1.f), zero = __float2bfloat16(0.f);
            bf16 h0 = (gc + 0 == gr) ? one : zero;
            bf16 h1 = (gc + 1 == gr) ? one : zero;
            bf16 h2 = (gc + 2 == gr) ? one : zero;
            bf16 h3 = (gc + 3 == gr) ? one : zero;
            const long long off = zo + (long long)gr * Hd + gc;
            uint2 hv = make_uint2(pack_bf(h0, h1), pack_bf(h2, h3));
            uint2 lv = make_uint2(0u, 0u);
            *(uint2*)(dN_h + off) = hv; *(uint2*)(dN_l + off) = lv;
            *(uint2*)(dT_h + off) = hv; *(uint2*)(dT_l + off) = lv;
        }
        return;
    }
    if (f1 | f2) {
        const long long so = (long long)(f1 ? li + 1 : li) * HH;
#pragma unroll 4
        for (int i = 0; i < 8; i++) {
            const int idx = i * 256 + tid;
            const int row = idx >> 4, c8 = (idx & 15) * 8;
            const long long doff = zo + (long long)(m0 + row) * Hd + n0 + c8;
            const long long soff = so + (long long)(m0 + row) * Hd + n0 + c8;
            *(uint4*)(dN_h + doff) = *(const uint4*)(sN_h + soff);
            *(uint4*)(dN_l + doff) = *(const uint4*)(sN_l + soff);
            *(uint4*)(dT_h + doff) = *(const uint4*)(sT_h + soff);
            *(uint4*)(dT_l + doff) = *(const uint4*)(sT_l + soff);
        }
        return;
    }
    gemm_core<2>(sN_h + (long long)li * HH, sN_l + (long long)li * HH,
                 sT_h + (long long)(li + 1) * HH, sT_l + (long long)(li + 1) * HH,
                 nullptr, nullptr,
                 dN_h + zo, dN_l + zo, dT_h + zo, dT_l + zo, m0, n0);
}

// ---------------------------------------------------------------------------
// fp32 -> bf16 hi/lo conversion
// ---------------------------------------------------------------------------
__global__ __launch_bounds__(256) void k_conv(
    const float* __restrict__ src, bf16* __restrict__ dh,
    bf16* __restrict__ dl)
{
    const long long i4 = ((long long)blockIdx.x * 256 + threadIdx.x) * 4;
    float4 v = *(const float4*)(src + i4);
    bf16 h0 = __float2bfloat16(v.x), h1 = __float2bfloat16(v.y);
    bf16 h2 = __float2bfloat16(v.z), h3 = __float2bfloat16(v.w);
    bf16 l0 = __float2bfloat16(v.x - __bfloat162float(h0));
    bf16 l1 = __float2bfloat16(v.y - __bfloat162float(h1));
    bf16 l2 = __float2bfloat16(v.z - __bfloat162float(h2));
    bf16 l3 = __float2bfloat16(v.w - __bfloat162float(h3));
    *(uint2*)(dh + i4) = make_uint2(pack_bf(h0, h1), pack_bf(h2, h3));
    *(uint2*)(dl + i4) = make_uint2(pack_bf(l0, l1), pack_bf(l2, l3));
}

// ---------------------------------------------------------------------------
// Chain flags + leaf factors
// ---------------------------------------------------------------------------
__global__ void k_flags(const int* __restrict__ lang,
                        unsigned char* fF, unsigned char* fP1, unsigned char* fP2)
{
    if (threadIdx.x == 0 && blockIdx.x == 0) {
        for (int a = 0; a < NL; a++) {
            for (int j = 0; j < 8; j++) fF[a * 8 + j] = (lang[j] == a) ? 1 : 0;
            for (int p = 0; p < 4; p++)
                fP1[a * 4 + p] = fF[a * 8 + 2 * p] & fF[a * 8 + 2 * p + 1];
            for (int p = 0; p < 2; p++)
                fP2[a * 2 + p] = fP1[a * 4 + 2 * p] & fP1[a * 4 + 2 * p + 1];
        }
    }
}

__device__ __forceinline__ void split_store4(
    bf16* dh, bf16* dl, long long off, float x, float y, float z, float w)
{
    bf16 h0 = __float2bfloat16(x), h1 = __float2bfloat16(y);
    bf16 h2 = __float2bfloat16(z), h3 = __float2bfloat16(w);
    bf16 l0 = __float2bfloat16(x - __bfloat162float(h0));
    bf16 l1 = __float2bfloat16(y - __bfloat162float(h1));
    bf16 l2 = __float2bfloat16(z - __bfloat162float(h2));
    bf16 l3 = __float2bfloat16(w - __bfloat162float(h3));
    *(uint2*)(dh + off) = make_uint2(pack_bf(h0, h1), pack_bf(h2, h3));
    *(uint2*)(dl + off) = make_uint2(pack_bf(l0, l1), pack_bf(l2, l3));
}

__global__ __launch_bounds__(256) void k_factors(
    const float* __restrict__ alignT, const int* __restrict__ lang,
    bf16* __restrict__ Fh, bf16* __restrict__ Fl,
    bf16* __restrict__ FTh, bf16* __restrict__ FTl)
{
    const int node = blockIdx.y;
    const int a = node >> 3, j = node & 7;
    const int c = __ldg(&lang[j]);
    const long long nb = (long long)node * HH;
    const long long i4 = ((long long)blockIdx.x * 256 + threadIdx.x) * 4;
    const int r = (int)(i4 / Hd), col = (int)(i4 % Hd);

    if (c == a) {
        float v0 = (col + 0 == r) ? 1.f : 0.f;
        float v1 = (col + 1 == r) ? 1.f : 0.f;
        float v2 = (col + 2 == r) ? 1.f : 0.f;
        float v3 = (col + 3 == r) ? 1.f : 0.f;
        split_store4(Fh,  Fl,  nb + i4, v0, v1, v2, v3);
        split_store4(FTh, FTl, nb + i4, v0, v1, v2, v3);
    } else {
        const float* sm = alignT + (long long)(a * NL + c) * HH;
        float4 v = *(const float4*)(sm + i4);
        split_store4(Fh, Fl, nb + i4, v.x, v.y, v.z, v.w);
        float t0 = sm[(long long)(col + 0) * Hd + r];
        float t1 = sm[(long long)(col + 1) * Hd + r];
        float t2 = sm[(long long)(col + 2) * Hd + r];
        float t3 = sm[(long long)(col + 3) * Hd + r];
        split_store4(FTh, FTl, nb + i4, t0, t1, t2, t3);
    }
}

// ---------------------------------------------------------------------------
// Flash attention (fp32 SIMT)
// ---------------------------------------------------------------------------
__global__ __launch_bounds__(256) void k_attn(
    const float* __restrict__ Q, const float* __restrict__ K,
    const float* __restrict__ V, float* __restrict__ O)
{
    __shared__ float Qs[64 * 64];
    __shared__ float KP[64 * 64];
    __shared__ float Vs[64 * 64];

    const int qt = blockIdx.x, h = blockIdx.y, b = blockIdx.z;
    const int tid = threadIdx.x;
    const int ty = tid >> 4, tx = tid & 15;
    const long long qbase = ((long long)(b * S + qt * 64)) * Hd + h * 64;

#pragma unroll
    for (int u = 0; u < 4; u++) {
        const int fidx = u * 256 + tid;
        const int r = fidx >> 4;
        const int d = (fidx & 15) * 4;
        float4 v = *(const float4*)(Q + qbase + (long long)r * Hd + d);
        v.x *= 0.125f; v.y *= 0.125f; v.z *= 0.125f; v.w *= 0.125f;
        *(float4*)&Qs[r * 64 + d] = v;
    }

    float m[4], l[4], o[4][4];
#pragma unroll
    for (int i = 0; i < 4; i++) {
        m[i] = -1e30f; l[i] = 0.f;
#pragma unroll
        for (int j = 0; j < 4; j++) o[i][j] = 0.f;
    }

    for (int kt = 0; kt < S / 64; kt++) {
        const long long kbase = ((long long)(b * S + kt * 64)) * Hd + h * 64;
        __syncthreads();
#pragma unroll
        for (int u = 0; u < 4; u++) {
            const int fidx = u * 256 + tid;
            const int r = fidx >> 4;
            const int d = (fidx & 15) * 4;
            float4 kv = *(const float4*)(K + kbase + (long long)r * Hd + d);
            KP[(d + 0) * 64 + r] = kv.x;
            KP[(d + 1) * 64 + r] = kv.y;
            KP[(d + 2) * 64 + r] = kv.z;
            KP[(d + 3) * 64 + r] = kv.w;
            *(float4*)&Vs[r * 64 + d] =
                *(const float4*)(V + kbase + (long long)r * Hd + d);
        }
        __syncthreads();

        float s[4][4];
#pragma unroll
        for (int i = 0; i < 4; i++)
#pragma unroll
            for (int j = 0; j < 4; j++) s[i][j] = 0.f;

#pragma unroll
        for (int d0 = 0; d0 < 64; d0 += 4) {
            float a0[4], a1[4], a2[4], a3[4];
            *(float4*)a0 = *(const float4*)&Qs[(ty * 4 + 0) * 64 + d0];
            *(float4*)a1 = *(const float4*)&Qs[(ty * 4 + 1) * 64 + d0];
            *(float4*)a2 = *(const float4*)&Qs[(ty * 4 + 2) * 64 + d0];
            *(float4*)a3 = *(const float4*)&Qs[(ty * 4 + 3) * 64 + d0];
#pragma unroll
            for (int dd = 0; dd < 4; dd++) {
                const float b0 = KP[(d0 + dd) * 64 + tx];
                const float b1 = KP[(d0 + dd) * 64 + tx + 16];
                const float b2 = KP[(d0 + dd) * 64 + tx + 32];
                const float b3 = KP[(d0 + dd) * 64 + tx + 48];
                s[0][0] += a0[dd] * b0; s[0][1] += a0[dd] * b1;
                s[0][2] += a0[dd] * b2; s[0][3] += a0[dd] * b3;
                s[1][0] += a1[dd] * b0; s[1][1] += a1[dd] * b1;
                s[1][2] += a1[dd] * b2; s[1][3] += a1[dd] * b3;
                s[2][0] += a2[dd] * b0; s[2][1] += a2[dd] * b1;
                s[2][2] += a2[dd] * b2; s[2][3] += a2[dd] * b3;
                s[3][0] += a3[dd] * b0; s[3][1] += a3[dd] * b1;
                s[3][2] += a3[dd] * b2; s[3][3] += a3[dd] * b3;
            }
        }

        float p[4][4];
#pragma unroll
        for (int i = 0; i < 4; i++) {
            float mx = fmaxf(fmaxf(s[i][0], s[i][1]), fmaxf(s[i][2], s[i][3]));
#pragma unroll
            for (int off = 8; off >= 1; off >>= 1)
                mx = fmaxf(mx, __shfl_xor_sync(0xffffffffu, mx, off));
            const float mn = fmaxf(m[i], mx);
            const float alpha = __expf(m[i] - mn);
            m[i] = mn;
            float rs = 0.f;
#pragma unroll
            for (int j = 0; j < 4; j++) {
                p[i][j] = __expf(s[i][j] - mn);
                rs += p[i][j];
            }
#pragma unroll
            for (int off = 8; off >= 1; off >>= 1)
                rs += __shfl_xor_sync(0xffffffffu, rs, off);
            l[i] = l[i] * alpha + rs;
            o[i][0] *= alpha; o[i][1] *= alpha;
            o[i][2] *= alpha; o[i][3] *= alpha;
        }

        __syncthreads();
#pragma unroll
        for (int i = 0; i < 4; i++)
#pragma unroll
            for (int j = 0; j < 4; j++)
                KP[(ty * 4 + i) * 64 + tx + 16 * j] = p[i][j];
        __syncthreads();

#pragma unroll
        for (int k = 0; k < 64; k++) {
            const float4 v = *(const float4*)&Vs[k * 64 + tx * 4];
            const float p0 = KP[(ty * 4 + 0) * 64 + k];
            const float p1 = KP[(ty * 4 + 1) * 64 + k];
            const float p2 = KP[(ty * 4 + 2) * 64 + k];
            const float p3 = KP[(ty * 4 + 3) * 64 + k];
            o[0][0] += p0 * v.x; o[0][1] += p0 * v.y; o[0][2] += p0 * v.z; o[0][3] += p0 * v.w;
            o[1][0] += p1 * v.x; o[1][1] += p1 * v.y; o[1][2] += p1 * v.z; o[1][3] += p1 * v.w;
            o[2][0] += p2 * v.x; o[2][1] += p2 * v.y; o[2][2] += p2 * v.z; o[2][3] += p2 * v.w;
            o[3][0] += p3 * v.x; o[3][1] += p3 * v.y; o[3][2] += p3 * v.z; o[3][3] += p3 * v.w;
        }
    }

#pragma unroll
    for (int i = 0; i < 4; i++) {
        const float inv = 1.f / l[i];
        float4 v = make_float4(o[i][0] * inv, o[i][1] * inv,
                               o[i][2] * inv, o[i][3] * inv);
        *(float4*)(O + qbase + (long long)(ty * 4 + i) * Hd + tx * 4) = v;
    }
}

// ---------------------------------------------------------------------------
// Residual + LayerNorm
// ---------------------------------------------------------------------------
__global__ __launch_bounds__(256) void k_ln(
    const float* __restrict__ X, const float* __restrict__ Rres,
    const float* __restrict__ gam, const float* __restrict__ bet,
    float* __restrict__ out)
{
    const int row = blockIdx.x;
    const long long base = (long long)row * Hd;
    const int tid = threadIdx.x;

    float v[3];
    float s = 0.f, s2 = 0.f;
#pragma unroll
    for (int u = 0; u < 3; u++) {
        const int idx = tid + u * 256;
        const float val = X[base + idx] + Rres[base + idx];
        v[u] = val; s += val; s2 += val * val;
    }
#pragma unroll
    for (int off = 16; off >= 1; off >>= 1) {
        s  += __shfl_xor_sync(0xffffffffu, s, off);
        s2 += __shfl_xor_sync(0xffffffffu, s2, off);
    }
    __shared__ float ss[8], ss2[8], mv[2];
    const int wid = tid >> 5, lane = tid & 31;
    if (lane == 0) { ss[wid] = s; ss2[wid] = s2; }
    __syncthreads();
    if (tid == 0) {
        float S_ = 0.f, S2_ = 0.f;
        for (int w = 0; w < 8; w++) { S_ += ss[w]; S2_ += ss2[w]; }
        const float mean = S_ * (1.f / 768.f);
        const float var  = S2_ * (1.f / 768.f) - mean * mean;
        mv[0] = mean;
        mv[1] = rsqrtf(var + 1e-5f);
    }
    __syncthreads();
    const float mean = mv[0], rstd = mv[1];
#pragma unroll
    for (int u = 0; u < 3; u++) {
        const int idx = tid + u * 256;
        out[base + idx] = (v[u] - mean) * rstd * gam[idx] + bet[idx];
    }
}

// ---------------------------------------------------------------------------
// kernel_launch — reordered so launch index 5 is a big tc_gemm (ncu -s 5 -c 1
// then profiles the GEMM, not a conversion kernel)
// ---------------------------------------------------------------------------
#define SYM(v, s) cudaGetSymbolAddress((void**)&v, s)

extern "C" void kernel_launch(void* const* d_in, const int* in_sizes, int n_in,
                              void* d_out, int out_size)
{
    const float* hs      = (const float*)d_in[0];
    const int*   lang    = (const int*)  d_in[1];
    const float* Wq_lang = (const float*)d_in[3];
    const float* bq_lang = (const float*)d_in[4];
    const float* Wk_lang = (const float*)d_in[5];
    const float* bk_lang = (const float*)d_in[6];
    const float* in_w    = (const float*)d_in[7];
    const float* in_b    = (const float*)d_in[8];
    const float* out_w   = (const float*)d_in[9];
    const float* out_b   = (const float*)d_in[10];
    const float* alignT  = (const float*)d_in[11];
    const float* proj_w  = (const float*)d_in[12];
    const float* proj_b  = (const float*)d_in[13];
    const float* ln_g    = (const float*)d_in[14];
    const float* ln_b    = (const float*)d_in[15];
    float* out = (float*)d_out;

    float *Qp, *Kp, *Vp, *ctx, *obuf;
    SYM(Qp, g_Q); SYM(Kp, g_K); SYM(Vp, g_V); SYM(ctx, g_ctx); SYM(obuf, g_o);

    bf16 *hs_h, *hs_l, *q_h, *q_l, *k_h, *k_l, *ctx_h, *ctx_l;
    bf16 *al_h, *al_l, *al2_h, *al2_l;
    SYM(hs_h, g_hs_h);   SYM(hs_l, g_hs_l);
    SYM(q_h, g_q_h);     SYM(q_l, g_q_l);
    SYM(k_h, g_k_h);     SYM(k_l, g_k_l);
    SYM(ctx_h, g_ctx_h); SYM(ctx_l, g_ctx_l);
    SYM(al_h, g_al_h);   SYM(al_l, g_al_l);
    SYM(al2_h, g_al2_h); SYM(al2_l, g_al2_l);

    bf16 *Wq_h, *Wq_l, *Wk_h, *Wk_l, *inw_h, *inw_l, *ow_h, *ow_l, *pw_h, *pw_l;
    SYM(Wq_h, g_Wq_h);   SYM(Wq_l, g_Wq_l);
    SYM(Wk_h, g_Wk_h);   SYM(Wk_l, g_Wk_l);
    SYM(inw_h, g_inw_h); SYM(inw_l, g_inw_l);
    SYM(ow_h, g_ow_h);   SYM(ow_l, g_ow_l);
    SYM(pw_h, g_pw_h);   SYM(pw_l, g_pw_l);

    bf16 *F_h, *F_l, *FT_h, *FT_l, *P1_h, *P1_l, *QT1_h, *QT1_l;
    bf16 *P2_h, *P2_l, *QT2_h, *QT2_l, *M_h, *M_l, *MT_h, *MT_l;
    SYM(F_h, g_F_h);   SYM(F_l, g_F_l);   SYM(FT_h, g_FT_h); SYM(FT_l, g_FT_l);
    SYM(P1_h, g_P1_h); SYM(P1_l, g_P1_l); SYM(QT1_h, g_QT1_h); SYM(QT1_l, g_QT1_l);
    SYM(P2_h, g_P2_h); SYM(P2_l, g_P2_l); SYM(QT2_h, g_QT2_h); SYM(QT2_l, g_QT2_l);
    SYM(M_h, g_M_h);   SYM(M_l, g_M_l);   SYM(MT_h, g_MT_h); SYM(MT_l, g_MT_l);

    unsigned char *fF, *fP1, *fP2;
    SYM(fF, g_fF); SYM(fP1, g_fP1); SYM(fP2, g_fP2);

    cudaFuncSetAttribute(tc_gemm<0, 0>, cudaFuncAttributeMaxDynamicSharedMemorySize, GEMM_SMEM);
    cudaFuncSetAttribute(tc_gemm<1, 0>, cudaFuncAttributeMaxDynamicSharedMemorySize, GEMM_SMEM);
    cudaFuncSetAttribute(tc_gemm<1, 1>, cudaFuncAttributeMaxDynamicSharedMemorySize, GEMM_SMEM);
    cudaFuncSetAttribute(tc_chain,      cudaFuncAttributeMaxDynamicSharedMemorySize, GEMM_SMEM);

    const long long sBH = (long long)S * Hd;
    const dim3 thr(256);

    // launches 0..4: conversions needed by the q-projection
    k_conv<<<BS * Hd / 1024, thr>>>(hs, hs_h, hs_l);                 // 0
    k_conv<<<(int)(NL * HH / 1024), thr>>>(Wq_lang, Wq_h, Wq_l);     // 1
    k_conv<<<(int)(NL * HH / 1024), thr>>>(Wk_lang, Wk_h, Wk_l);     // 2
    k_conv<<<(int)(3 * HH / 1024), thr>>>(in_w, inw_h, inw_l);       // 3
    k_conv<<<(int)(HH / 1024), thr>>>(out_w, ow_h, ow_l);            // 4

    // launch 5: PROFILED GEMM — per-language q projection
    tc_gemm<1, 1><<<dim3(6, 6, Bsz), thr, GEMM_SMEM>>>(
        hs_h, hs_l, sBH, Wq_h, Wq_l, bq_lang, lang, nullptr, q_h, q_l, sBH);
    tc_gemm<1, 1><<<dim3(6, 6, Bsz), thr, GEMM_SMEM>>>(
        hs_h, hs_l, sBH, Wk_h, Wk_l, bk_lang, lang, nullptr, k_h, k_l, sBH);

    // remaining conversions + chain
    k_conv<<<(int)(HH / 1024), thr>>>(proj_w, pw_h, pw_l);
    k_flags<<<1, 32>>>(lang, fF, fP1, fP2);
    k_factors<<<dim3((int)(HH / 1024), NL * 8), thr>>>(alignT, lang, F_h, F_l, FT_h, FT_l);
    tc_chain<<<dim3(6, 6, NL * 4), thr, GEMM_SMEM>>>(F_h, F_l, FT_h, FT_l, fF,
                                                     P1_h, P1_l, QT1_h, QT1_l, 8, 4);
    tc_chain<<<dim3(6, 6, NL * 2), thr, GEMM_SMEM>>>(P1_h, P1_l, QT1_h, QT1_l, fP1,
                                                     P2_h, P2_l, QT2_h, QT2_l, 4, 2);
    tc_chain<<<dim3(6, 6, NL), thr, GEMM_SMEM>>>(P2_h, P2_l, QT2_h, QT2_l, fP2,
                                                 M_h, M_l, MT_h, MT_l, 2, 1);

    // QKV (fp32 out)
    tc_gemm<0, 0><<<dim3(6, 48, 1), thr, GEMM_SMEM>>>(
        q_h, q_l, 0, inw_h, inw_l, in_b, nullptr, Qp, nullptr, nullptr, 0);
    tc_gemm<0, 0><<<dim3(6, 48, 1), thr, GEMM_SMEM>>>(
        k_h, k_l, 0, inw_h + HH, inw_l + HH, in_b + Hd, nullptr, Kp, nullptr, nullptr, 0);
    tc_gemm<0, 0><<<dim3(6, 48, 1), thr, GEMM_SMEM>>>(
        hs_h, hs_l, 0, inw_h + 2 * HH, inw_l + 2 * HH, in_b + 2 * Hd, nullptr,
        Vp, nullptr, nullptr, 0);

    // attention
    k_attn<<<dim3(S / 64, NH, Bsz), thr>>>(Qp, Kp, Vp, ctx);
    k_conv<<<BS * Hd / 1024, thr>>>(ctx, ctx_h, ctx_l);

    // out_proj (bf16 out)
    tc_gemm<1, 0><<<dim3(6, 48, 1), thr, GEMM_SMEM>>>(
        ctx_h, ctx_l, 0, ow_h, ow_l, out_b, nullptr, nullptr, al_h, al_l, 0);

    // aligned @ M[lang[b]]
    tc_gemm<1, 1><<<dim3(6, 6, Bsz), thr, GEMM_SMEM>>>(
        al_h, al_l, sBH, MT_h, MT_l, nullptr, lang, nullptr, al2_h, al2_l, sBH);

    // final proj (fp32 out)
    tc_gemm<0, 0><<<dim3(6, 48, 1), thr, GEMM_SMEM>>>(
        al2_h, al2_l, 0, pw_h, pw_l, proj_b, nullptr, obuf, nullptr, nullptr, 0);

    // residual + LayerNorm
    k_ln<<<BS, thr>>>(obuf, hs, ln_g, ln_b, out);
}

// round 8
// speedup vs baseline: 1.9236x; 1.1833x over previous
#include <cuda_runtime.h>
#include <cuda_bf16.h>
#include <cstdint>

// ---------------------------------------------------------------------------
// Problem constants
// ---------------------------------------------------------------------------
constexpr int Bsz = 8;
constexpr int S   = 768;
constexpr int Hd  = 768;
constexpr int NH  = 12;
constexpr int NL  = 5;
constexpr int BS  = Bsz * S;                 // 6144 rows
constexpr long long HH = (long long)Hd * Hd; // 589824

typedef __nv_bfloat16 bf16;

// ---------------------------------------------------------------------------
// Scratch (static device globals)
// ---------------------------------------------------------------------------
__device__ float g_o  [BS * Hd];

__device__ bf16 g_hs_h [BS * Hd], g_hs_l [BS * Hd];
__device__ bf16 g_q_h  [BS * Hd], g_q_l  [BS * Hd];
__device__ bf16 g_k_h  [BS * Hd], g_k_l  [BS * Hd];
__device__ bf16 g_Qh   [BS * Hd], g_Ql   [BS * Hd];
__device__ bf16 g_Kh   [BS * Hd], g_Kl   [BS * Hd];
__device__ bf16 g_Vh   [BS * Hd], g_Vl   [BS * Hd];
__device__ bf16 g_ctx_h[BS * Hd], g_ctx_l[BS * Hd];
__device__ bf16 g_al_h [BS * Hd], g_al_l [BS * Hd];
__device__ bf16 g_al2_h[BS * Hd], g_al2_l[BS * Hd];

__device__ bf16 g_Wq_h [NL * Hd * Hd], g_Wq_l [NL * Hd * Hd];
__device__ bf16 g_Wk_h [NL * Hd * Hd], g_Wk_l [NL * Hd * Hd];
__device__ bf16 g_inw_h[3 * Hd * Hd],  g_inw_l[3 * Hd * Hd];
__device__ bf16 g_ow_h [Hd * Hd],      g_ow_l [Hd * Hd];
__device__ bf16 g_pw_h [Hd * Hd],      g_pw_l [Hd * Hd];

__device__ bf16 g_F_h [NL * 8 * Hd * Hd], g_F_l [NL * 8 * Hd * Hd];
__device__ bf16 g_FT_h[NL * 8 * Hd * Hd], g_FT_l[NL * 8 * Hd * Hd];
__device__ bf16 g_P1_h[NL * 4 * Hd * Hd], g_P1_l[NL * 4 * Hd * Hd];
__device__ bf16 g_QT1_h[NL * 4 * Hd * Hd], g_QT1_l[NL * 4 * Hd * Hd];
__device__ bf16 g_P2_h[NL * 2 * Hd * Hd], g_P2_l[NL * 2 * Hd * Hd];
__device__ bf16 g_QT2_h[NL * 2 * Hd * Hd], g_QT2_l[NL * 2 * Hd * Hd];
__device__ bf16 g_M_h [NL * Hd * Hd],     g_M_l [NL * Hd * Hd];
__device__ bf16 g_MT_h[NL * Hd * Hd],     g_MT_l[NL * Hd * Hd];

__device__ unsigned char g_fF [NL * 8];
__device__ unsigned char g_fP1[NL * 4];
__device__ unsigned char g_fP2[NL * 2];

// ---------------------------------------------------------------------------
// Small PTX helpers
// ---------------------------------------------------------------------------
__device__ __forceinline__ uint32_t smem_u32(const void* p) {
    return (uint32_t)__cvta_generic_to_shared(p);
}
__device__ __forceinline__ void cp16(uint32_t d, const void* s) {
    asm volatile("cp.async.cg.shared.global [%0], [%1], 16;"
                 :: "r"(d), "l"(s) : "memory");
}
__device__ __forceinline__ void cp_commit() {
    asm volatile("cp.async.commit_group;" ::: "memory");
}
template <int N>
__device__ __forceinline__ void cp_wait() {
    asm volatile("cp.async.wait_group %0;" :: "n"(N) : "memory");
}
__device__ __forceinline__ void ldsm4(uint32_t* r, uint32_t addr) {
    asm volatile("ldmatrix.sync.aligned.m8n8.x4.shared.b16 {%0,%1,%2,%3}, [%4];"
                 : "=r"(r[0]), "=r"(r[1]), "=r"(r[2]), "=r"(r[3]) : "r"(addr));
}
__device__ __forceinline__ void mma_bf16(float* d, const uint32_t* a,
                                         uint32_t b0, uint32_t b1) {
    asm volatile(
        "mma.sync.aligned.m16n8k16.row.col.f32.bf16.bf16.f32 "
        "{%0,%1,%2,%3}, {%4,%5,%6,%7}, {%8,%9}, {%0,%1,%2,%3};"
        : "+f"(d[0]), "+f"(d[1]), "+f"(d[2]), "+f"(d[3])
        : "r"(a[0]), "r"(a[1]), "r"(a[2]), "r"(a[3]), "r"(b0), "r"(b1));
}
__device__ __forceinline__ uint32_t pack_bf(bf16 a, bf16 b) {
    return (uint32_t)__bfloat16_as_ushort(a) |
           ((uint32_t)__bfloat16_as_ushort(b) << 16);
}
__device__ __forceinline__ uint32_t pack_f2(float a, float b) {
    return pack_bf(__float2bfloat16(a), __float2bfloat16(b));
}

// ---------------------------------------------------------------------------
// GEMM config: 128x128 tile, BLK_K=32, 8 warps, 2-stage pipeline (best known)
// ---------------------------------------------------------------------------
constexpr int SKP     = 40;
constexpr int TILE_B  = 128 * SKP * 2;       // 10240 B
constexpr int STAGE_B = 4 * TILE_B;          // 40960 B (Ah Al Wh Wl)
constexpr int GEMM_SMEM = 2 * STAGE_B;       // 81920 B

__device__ __forceinline__ void gemm_issue(
    const bf16* __restrict__ base, int lw, uint32_t sdst0, int kc)
{
    const bf16* g0 = base + kc * 32;
#pragma unroll
    for (int i = 0; i < 8; i++) {
        const int chunk = i * 64 + lw;
        const int row = chunk >> 2, cs = chunk & 3;
        cp16(sdst0 + row * (SKP * 2) + cs * 16,
             g0 + (long long)row * Hd + cs * 8);
    }
}

// MODE 0: fp32 out (+bias). MODE 1: bf16 hi/lo out (+bias if non-null).
// MODE 2: bf16 hi/lo out + transposed hi/lo out (no bias).
template <int MODE>
__device__ void gemm_core(
    const bf16* __restrict__ Ah, const bf16* __restrict__ Al,
    const bf16* __restrict__ Wh, const bf16* __restrict__ Wl,
    const float* __restrict__ bias,
    float* __restrict__ C,
    bf16* __restrict__ Ch, bf16* __restrict__ Cl,
    bf16* __restrict__ Th, bf16* __restrict__ Tl,
    int m0, int n0)
{
    extern __shared__ char dsm[];
    const int tid = threadIdx.x;
    const int wid = tid >> 5, lane = tid & 31;
    const int m_off = (wid & 3) * 32;
    const int n_off = (wid >> 2) * 64;
    const uint32_t sbase = smem_u32(dsm);

    const int ltile = tid >> 6;
    const int lw = tid & 63;
    const bf16* gbase =
        (ltile == 0) ? Ah + (long long)m0 * Hd :
        (ltile == 1) ? Al + (long long)m0 * Hd :
        (ltile == 2) ? Wh + (long long)n0 * Hd :
                       Wl + (long long)n0 * Hd;
    const uint32_t sdst_tile = ltile * TILE_B;

    gemm_issue(gbase, lw, sbase + sdst_tile, 0);             cp_commit();
    gemm_issue(gbase, lw, sbase + STAGE_B + sdst_tile, 1);   cp_commit();

    float acc[2][8][4];
#pragma unroll
    for (int mi = 0; mi < 2; mi++)
#pragma unroll
        for (int j = 0; j < 8; j++)
#pragma unroll
            for (int e = 0; e < 4; e++) acc[mi][j][e] = 0.f;

    const int r_off = ((lane >> 3) & 1) * 8 + (lane & 7);
    const int c_off = (lane >> 4) * 8;

    for (int kc = 0; kc < 24; kc++) {
        cp_wait<1>();
        __syncthreads();
        const uint32_t sb = sbase + (kc & 1) * STAGE_B;
        const uint32_t aAh = sb + (m_off + r_off) * (SKP * 2) + c_off * 2;
        const uint32_t aAl = aAh + TILE_B;
        const uint32_t aWh = sb + 2 * TILE_B + (n_off + r_off) * (SKP * 2) + c_off * 2;
        const uint32_t aWl = aWh + TILE_B;

#pragma unroll
        for (int kk = 0; kk < 2; kk++) {
            uint32_t ah[2][4], alr[2][4];
#pragma unroll
            for (int t = 0; t < 2; t++) {
                ldsm4(ah[t],  aAh + t * 16 * (SKP * 2) + kk * 32);
                ldsm4(alr[t], aAl + t * 16 * (SKP * 2) + kk * 32);
            }
#pragma unroll
            for (int u = 0; u < 4; u++) {
                uint32_t bh[4];
                ldsm4(bh, aWh + u * 16 * (SKP * 2) + kk * 32);
#pragma unroll
                for (int mi = 0; mi < 2; mi++) {
                    mma_bf16(acc[mi][2 * u],     ah[mi],  bh[0], bh[2]);
                    mma_bf16(acc[mi][2 * u + 1], ah[mi],  bh[1], bh[3]);
                    mma_bf16(acc[mi][2 * u],     alr[mi], bh[0], bh[2]);
                    mma_bf16(acc[mi][2 * u + 1], alr[mi], bh[1], bh[3]);
                }
                uint32_t bl[4];
                ldsm4(bl, aWl + u * 16 * (SKP * 2) + kk * 32);
#pragma unroll
                for (int mi = 0; mi < 2; mi++) {
                    mma_bf16(acc[mi][2 * u],     ah[mi], bl[0], bl[2]);
                    mma_bf16(acc[mi][2 * u + 1], ah[mi], bl[1], bl[3]);
                }
            }
        }
        __syncthreads();
        if (kc + 2 < 24)
            gemm_issue(gbase, lw, sbase + (kc & 1) * STAGE_B + sdst_tile, kc + 2);
        cp_commit();
    }

    float* sf = (float*)dsm;
    const int g = lane >> 2, t2 = (lane & 3) * 2;
#pragma unroll
    for (int mi = 0; mi < 2; mi++)
#pragma unroll
        for (int j = 0; j < 8; j++) {
            const int r = m_off + mi * 16 + g;
            const int c = n_off + j * 8 + t2;
            sf[r * 132 + c]           = acc[mi][j][0];
            sf[r * 132 + c + 1]       = acc[mi][j][1];
            sf[(r + 8) * 132 + c]     = acc[mi][j][2];
            sf[(r + 8) * 132 + c + 1] = acc[mi][j][3];
        }
    __syncthreads();

    if (MODE == 0) {
#pragma unroll 4
        for (int i = 0; i < 16; i++) {
            const int task = i * 256 + tid;
            const int row = task >> 5, c4 = (task & 31) * 4;
            float4 v = *(float4*)&sf[row * 132 + c4];
            v.x += bias[n0 + c4 + 0];
            v.y += bias[n0 + c4 + 1];
            v.z += bias[n0 + c4 + 2];
            v.w += bias[n0 + c4 + 3];
            *(float4*)(C + (long long)(m0 + row) * Hd + n0 + c4) = v;
        }
    } else {
#pragma unroll 4
        for (int i = 0; i < 16; i++) {
            const int task = i * 256 + tid;
            const int row = task >> 5, c4 = (task & 31) * 4;
            float4 v = *(float4*)&sf[row * 132 + c4];
            if (MODE == 1 && bias) {
                v.x += bias[n0 + c4 + 0];
                v.y += bias[n0 + c4 + 1];
                v.z += bias[n0 + c4 + 2];
                v.w += bias[n0 + c4 + 3];
            }
            bf16 h0 = __float2bfloat16(v.x), h1 = __float2bfloat16(v.y);
            bf16 h2 = __float2bfloat16(v.z), h3 = __float2bfloat16(v.w);
            bf16 l0 = __float2bfloat16(v.x - __bfloat162float(h0));
            bf16 l1 = __float2bfloat16(v.y - __bfloat162float(h1));
            bf16 l2 = __float2bfloat16(v.z - __bfloat162float(h2));
            bf16 l3 = __float2bfloat16(v.w - __bfloat162float(h3));
            const long long off = (long long)(m0 + row) * Hd + n0 + c4;
            *(uint2*)(Ch + off) = make_uint2(pack_bf(h0, h1), pack_bf(h2, h3));
            *(uint2*)(Cl + off) = make_uint2(pack_bf(l0, l1), pack_bf(l2, l3));
        }
        if (MODE == 2) {
            const int c = tid & 127;
            const int half = tid >> 7;
#pragma unroll 4
            for (int i = 0; i < 16; i++) {
                const int r4 = half * 64 + i * 4;
                float v0 = sf[(r4 + 0) * 132 + c];
                float v1 = sf[(r4 + 1) * 132 + c];
                float v2 = sf[(r4 + 2) * 132 + c];
                float v3 = sf[(r4 + 3) * 132 + c];
                bf16 h0 = __float2bfloat16(v0), h1 = __float2bfloat16(v1);
                bf16 h2 = __float2bfloat16(v2), h3 = __float2bfloat16(v3);
                bf16 l0 = __float2bfloat16(v0 - __bfloat162float(h0));
                bf16 l1 = __float2bfloat16(v1 - __bfloat162float(h1));
                bf16 l2 = __float2bfloat16(v2 - __bfloat162float(h2));
                bf16 l3 = __float2bfloat16(v3 - __bfloat162float(h3));
                const long long off = (long long)(n0 + c) * Hd + m0 + r4;
                *(uint2*)(Th + off) = make_uint2(pack_bf(h0, h1), pack_bf(h2, h3));
                *(uint2*)(Tl + off) = make_uint2(pack_bf(l0, l1), pack_bf(l2, l3));
            }
        }
    }
}

// ---------------------------------------------------------------------------
// GEMM wrappers
// ---------------------------------------------------------------------------
template <int MODE, int WSEL>
__global__ __launch_bounds__(256, 2) void tc_gemm(
    const bf16* __restrict__ Ah, const bf16* __restrict__ Al, long long sAz,
    const bf16* __restrict__ Wh, const bf16* __restrict__ Wl,
    const float* __restrict__ bias, const int* __restrict__ lang,
    float* __restrict__ C, bf16* __restrict__ Ch, bf16* __restrict__ Cl,
    long long sCz)
{
    const int z = blockIdx.z;
    const bf16* wh = Wh;
    const bf16* wl = Wl;
    const float* bs = bias;
    if (WSEL) {
        const int lg = __ldg(&lang[z]);
        wh += (long long)lg * HH;
        wl += (long long)lg * HH;
        if (bias) bs += lg * Hd;
    }
    const long long ao = (long long)z * sAz;
    const long long co = (long long)z * sCz;
    gemm_core<MODE>(Ah + ao, Al + ao, wh, wl, bs,
                    (MODE == 0) ? C + co : nullptr,
                    (MODE != 0) ? Ch + co : nullptr,
                    (MODE != 0) ? Cl + co : nullptr,
                    nullptr, nullptr,
                    blockIdx.y * 128, blockIdx.x * 128);
}

// merged q/k lang projection: z = fam*8 + batch
__global__ __launch_bounds__(256, 2) void k_qk2(
    const bf16* __restrict__ hs_h, const bf16* __restrict__ hs_l,
    const bf16* __restrict__ Wq_h, const bf16* __restrict__ Wq_l,
    const bf16* __restrict__ Wk_h, const bf16* __restrict__ Wk_l,
    const float* __restrict__ bq, const float* __restrict__ bk,
    const int* __restrict__ lang,
    bf16* __restrict__ q_h, bf16* __restrict__ q_l,
    bf16* __restrict__ k_h, bf16* __restrict__ k_l)
{
    const int z = blockIdx.z;
    const int fam = z >> 3, b = z & 7;
    const int lg = __ldg(&lang[b]);
    const long long ao = (long long)b * S * Hd;
    const bf16* wh = (fam ? Wk_h : Wq_h) + (long long)lg * HH;
    const bf16* wl = (fam ? Wk_l : Wq_l) + (long long)lg * HH;
    const float* bs = (fam ? bk : bq) + lg * Hd;
    bf16* oh = (fam ? k_h : q_h) + ao;
    bf16* ol = (fam ? k_l : q_l) + ao;
    gemm_core<1>(hs_h + ao, hs_l + ao, wh, wl, bs, nullptr, oh, ol,
                 nullptr, nullptr, blockIdx.y * 128, blockIdx.x * 128);
}

// merged QKV: z = kind*8 + batch; outputs bf16 hi/lo
__global__ __launch_bounds__(256, 2) void k_qkv3(
    const bf16* __restrict__ q_h, const bf16* __restrict__ q_l,
    const bf16* __restrict__ k_h, const bf16* __restrict__ k_l,
    const bf16* __restrict__ hs_h, const bf16* __restrict__ hs_l,
    const bf16* __restrict__ inw_h, const bf16* __restrict__ inw_l,
    const float* __restrict__ in_b,
    bf16* __restrict__ Qh, bf16* __restrict__ Ql,
    bf16* __restrict__ Kh, bf16* __restrict__ Kl,
    bf16* __restrict__ Vh, bf16* __restrict__ Vl)
{
    const int z = blockIdx.z;
    const int kind = z >> 3, b = z & 7;
    const long long ao = (long long)b * S * Hd;
    const bf16 *ah, *al;
    bf16 *oh, *ol;
    if (kind == 0)      { ah = q_h;  al = q_l;  oh = Qh; ol = Ql; }
    else if (kind == 1) { ah = k_h;  al = k_l;  oh = Kh; ol = Kl; }
    else                { ah = hs_h; al = hs_l; oh = Vh; ol = Vl; }
    gemm_core<1>(ah + ao, al + ao,
                 inw_h + (long long)kind * HH, inw_l + (long long)kind * HH,
                 in_b + kind * Hd, nullptr, oh + ao, ol + ao,
                 nullptr, nullptr, blockIdx.y * 128, blockIdx.x * 128);
}

__global__ __launch_bounds__(256, 2) void tc_chain(
    const bf16* __restrict__ sN_h, const bf16* __restrict__ sN_l,
    const bf16* __restrict__ sT_h, const bf16* __restrict__ sT_l,
    const unsigned char* __restrict__ fs,
    bf16* __restrict__ dN_h, bf16* __restrict__ dN_l,
    bf16* __restrict__ dT_h, bf16* __restrict__ dT_l,
    int spa, int dpa)
{
    const int z = blockIdx.z;
    const int a = z / dpa, p = z - a * dpa;
    const int li = a * spa + 2 * p;
    const unsigned char f1 = fs[li], f2 = fs[li + 1];
    const long long zo = (long long)z * HH;
    const int m0 = blockIdx.y * 128, n0 = blockIdx.x * 128;
    const int tid = threadIdx.x;

    if (f1 & f2) {
#pragma unroll 4
        for (int i = 0; i < 16; i++) {
            const int task = i * 256 + tid;
            const int row = task >> 5, c4 = (task & 31) * 4;
            const int gr = m0 + row, gc = n0 + c4;
            bf16 one = __float2bfloat16(1.f), zero = __float2bfloat16(0.f);
            bf16 h0 = (gc + 0 == gr) ? one : zero;
            bf16 h1 = (gc + 1 == gr) ? one : zero;
            bf16 h2 = (gc + 2 == gr) ? one : zero;
            bf16 h3 = (gc + 3 == gr) ? one : zero;
            const long long off = zo + (long long)gr * Hd + gc;
            uint2 hv = make_uint2(pack_bf(h0, h1), pack_bf(h2, h3));
            uint2 lv = make_uint2(0u, 0u);
            *(uint2*)(dN_h + off) = hv; *(uint2*)(dN_l + off) = lv;
            *(uint2*)(dT_h + off) = hv; *(uint2*)(dT_l + off) = lv;
        }
        return;
    }
    if (f1 | f2) {
        const long long so = (long long)(f1 ? li + 1 : li) * HH;
#pragma unroll 4
        for (int i = 0; i < 8; i++) {
            const int idx = i * 256 + tid;
            const int row = idx >> 4, c8 = (idx & 15) * 8;
            const long long doff = zo + (long long)(m0 + row) * Hd + n0 + c8;
            const long long soff = so + (long long)(m0 + row) * Hd + n0 + c8;
            *(uint4*)(dN_h + doff) = *(const uint4*)(sN_h + soff);
            *(uint4*)(dN_l + doff) = *(const uint4*)(sN_l + soff);
            *(uint4*)(dT_h + doff) = *(const uint4*)(sT_h + soff);
            *(uint4*)(dT_l + doff) = *(const uint4*)(sT_l + soff);
        }
        return;
    }
    gemm_core<2>(sN_h + (long long)li * HH, sN_l + (long long)li * HH,
                 sT_h + (long long)(li + 1) * HH, sT_l + (long long)(li + 1) * HH,
                 nullptr, nullptr,
                 dN_h + zo, dN_l + zo, dT_h + zo, dT_l + zo, m0, n0);
}

// ---------------------------------------------------------------------------
// Tensor-core flash attention.
// Block = (qt 64 rows, head, batch). 8 warps: wm = wid&3 (m16), wn = wid>>2
// (kv half, 32 cols). 3-term hi/lo splits for QK^T and PV. Softmax fp32.
// smem tiles: [2 chunks][64 rows][40 bf16 (80B)] like the GEMM.
// ---------------------------------------------------------------------------
constexpr int AT_CHUNK = 64 * 80;            // 5120 B
constexpr int AT_TILE  = 2 * AT_CHUNK;       // 10240 B per array
constexpr int ATT_SMEM = 6 * AT_TILE;        // Qh Ql Kh Kl VTh VTl = 61440 B

__global__ __launch_bounds__(256) void k_attn_tc(
    const bf16* __restrict__ Qg_h, const bf16* __restrict__ Qg_l,
    const bf16* __restrict__ Kg_h, const bf16* __restrict__ Kg_l,
    const bf16* __restrict__ Vg_h, const bf16* __restrict__ Vg_l,
    bf16* __restrict__ Oh, bf16* __restrict__ Ol)
{
    extern __shared__ char dsm[];
    __shared__ float smax[4][2][16];
    __shared__ float larr[2][64];

    const int qt = blockIdx.x, h = blockIdx.y, b = blockIdx.z;
    const int tid = threadIdx.x;
    const int wid = tid >> 5, lane = tid & 31;
    const int wm = wid & 3, wn = wid >> 2;
    const int g = lane >> 2, t2 = (lane & 3) * 2;
    const int r_off = ((lane >> 3) & 1) * 8 + (lane & 7);
    const int c_off = (lane >> 4) * 8;

    const uint32_t sQh = smem_u32(dsm);
    const uint32_t sQl = sQh + AT_TILE;
    const uint32_t sKh = sQh + 2 * AT_TILE;
    const uint32_t sKl = sQh + 3 * AT_TILE;
    const uint32_t sVh = sQh + 4 * AT_TILE;
    const uint32_t sVl = sQh + 5 * AT_TILE;
    unsigned short* vth16 = (unsigned short*)(dsm + 4 * AT_TILE);
    unsigned short* vtl16 = (unsigned short*)(dsm + 5 * AT_TILE);

    const long long qrow0 = (long long)(b * S + qt * 64);
    const int hoff = h * 64;

    // load Q hi/lo (512 cp16 tasks per array)
#pragma unroll
    for (int i = 0; i < 2; i++) {
        const int task = i * 256 + tid;
        const int row = task >> 3, rem = task & 7;
        const int chunk = rem >> 2, sub = rem & 3;
        const uint32_t sd = chunk * AT_CHUNK + row * 80 + sub * 16;
        const long long gsrc = (qrow0 + row) * Hd + hoff + chunk * 32 + sub * 8;
        cp16(sQh + sd, Qg_h + gsrc);
        cp16(sQl + sd, Qg_l + gsrc);
    }
    cp_commit();

    float m0v = -1e30f, m1v = -1e30f, l0v = 0.f, l1v = 0.f;
    float ctx[8][4];
#pragma unroll
    for (int t = 0; t < 8; t++)
#pragma unroll
        for (int e = 0; e < 4; e++) ctx[t][e] = 0.f;

    for (int kt = 0; kt < 12; kt++) {
        __syncthreads();   // prev K/V + smax fully consumed
        const long long krow0 = (long long)(b * S + kt * 64);
        // K hi/lo via cp.async
#pragma unroll
        for (int i = 0; i < 2; i++) {
            const int task = i * 256 + tid;
            const int row = task >> 3, rem = task & 7;
            const int chunk = rem >> 2, sub = rem & 3;
            const uint32_t sd = chunk * AT_CHUNK + row * 80 + sub * 16;
            const long long gsrc = (krow0 + row) * Hd + hoff + chunk * 32 + sub * 8;
            cp16(sKh + sd, Kg_h + gsrc);
            cp16(sKl + sd, Kg_l + gsrc);
        }
        cp_commit();
        // V transposed into smem (scalar)
#pragma unroll
        for (int i = 0; i < 8; i++) {
            const int task = i * 256 + tid;
            const int r = task >> 5;            // kv row
            const int c2 = (task & 31) * 2;     // d col pair
            const long long gsrc = (krow0 + r) * Hd + hoff + c2;
            const uint32_t vh2 = *(const uint32_t*)(Vg_h + gsrc);
            const uint32_t vl2 = *(const uint32_t*)(Vg_l + gsrc);
            const int base = (r >> 5) * 2560 + (r & 31);
            vth16[base + c2 * 40]       = (unsigned short)(vh2 & 0xffff);
            vth16[base + (c2 + 1) * 40] = (unsigned short)(vh2 >> 16);
            vtl16[base + c2 * 40]       = (unsigned short)(vl2 & 0xffff);
            vtl16[base + (c2 + 1) * 40] = (unsigned short)(vl2 >> 16);
        }
        cp_wait<0>();
        __syncthreads();

        // ---- QK^T : scores m16 x n32 ----
        float sacc[4][4];
#pragma unroll
        for (int t = 0; t < 4; t++)
#pragma unroll
            for (int e = 0; e < 4; e++) sacc[t][e] = 0.f;

#pragma unroll
        for (int c = 0; c < 2; c++) {
#pragma unroll
            for (int kk2 = 0; kk2 < 2; kk2++) {
                const uint32_t koff = c * AT_CHUNK + kk2 * 32;
                uint32_t qa_h[4], qa_l[4];
                ldsm4(qa_h, sQh + koff + (wm * 16 + r_off) * 80 + c_off * 2);
                ldsm4(qa_l, sQl + koff + (wm * 16 + r_off) * 80 + c_off * 2);
#pragma unroll
                for (int u = 0; u < 2; u++) {
                    const uint32_t roff2 = koff + (wn * 32 + u * 16 + r_off) * 80 + c_off * 2;
                    uint32_t kb_h[4], kb_l[4];
                    ldsm4(kb_h, sKh + roff2);
                    ldsm4(kb_l, sKl + roff2);
                    mma_bf16(sacc[u * 2],     qa_h, kb_h[0], kb_h[2]);
                    mma_bf16(sacc[u * 2 + 1], qa_h, kb_h[1], kb_h[3]);
                    mma_bf16(sacc[u * 2],     qa_l, kb_h[0], kb_h[2]);
                    mma_bf16(sacc[u * 2 + 1], qa_l, kb_h[1], kb_h[3]);
                    mma_bf16(sacc[u * 2],     qa_h, kb_l[0], kb_l[2]);
                    mma_bf16(sacc[u * 2 + 1], qa_h, kb_l[1], kb_l[3]);
                }
            }
        }
#pragma unroll
        for (int t = 0; t < 4; t++)
#pragma unroll
            for (int e = 0; e < 4; e++) sacc[t][e] *= 0.125f;

        // ---- softmax (fp32) ----
        float rm0 = -1e30f, rm1 = -1e30f;
#pragma unroll
        for (int t = 0; t < 4; t++) {
            rm0 = fmaxf(rm0, fmaxf(sacc[t][0], sacc[t][1]));
            rm1 = fmaxf(rm1, fmaxf(sacc[t][2], sacc[t][3]));
        }
        rm0 = fmaxf(rm0, __shfl_xor_sync(0xffffffffu, rm0, 1));
        rm0 = fmaxf(rm0, __shfl_xor_sync(0xffffffffu, rm0, 2));
        rm1 = fmaxf(rm1, __shfl_xor_sync(0xffffffffu, rm1, 1));
        rm1 = fmaxf(rm1, __shfl_xor_sync(0xffffffffu, rm1, 2));
        if ((lane & 3) == 0) {
            smax[wm][wn][g]     = rm0;
            smax[wm][wn][g + 8] = rm1;
        }
        __syncthreads();
        rm0 = fmaxf(rm0, smax[wm][wn ^ 1][g]);
        rm1 = fmaxf(rm1, smax[wm][wn ^ 1][g + 8]);

        const float mn0 = fmaxf(m0v, rm0);
        const float mn1 = fmaxf(m1v, rm1);
        const float a0 = __expf(m0v - mn0);
        const float a1 = __expf(m1v - mn1);
        m0v = mn0; m1v = mn1;

        float rs0 = 0.f, rs1 = 0.f;
#pragma unroll
        for (int t = 0; t < 4; t++) {
            sacc[t][0] = __expf(sacc[t][0] - mn0);
            sacc[t][1] = __expf(sacc[t][1] - mn0);
            sacc[t][2] = __expf(sacc[t][2] - mn1);
            sacc[t][3] = __expf(sacc[t][3] - mn1);
            rs0 += sacc[t][0] + sacc[t][1];
            rs1 += sacc[t][2] + sacc[t][3];
        }
        rs0 += __shfl_xor_sync(0xffffffffu, rs0, 1);
        rs0 += __shfl_xor_sync(0xffffffffu, rs0, 2);
        rs1 += __shfl_xor_sync(0xffffffffu, rs1, 1);
        rs1 += __shfl_xor_sync(0xffffffffu, rs1, 2);
        l0v = l0v * a0 + rs0;
        l1v = l1v * a1 + rs1;
#pragma unroll
        for (int t = 0; t < 8; t++) {
            ctx[t][0] *= a0; ctx[t][1] *= a0;
            ctx[t][2] *= a1; ctx[t][3] *= a1;
        }

        // ---- pack P hi/lo as A operands ----
        uint32_t pah[2][4], pal[2][4];
#pragma unroll
        for (int kk2 = 0; kk2 < 2; kk2++) {
            const int e = 2 * kk2;
#pragma unroll
            for (int half = 0; half < 2; half++) {
                const int tt = e + half;
                float v0 = sacc[tt][0], v1 = sacc[tt][1];
                float v2 = sacc[tt][2], v3 = sacc[tt][3];
                bf16 h0 = __float2bfloat16(v0), h1 = __float2bfloat16(v1);
                bf16 h2 = __float2bfloat16(v2), h3 = __float2bfloat16(v3);
                pah[kk2][half * 2 + 0] = pack_bf(h0, h1);
                pah[kk2][half * 2 + 1] = pack_bf(h2, h3);
                pal[kk2][half * 2 + 0] =
                    pack_f2(v0 - __bfloat162float(h0), v1 - __bfloat162float(h1));
                pal[kk2][half * 2 + 1] =
                    pack_f2(v2 - __bfloat162float(h2), v3 - __bfloat162float(h3));
            }
        }

        // ---- PV : ctx m16 x n64 over warp's kv half ----
#pragma unroll
        for (int kk2 = 0; kk2 < 2; kk2++) {
            const uint32_t voff = wn * AT_CHUNK + kk2 * 32;
#pragma unroll
            for (int u = 0; u < 4; u++) {
                const uint32_t roff2 = voff + (u * 16 + r_off) * 80 + c_off * 2;
                uint32_t vb_h[4], vb_l[4];
                ldsm4(vb_h, sVh + roff2);
                ldsm4(vb_l, sVl + roff2);
                mma_bf16(ctx[u * 2],     pah[kk2], vb_h[0], vb_h[2]);
                mma_bf16(ctx[u * 2 + 1], pah[kk2], vb_h[1], vb_h[3]);
                mma_bf16(ctx[u * 2],     pal[kk2], vb_h[0], vb_h[2]);
                mma_bf16(ctx[u * 2 + 1], pal[kk2], vb_h[1], vb_h[3]);
                mma_bf16(ctx[u * 2],     pah[kk2], vb_l[0], vb_l[2]);
                mma_bf16(ctx[u * 2 + 1], pah[kk2], vb_l[1], vb_l[3]);
            }
        }
    }

    // ---- merge the two kv-half partials and write out ----
    __syncthreads();
    float* csum = (float*)(dsm + 2 * AT_TILE);   // [64][68], aliases K area
    if (wn == 1) {
#pragma unroll
        for (int t = 0; t < 8; t++) {
            const int u = t >> 1, v = t & 1;
            const int colb = u * 16 + v * 8 + t2;
            csum[(wm * 16 + g) * 68 + colb]         = ctx[t][0];
            csum[(wm * 16 + g) * 68 + colb + 1]     = ctx[t][1];
            csum[(wm * 16 + g + 8) * 68 + colb]     = ctx[t][2];
            csum[(wm * 16 + g + 8) * 68 + colb + 1] = ctx[t][3];
        }
    }
    if ((lane & 3) == 0) {
        larr[wn][wm * 16 + g]     = l0v;
        larr[wn][wm * 16 + g + 8] = l1v;
    }
    __syncthreads();
    if (wn == 0) {
#pragma unroll
        for (int t = 0; t < 8; t++) {
            const int u = t >> 1, v = t & 1;
            const int colb = u * 16 + v * 8 + t2;
            csum[(wm * 16 + g) * 68 + colb]         += ctx[t][0];
            csum[(wm * 16 + g) * 68 + colb + 1]     += ctx[t][1];
            csum[(wm * 16 + g + 8) * 68 + colb]     += ctx[t][2];
            csum[(wm * 16 + g + 8) * 68 + colb + 1] += ctx[t][3];
        }
    }
    __syncthreads();
#pragma unroll
    for (int i = 0; i < 4; i++) {
        const int idx = i * 256 + tid;
        const int row = idx >> 4, c4 = (idx & 15) * 4;
        const float inv = 1.f / (larr[0][row] + larr[1][row]);
        float4 v = *(float4*)&csum[row * 68 + c4];
        v.x *= inv; v.y *= inv; v.z *= inv; v.w *= inv;
        bf16 h0 = __float2bfloat16(v.x), h1 = __float2bfloat16(v.y);
        bf16 h2 = __float2bfloat16(v.z), h3 = __float2bfloat16(v.w);
        bf16 l0 = __float2bfloat16(v.x - __bfloat162float(h0));
        bf16 l1 = __float2bfloat16(v.y - __bfloat162float(h1));
        bf16 l2 = __float2bfloat16(v.z - __bfloat162float(h2));
        bf16 l3 = __float2bfloat16(v.w - __bfloat162float(h3));
        const long long off = (qrow0 + row) * Hd + hoff + c4;
        *(uint2*)(Oh + off) = make_uint2(pack_bf(h0, h1), pack_bf(h2, h3));
        *(uint2*)(Ol + off) = make_uint2(pack_bf(l0, l1), pack_bf(l2, l3));
    }
}

// ---------------------------------------------------------------------------
// conversions / chain leaves / LN (unchanged)
// ---------------------------------------------------------------------------
__global__ __launch_bounds__(256) void k_conv(
    const float* __restrict__ src, bf16* __restrict__ dh,
    bf16* __restrict__ dl)
{
    const long long i4 = ((long long)blockIdx.x * 256 + threadIdx.x) * 4;
    float4 v = *(const float4*)(src + i4);
    bf16 h0 = __float2bfloat16(v.x), h1 = __float2bfloat16(v.y);
    bf16 h2 = __float2bfloat16(v.z), h3 = __float2bfloat16(v.w);
    bf16 l0 = __float2bfloat16(v.x - __bfloat162float(h0));
    bf16 l1 = __float2bfloat16(v.y - __bfloat162float(h1));
    bf16 l2 = __float2bfloat16(v.z - __bfloat162float(h2));
    bf16 l3 = __float2bfloat16(v.w - __bfloat162float(h3));
    *(uint2*)(dh + i4) = make_uint2(pack_bf(h0, h1), pack_bf(h2, h3));
    *(uint2*)(dl + i4) = make_uint2(pack_bf(l0, l1), pack_bf(l2, l3));
}

__global__ void k_flags(const int* __restrict__ lang,
                        unsigned char* fF, unsigned char* fP1, unsigned char* fP2)
{
    if (threadIdx.x == 0 && blockIdx.x == 0) {
        for (int a = 0; a < NL; a++) {
            for (int j = 0; j < 8; j++) fF[a * 8 + j] = (lang[j] == a) ? 1 : 0;
            for (int p = 0; p < 4; p++)
                fP1[a * 4 + p] = fF[a * 8 + 2 * p] & fF[a * 8 + 2 * p + 1];
            for (int p = 0; p < 2; p++)
                fP2[a * 2 + p] = fP1[a * 4 + 2 * p] & fP1[a * 4 + 2 * p + 1];
        }
    }
}

__device__ __forceinline__ void split_store4(
    bf16* dh, bf16* dl, long long off, float x, float y, float z, float w)
{
    bf16 h0 = __float2bfloat16(x), h1 = __float2bfloat16(y);
    bf16 h2 = __float2bfloat16(z), h3 = __float2bfloat16(w);
    bf16 l0 = __float2bfloat16(x - __bfloat162float(h0));
    bf16 l1 = __float2bfloat16(y - __bfloat162float(h1));
    bf16 l2 = __float2bfloat16(z - __bfloat162float(h2));
    bf16 l3 = __float2bfloat16(w - __bfloat162float(h3));
    *(uint2*)(dh + off) = make_uint2(pack_bf(h0, h1), pack_bf(h2, h3));
    *(uint2*)(dl + off) = make_uint2(pack_bf(l0, l1), pack_bf(l2, l3));
}

__global__ __launch_bounds__(256) void k_factors(
    const float* __restrict__ alignT, const int* __restrict__ lang,
    bf16* __restrict__ Fh, bf16* __restrict__ Fl,
    bf16* __restrict__ FTh, bf16* __restrict__ FTl)
{
    const int node = blockIdx.y;
    const int a = node >> 3, j = node & 7;
    const int c = __ldg(&lang[j]);
    const long long nb = (long long)node * HH;
    const long long i4 = ((long long)blockIdx.x * 256 + threadIdx.x) * 4;
    const int r = (int)(i4 / Hd), col = (int)(i4 % Hd);

    if (c == a) {
        float v0 = (col + 0 == r) ? 1.f : 0.f;
        float v1 = (col + 1 == r) ? 1.f : 0.f;
        float v2 = (col + 2 == r) ? 1.f : 0.f;
        float v3 = (col + 3 == r) ? 1.f : 0.f;
        split_store4(Fh,  Fl,  nb + i4, v0, v1, v2, v3);
        split_store4(FTh, FTl, nb + i4, v0, v1, v2, v3);
    } else {
        const float* sm = alignT + (long long)(a * NL + c) * HH;
        float4 v = *(const float4*)(sm + i4);
        split_store4(Fh, Fl, nb + i4, v.x, v.y, v.z, v.w);
        float t0 = sm[(long long)(col + 0) * Hd + r];
        float t1 = sm[(long long)(col + 1) * Hd + r];
        float t2 = sm[(long long)(col + 2) * Hd + r];
        float t3 = sm[(long long)(col + 3) * Hd + r];
        split_store4(FTh, FTl, nb + i4, t0, t1, t2, t3);
    }
}

__global__ __launch_bounds__(256) void k_ln(
    const float* __restrict__ X, const float* __restrict__ Rres,
    const float* __restrict__ gam, const float* __restrict__ bet,
    float* __restrict__ out)
{
    const int row = blockIdx.x;
    const long long base = (long long)row * Hd;
    const int tid = threadIdx.x;

    float v[3];
    float s = 0.f, s2 = 0.f;
#pragma unroll
    for (int u = 0; u < 3; u++) {
        const int idx = tid + u * 256;
        const float val = X[base + idx] + Rres[base + idx];
        v[u] = val; s += val; s2 += val * val;
    }
#pragma unroll
    for (int off = 16; off >= 1; off >>= 1) {
        s  += __shfl_xor_sync(0xffffffffu, s, off);
        s2 += __shfl_xor_sync(0xffffffffu, s2, off);
    }
    __shared__ float ss[8], ss2[8], mv[2];
    const int wid = tid >> 5, lane = tid & 31;
    if (lane == 0) { ss[wid] = s; ss2[wid] = s2; }
    __syncthreads();
    if (tid == 0) {
        float S_ = 0.f, S2_ = 0.f;
        for (int w = 0; w < 8; w++) { S_ += ss[w]; S2_ += ss2[w]; }
        const float mean = S_ * (1.f / 768.f);
        const float var  = S2_ * (1.f / 768.f) - mean * mean;
        mv[0] = mean;
        mv[1] = rsqrtf(var + 1e-5f);
    }
    __syncthreads();
    const float mean = mv[0], rstd = mv[1];
#pragma unroll
    for (int u = 0; u < 3; u++) {
        const int idx = tid + u * 256;
        out[base + idx] = (v[u] - mean) * rstd * gam[idx] + bet[idx];
    }
}

// ---------------------------------------------------------------------------
// kernel_launch
// ---------------------------------------------------------------------------
#define SYM(v, s) cudaGetSymbolAddress((void**)&v, s)

extern "C" void kernel_launch(void* const* d_in, const int* in_sizes, int n_in,
                              void* d_out, int out_size)
{
    const float* hs      = (const float*)d_in[0];
    const int*   lang    = (const int*)  d_in[1];
    const float* Wq_lang = (const float*)d_in[3];
    const float* bq_lang = (const float*)d_in[4];
    const float* Wk_lang = (const float*)d_in[5];
    const float* bk_lang = (const float*)d_in[6];
    const float* in_w    = (const float*)d_in[7];
    const float* in_b    = (const float*)d_in[8];
    const float* out_w   = (const float*)d_in[9];
    const float* out_b   = (const float*)d_in[10];
    const float* alignT  = (const float*)d_in[11];
    const float* proj_w  = (const float*)d_in[12];
    const float* proj_b  = (const float*)d_in[13];
    const float* ln_g    = (const float*)d_in[14];
    const float* ln_b    = (const float*)d_in[15];
    float* out = (float*)d_out;

    float* obuf;
    SYM(obuf, g_o);

    bf16 *hs_h, *hs_l, *q_h, *q_l, *k_h, *k_l;
    bf16 *Qh, *Ql, *Kh, *Kl, *Vh, *Vl, *ctx_h, *ctx_l;
    bf16 *al_h, *al_l, *al2_h, *al2_l;
    SYM(hs_h, g_hs_h);   SYM(hs_l, g_hs_l);
    SYM(q_h, g_q_h);     SYM(q_l, g_q_l);
    SYM(k_h, g_k_h);     SYM(k_l, g_k_l);
    SYM(Qh, g_Qh);       SYM(Ql, g_Ql);
    SYM(Kh, g_Kh);       SYM(Kl, g_Kl);
    SYM(Vh, g_Vh);       SYM(Vl, g_Vl);
    SYM(ctx_h, g_ctx_h); SYM(ctx_l, g_ctx_l);
    SYM(al_h, g_al_h);   SYM(al_l, g_al_l);
    SYM(al2_h, g_al2_h); SYM(al2_l, g_al2_l);

    bf16 *Wq_h, *Wq_l, *Wk_h, *Wk_l, *inw_h, *inw_l, *ow_h, *ow_l, *pw_h, *pw_l;
    SYM(Wq_h, g_Wq_h);   SYM(Wq_l, g_Wq_l);
    SYM(Wk_h, g_Wk_h);   SYM(Wk_l, g_Wk_l);
    SYM(inw_h, g_inw_h); SYM(inw_l, g_inw_l);
    SYM(ow_h, g_ow_h);   SYM(ow_l, g_ow_l);
    SYM(pw_h, g_pw_h);   SYM(pw_l, g_pw_l);

    bf16 *F_h, *F_l, *FT_h, *FT_l, *P1_h, *P1_l, *QT1_h, *QT1_l;
    bf16 *P2_h, *P2_l, *QT2_h, *QT2_l, *M_h, *M_l, *MT_h, *MT_l;
    SYM(F_h, g_F_h);   SYM(F_l, g_F_l);   SYM(FT_h, g_FT_h); SYM(FT_l, g_FT_l);
    SYM(P1_h, g_P1_h); SYM(P1_l, g_P1_l); SYM(QT1_h, g_QT1_h); SYM(QT1_l, g_QT1_l);
    SYM(P2_h, g_P2_h); SYM(P2_l, g_P2_l); SYM(QT2_h, g_QT2_h); SYM(QT2_l, g_QT2_l);
    SYM(M_h, g_M_h);   SYM(M_l, g_M_l);   SYM(MT_h, g_MT_h); SYM(MT_l, g_MT_l);

    unsigned char *fF, *fP1, *fP2;
    SYM(fF, g_fF); SYM(fP1, g_fP1); SYM(fP2, g_fP2);

    cudaFuncSetAttribute(tc_gemm<0, 0>, cudaFuncAttributeMaxDynamicSharedMemorySize, GEMM_SMEM);
    cudaFuncSetAttribute(tc_gemm<1, 0>, cudaFuncAttributeMaxDynamicSharedMemorySize, GEMM_SMEM);
    cudaFuncSetAttribute(tc_gemm<1, 1>, cudaFuncAttributeMaxDynamicSharedMemorySize, GEMM_SMEM);
    cudaFuncSetAttribute(tc_chain,      cudaFuncAttributeMaxDynamicSharedMemorySize, GEMM_SMEM);
    cudaFuncSetAttribute(k_qk2,         cudaFuncAttributeMaxDynamicSharedMemorySize, GEMM_SMEM);
    cudaFuncSetAttribute(k_qkv3,        cudaFuncAttributeMaxDynamicSharedMemorySize, GEMM_SMEM);
    cudaFuncSetAttribute(k_attn_tc,     cudaFuncAttributeMaxDynamicSharedMemorySize, ATT_SMEM);

    const long long sBH = (long long)S * Hd;
    const dim3 thr(256);

    // conversions
    k_conv<<<BS * Hd / 1024, thr>>>(hs, hs_h, hs_l);
    k_conv<<<(int)(NL * HH / 1024), thr>>>(Wq_lang, Wq_h, Wq_l);
    k_conv<<<(int)(NL * HH / 1024), thr>>>(Wk_lang, Wk_h, Wk_l);
    k_conv<<<(int)(3 * HH / 1024), thr>>>(in_w, inw_h, inw_l);
    k_conv<<<(int)(HH / 1024), thr>>>(out_w, ow_h, ow_l);
    k_conv<<<(int)(HH / 1024), thr>>>(proj_w, pw_h, pw_l);

    // chain flags + leaves
    k_flags<<<1, 32>>>(lang, fF, fP1, fP2);
    k_factors<<<dim3((int)(HH / 1024), NL * 8), thr>>>(alignT, lang, F_h, F_l, FT_h, FT_l);

    // merged per-language q/k projections
    k_qk2<<<dim3(6, 6, 16), thr, GEMM_SMEM>>>(
        hs_h, hs_l, Wq_h, Wq_l, Wk_h, Wk_l, bq_lang, bk_lang, lang,
        q_h, q_l, k_h, k_l);

    // merged QKV (bf16 hi/lo out)
    k_qkv3<<<dim3(6, 6, 24), thr, GEMM_SMEM>>>(
        q_h, q_l, k_h, k_l, hs_h, hs_l, inw_h, inw_l, in_b,
        Qh, Ql, Kh, Kl, Vh, Vl);

    // chain levels (independent of attention inputs; before alignM)
    tc_chain<<<dim3(6, 6, NL * 4), thr, GEMM_SMEM>>>(F_h, F_l, FT_h, FT_l, fF,
                                                     P1_h, P1_l, QT1_h, QT1_l, 8, 4);
    tc_chain<<<dim3(6, 6, NL * 2), thr, GEMM_SMEM>>>(P1_h, P1_l, QT1_h, QT1_l, fP1,
                                                     P2_h, P2_l, QT2_h, QT2_l, 4, 2);
    tc_chain<<<dim3(6, 6, NL), thr, GEMM_SMEM>>>(P2_h, P2_l, QT2_h, QT2_l, fP2,
                                                 M_h, M_l, MT_h, MT_l, 2, 1);

    // tensor-core attention (ctx in bf16 hi/lo)
    k_attn_tc<<<dim3(S / 64, NH, Bsz), thr, ATT_SMEM>>>(
        Qh, Ql, Kh, Kl, Vh, Vl, ctx_h, ctx_l);

    // out_proj (bf16 out)
    tc_gemm<1, 0><<<dim3(6, 48, 1), thr, GEMM_SMEM>>>(
        ctx_h, ctx_l, 0, ow_h, ow_l, out_b, nullptr, nullptr, al_h, al_l, 0);

    // aligned @ M[lang[b]]
    tc_gemm<1, 1><<<dim3(6, 6, Bsz), thr, GEMM_SMEM>>>(
        al_h, al_l, sBH, MT_h, MT_l, nullptr, lang, nullptr, al2_h, al2_l, sBH);

    // final proj (fp32 out)
    tc_gemm<0, 0><<<dim3(6, 48, 1), thr, GEMM_SMEM>>>(
        al2_h, al2_l, 0, pw_h, pw_l, proj_b, nullptr, obuf, nullptr, nullptr, 0);

    // residual + LayerNorm
    k_ln<<<BS, thr>>>(obuf, hs, ln_g, ln_b, out);
}

// round 9
// speedup vs baseline: 2.3277x; 1.2101x over previous
#include <cuda_runtime.h>
#include <cuda_bf16.h>
#include <cstdint>

// ---------------------------------------------------------------------------
// Problem constants
// ---------------------------------------------------------------------------
constexpr int Bsz = 8;
constexpr int S   = 768;
constexpr int Hd  = 768;
constexpr int NH  = 12;
constexpr int NL  = 5;
constexpr int BS  = Bsz * S;
constexpr long long HH = (long long)Hd * Hd;

typedef __nv_bfloat16 bf16;

// ---------------------------------------------------------------------------
// Scratch
// ---------------------------------------------------------------------------
__device__ float g_o  [BS * Hd];

__device__ bf16 g_hs_h [BS * Hd], g_hs_l [BS * Hd];
__device__ bf16 g_q_h  [BS * Hd], g_q_l  [BS * Hd];
__device__ bf16 g_k_h  [BS * Hd], g_k_l  [BS * Hd];
__device__ bf16 g_Qh   [BS * Hd], g_Ql   [BS * Hd];
__device__ bf16 g_Kh   [BS * Hd], g_Kl   [BS * Hd];
__device__ bf16 g_Vh   [BS * Hd], g_Vl   [BS * Hd];
__device__ bf16 g_ctx_h[BS * Hd], g_ctx_l[BS * Hd];
__device__ bf16 g_al_h [BS * Hd], g_al_l [BS * Hd];
__device__ bf16 g_al2_h[BS * Hd], g_al2_l[BS * Hd];

__device__ bf16 g_Wq_h [NL * Hd * Hd], g_Wq_l [NL * Hd * Hd];
__device__ bf16 g_Wk_h [NL * Hd * Hd], g_Wk_l [NL * Hd * Hd];
__device__ bf16 g_inw_h[3 * Hd * Hd],  g_inw_l[3 * Hd * Hd];
__device__ bf16 g_ow_h [Hd * Hd],      g_ow_l [Hd * Hd];
__device__ bf16 g_pw_h [Hd * Hd],      g_pw_l [Hd * Hd];

__device__ bf16 g_F_h [NL * 8 * Hd * Hd], g_F_l [NL * 8 * Hd * Hd];
__device__ bf16 g_FT_h[NL * 8 * Hd * Hd], g_FT_l[NL * 8 * Hd * Hd];
__device__ bf16 g_P1_h[NL * 4 * Hd * Hd], g_P1_l[NL * 4 * Hd * Hd];
__device__ bf16 g_QT1_h[NL * 4 * Hd * Hd], g_QT1_l[NL * 4 * Hd * Hd];
__device__ bf16 g_P2_h[NL * 2 * Hd * Hd], g_P2_l[NL * 2 * Hd * Hd];
__device__ bf16 g_QT2_h[NL * 2 * Hd * Hd], g_QT2_l[NL * 2 * Hd * Hd];
__device__ bf16 g_M_h [NL * Hd * Hd],     g_M_l [NL * Hd * Hd];
__device__ bf16 g_MT_h[NL * Hd * Hd],     g_MT_l[NL * Hd * Hd];

__device__ unsigned char g_fF [NL * 8];
__device__ unsigned char g_fP1[NL * 4];
__device__ unsigned char g_fP2[NL * 2];

// ---------------------------------------------------------------------------
// PTX helpers
// ---------------------------------------------------------------------------
__device__ __forceinline__ uint32_t smem_u32(const void* p) {
    return (uint32_t)__cvta_generic_to_shared(p);
}
__device__ __forceinline__ void cp16(uint32_t d, const void* s) {
    asm volatile("cp.async.cg.shared.global [%0], [%1], 16;"
                 :: "r"(d), "l"(s) : "memory");
}
__device__ __forceinline__ void cp_commit() {
    asm volatile("cp.async.commit_group;" ::: "memory");
}
template <int N>
__device__ __forceinline__ void cp_wait() {
    asm volatile("cp.async.wait_group %0;" :: "n"(N) : "memory");
}
__device__ __forceinline__ void ldsm4(uint32_t* r, uint32_t addr) {
    asm volatile("ldmatrix.sync.aligned.m8n8.x4.shared.b16 {%0,%1,%2,%3}, [%4];"
                 : "=r"(r[0]), "=r"(r[1]), "=r"(r[2]), "=r"(r[3]) : "r"(addr));
}
__device__ __forceinline__ void mma_bf16(float* d, const uint32_t* a,
                                         uint32_t b0, uint32_t b1) {
    asm volatile(
        "mma.sync.aligned.m16n8k16.row.col.f32.bf16.bf16.f32 "
        "{%0,%1,%2,%3}, {%4,%5,%6,%7}, {%8,%9}, {%0,%1,%2,%3};"
        : "+f"(d[0]), "+f"(d[1]), "+f"(d[2]), "+f"(d[3])
        : "r"(a[0]), "r"(a[1]), "r"(a[2]), "r"(a[3]), "r"(b0), "r"(b1));
}
__device__ __forceinline__ uint32_t pack_bf(bf16 a, bf16 b) {
    return (uint32_t)__bfloat16_as_ushort(a) |
           ((uint32_t)__bfloat16_as_ushort(b) << 16);
}
__device__ __forceinline__ uint32_t pack_f2(float a, float b) {
    return pack_bf(__float2bfloat16(a), __float2bfloat16(b));
}

// ---------------------------------------------------------------------------
// GEMM: 128x128 tile, BLK_K=32, 8 warps, 2-stage pipeline.
// LOWP=1: hi*hi only (1 MMA pass); skips lo-tile loads.
// ---------------------------------------------------------------------------
constexpr int SKP     = 40;
constexpr int TILE_B  = 128 * SKP * 2;
constexpr int STAGE_B = 4 * TILE_B;
constexpr int GEMM_SMEM = 2 * STAGE_B;       // 81920 B

__device__ __forceinline__ void gemm_issue(
    const bf16* __restrict__ base, int lw, uint32_t sdst0, int kc)
{
    const bf16* g0 = base + kc * 32;
#pragma unroll
    for (int i = 0; i < 8; i++) {
        const int chunk = i * 64 + lw;
        const int row = chunk >> 2, cs = chunk & 3;
        cp16(sdst0 + row * (SKP * 2) + cs * 16,
             g0 + (long long)row * Hd + cs * 8);
    }
}

// MODE 0: fp32 out (+bias). MODE 1: bf16 hi/lo out (+bias if non-null).
// MODE 2: bf16 hi/lo out + transposed hi/lo out (no bias).
template <int MODE, int LOWP>
__device__ void gemm_core(
    const bf16* __restrict__ Ah, const bf16* __restrict__ Al,
    const bf16* __restrict__ Wh, const bf16* __restrict__ Wl,
    const float* __restrict__ bias,
    float* __restrict__ C,
    bf16* __restrict__ Ch, bf16* __restrict__ Cl,
    bf16* __restrict__ Th, bf16* __restrict__ Tl,
    int m0, int n0)
{
    extern __shared__ char dsm[];
    const int tid = threadIdx.x;
    const int wid = tid >> 5, lane = tid & 31;
    const int m_off = (wid & 3) * 32;
    const int n_off = (wid >> 2) * 64;
    const uint32_t sbase = smem_u32(dsm);

    const int ltile = tid >> 6;
    const int lw = tid & 63;
    const bf16* gbase =
        (ltile == 0) ? Ah + (long long)m0 * Hd :
        (ltile == 1) ? Al + (long long)m0 * Hd :
        (ltile == 2) ? Wh + (long long)n0 * Hd :
                       Wl + (long long)n0 * Hd;
    const uint32_t sdst_tile = ltile * TILE_B;
    const bool do_issue = (!LOWP) || ((ltile & 1) == 0);

    if (do_issue) gemm_issue(gbase, lw, sbase + sdst_tile, 0);
    cp_commit();
    if (do_issue) gemm_issue(gbase, lw, sbase + STAGE_B + sdst_tile, 1);
    cp_commit();

    float acc[2][8][4];
#pragma unroll
    for (int mi = 0; mi < 2; mi++)
#pragma unroll
        for (int j = 0; j < 8; j++)
#pragma unroll
            for (int e = 0; e < 4; e++) acc[mi][j][e] = 0.f;

    const int r_off = ((lane >> 3) & 1) * 8 + (lane & 7);
    const int c_off = (lane >> 4) * 8;

    for (int kc = 0; kc < 24; kc++) {
        cp_wait<1>();
        __syncthreads();
        const uint32_t sb = sbase + (kc & 1) * STAGE_B;
        const uint32_t aAh = sb + (m_off + r_off) * (SKP * 2) + c_off * 2;
        const uint32_t aAl = aAh + TILE_B;
        const uint32_t aWh = sb + 2 * TILE_B + (n_off + r_off) * (SKP * 2) + c_off * 2;
        const uint32_t aWl = aWh + TILE_B;

#pragma unroll
        for (int kk = 0; kk < 2; kk++) {
            uint32_t ah[2][4], alr[2][4];
#pragma unroll
            for (int t = 0; t < 2; t++) {
                ldsm4(ah[t], aAh + t * 16 * (SKP * 2) + kk * 32);
                if (!LOWP)
                    ldsm4(alr[t], aAl + t * 16 * (SKP * 2) + kk * 32);
            }
#pragma unroll
            for (int u = 0; u < 4; u++) {
                uint32_t bh[4];
                ldsm4(bh, aWh + u * 16 * (SKP * 2) + kk * 32);
#pragma unroll
                for (int mi = 0; mi < 2; mi++) {
                    mma_bf16(acc[mi][2 * u],     ah[mi], bh[0], bh[2]);
                    mma_bf16(acc[mi][2 * u + 1], ah[mi], bh[1], bh[3]);
                    if (!LOWP) {
                        mma_bf16(acc[mi][2 * u],     alr[mi], bh[0], bh[2]);
                        mma_bf16(acc[mi][2 * u + 1], alr[mi], bh[1], bh[3]);
                    }
                }
                if (!LOWP) {
                    uint32_t bl[4];
                    ldsm4(bl, aWl + u * 16 * (SKP * 2) + kk * 32);
#pragma unroll
                    for (int mi = 0; mi < 2; mi++) {
                        mma_bf16(acc[mi][2 * u],     ah[mi], bl[0], bl[2]);
                        mma_bf16(acc[mi][2 * u + 1], ah[mi], bl[1], bl[3]);
                    }
                }
            }
        }
        __syncthreads();
        if (kc + 2 < 24 && do_issue)
            gemm_issue(gbase, lw, sbase + (kc & 1) * STAGE_B + sdst_tile, kc + 2);
        cp_commit();
    }

    float* sf = (float*)dsm;
    const int g = lane >> 2, t2 = (lane & 3) * 2;
#pragma unroll
    for (int mi = 0; mi < 2; mi++)
#pragma unroll
        for (int j = 0; j < 8; j++) {
            const int r = m_off + mi * 16 + g;
            const int c = n_off + j * 8 + t2;
            sf[r * 132 + c]           = acc[mi][j][0];
            sf[r * 132 + c + 1]       = acc[mi][j][1];
            sf[(r + 8) * 132 + c]     = acc[mi][j][2];
            sf[(r + 8) * 132 + c + 1] = acc[mi][j][3];
        }
    __syncthreads();

    if (MODE == 0) {
#pragma unroll 4
        for (int i = 0; i < 16; i++) {
            const int task = i * 256 + tid;
            const int row = task >> 5, c4 = (task & 31) * 4;
            float4 v = *(float4*)&sf[row * 132 + c4];
            v.x += bias[n0 + c4 + 0];
            v.y += bias[n0 + c4 + 1];
            v.z += bias[n0 + c4 + 2];
            v.w += bias[n0 + c4 + 3];
            *(float4*)(C + (long long)(m0 + row) * Hd + n0 + c4) = v;
        }
    } else {
#pragma unroll 4
        for (int i = 0; i < 16; i++) {
            const int task = i * 256 + tid;
            const int row = task >> 5, c4 = (task & 31) * 4;
            float4 v = *(float4*)&sf[row * 132 + c4];
            if (MODE == 1 && bias) {
                v.x += bias[n0 + c4 + 0];
                v.y += bias[n0 + c4 + 1];
                v.z += bias[n0 + c4 + 2];
                v.w += bias[n0 + c4 + 3];
            }
            bf16 h0 = __float2bfloat16(v.x), h1 = __float2bfloat16(v.y);
            bf16 h2 = __float2bfloat16(v.z), h3 = __float2bfloat16(v.w);
            bf16 l0 = __float2bfloat16(v.x - __bfloat162float(h0));
            bf16 l1 = __float2bfloat16(v.y - __bfloat162float(h1));
            bf16 l2 = __float2bfloat16(v.z - __bfloat162float(h2));
            bf16 l3 = __float2bfloat16(v.w - __bfloat162float(h3));
            const long long off = (long long)(m0 + row) * Hd + n0 + c4;
            *(uint2*)(Ch + off) = make_uint2(pack_bf(h0, h1), pack_bf(h2, h3));
            *(uint2*)(Cl + off) = make_uint2(pack_bf(l0, l1), pack_bf(l2, l3));
        }
        if (MODE == 2) {
            const int c = tid & 127;
            const int half = tid >> 7;
#pragma unroll 4
            for (int i = 0; i < 16; i++) {
                const int r4 = half * 64 + i * 4;
                float v0 = sf[(r4 + 0) * 132 + c];
                float v1 = sf[(r4 + 1) * 132 + c];
                float v2 = sf[(r4 + 2) * 132 + c];
                float v3 = sf[(r4 + 3) * 132 + c];
                bf16 h0 = __float2bfloat16(v0), h1 = __float2bfloat16(v1);
                bf16 h2 = __float2bfloat16(v2), h3 = __float2bfloat16(v3);
                bf16 l0 = __float2bfloat16(v0 - __bfloat162float(h0));
                bf16 l1 = __float2bfloat16(v1 - __bfloat162float(h1));
                bf16 l2 = __float2bfloat16(v2 - __bfloat162float(h2));
                bf16 l3 = __float2bfloat16(v3 - __bfloat162float(h3));
                const long long off = (long long)(n0 + c) * Hd + m0 + r4;
                *(uint2*)(Th + off) = make_uint2(pack_bf(h0, h1), pack_bf(h2, h3));
                *(uint2*)(Tl + off) = make_uint2(pack_bf(l0, l1), pack_bf(l2, l3));
            }
        }
    }
}

// ---------------------------------------------------------------------------
// Chain product block (zz = product index within level), LOWP gemm.
// ---------------------------------------------------------------------------
__device__ void chain_work(
    int zz,
    const bf16* __restrict__ sN_h, const bf16* __restrict__ sN_l,
    const bf16* __restrict__ sT_h, const bf16* __restrict__ sT_l,
    const unsigned char* __restrict__ fs,
    bf16* __restrict__ dN_h, bf16* __restrict__ dN_l,
    bf16* __restrict__ dT_h, bf16* __restrict__ dT_l,
    int spa, int dpa)
{
    const int a = zz / dpa, p = zz - a * dpa;
    const int li = a * spa + 2 * p;
    const unsigned char f1 = fs[li], f2 = fs[li + 1];
    const long long zo = (long long)zz * HH;
    const int m0 = blockIdx.y * 128, n0 = blockIdx.x * 128;
    const int tid = threadIdx.x;

    if (f1 & f2) {
#pragma unroll 4
        for (int i = 0; i < 16; i++) {
            const int task = i * 256 + tid;
            const int row = task >> 5, c4 = (task & 31) * 4;
            const int gr = m0 + row, gc = n0 + c4;
            bf16 one = __float2bfloat16(1.f), zero = __float2bfloat16(0.f);
            bf16 h0 = (gc + 0 == gr) ? one : zero;
            bf16 h1 = (gc + 1 == gr) ? one : zero;
            bf16 h2 = (gc + 2 == gr) ? one : zero;
            bf16 h3 = (gc + 3 == gr) ? one : zero;
            const long long off = zo + (long long)gr * Hd + gc;
            uint2 hv = make_uint2(pack_bf(h0, h1), pack_bf(h2, h3));
            uint2 lv = make_uint2(0u, 0u);
            *(uint2*)(dN_h + off) = hv; *(uint2*)(dN_l + off) = lv;
            *(uint2*)(dT_h + off) = hv; *(uint2*)(dT_l + off) = lv;
        }
        return;
    }
    if (f1 | f2) {
        const long long so = (long long)(f1 ? li + 1 : li) * HH;
#pragma unroll 4
        for (int i = 0; i < 8; i++) {
            const int idx = i * 256 + tid;
            const int row = idx >> 4, c8 = (idx & 15) * 8;
            const long long doff = zo + (long long)(m0 + row) * Hd + n0 + c8;
            const long long soff = so + (long long)(m0 + row) * Hd + n0 + c8;
            *(uint4*)(dN_h + doff) = *(const uint4*)(sN_h + soff);
            *(uint4*)(dN_l + doff) = *(const uint4*)(sN_l + soff);
            *(uint4*)(dT_h + doff) = *(const uint4*)(sT_h + soff);
            *(uint4*)(dT_l + doff) = *(const uint4*)(sT_l + soff);
        }
        return;
    }
    gemm_core<2, 1>(sN_h + (long long)li * HH, nullptr,
                    sT_h + (long long)(li + 1) * HH, nullptr,
                    nullptr, nullptr,
                    dN_h + zo, dN_l + zo, dT_h + zo, dT_l + zo, m0, n0);
}

// ---------------------------------------------------------------------------
// Merged launches
// ---------------------------------------------------------------------------
// L1: z<16 -> q/k lang projection (fam=z>>3, batch=z&7); z>=16 -> chain level1
__global__ __launch_bounds__(256, 2) void k_l1(
    const bf16* __restrict__ hs_h, const bf16* __restrict__ hs_l,
    const bf16* __restrict__ Wq_h, const bf16* __restrict__ Wq_l,
    const bf16* __restrict__ Wk_h, const bf16* __restrict__ Wk_l,
    const float* __restrict__ bq, const float* __restrict__ bk,
    const int* __restrict__ lang,
    bf16* __restrict__ q_h, bf16* __restrict__ q_l,
    bf16* __restrict__ k_h, bf16* __restrict__ k_l,
    const bf16* __restrict__ F_h, const bf16* __restrict__ F_l,
    const bf16* __restrict__ FT_h, const bf16* __restrict__ FT_l,
    const unsigned char* __restrict__ fF,
    bf16* __restrict__ P1_h, bf16* __restrict__ P1_l,
    bf16* __restrict__ QT1_h, bf16* __restrict__ QT1_l)
{
    const int z = blockIdx.z;
    if (z < 16) {
        const int fam = z >> 3, b = z & 7;
        const int lg = __ldg(&lang[b]);
        const long long ao = (long long)b * S * Hd;
        const bf16* wh = (fam ? Wk_h : Wq_h) + (long long)lg * HH;
        const bf16* wl = (fam ? Wk_l : Wq_l) + (long long)lg * HH;
        const float* bs = (fam ? bk : bq) + lg * Hd;
        bf16* oh = (fam ? k_h : q_h) + ao;
        bf16* ol = (fam ? k_l : q_l) + ao;
        gemm_core<1, 0>(hs_h + ao, hs_l + ao, wh, wl, bs, nullptr, oh, ol,
                        nullptr, nullptr, blockIdx.y * 128, blockIdx.x * 128);
    } else {
        chain_work(z - 16, F_h, F_l, FT_h, FT_l, fF,
                   P1_h, P1_l, QT1_h, QT1_l, 8, 4);
    }
}

// L2: z<24 -> QKV (kind=z>>3, batch=z&7); z>=24 -> chain level2
__global__ __launch_bounds__(256, 2) void k_l2(
    const bf16* __restrict__ q_h, const bf16* __restrict__ q_l,
    const bf16* __restrict__ k_h, const bf16* __restrict__ k_l,
    const bf16* __restrict__ hs_h, const bf16* __restrict__ hs_l,
    const bf16* __restrict__ inw_h, const bf16* __restrict__ inw_l,
    const float* __restrict__ in_b,
    bf16* __restrict__ Qh, bf16* __restrict__ Ql,
    bf16* __restrict__ Kh, bf16* __restrict__ Kl,
    bf16* __restrict__ Vh, bf16* __restrict__ Vl,
    const bf16* __restrict__ P1_h, const bf16* __restrict__ P1_l,
    const bf16* __restrict__ QT1_h, const bf16* __restrict__ QT1_l,
    const unsigned char* __restrict__ fP1,
    bf16* __restrict__ P2_h, bf16* __restrict__ P2_l,
    bf16* __restrict__ QT2_h, bf16* __restrict__ QT2_l)
{
    const int z = blockIdx.z;
    if (z < 24) {
        const int kind = z >> 3, b = z & 7;
        const long long ao = (long long)b * S * Hd;
        const bf16 *ah, *al;
        bf16 *oh, *ol;
        if (kind == 0)      { ah = q_h;  al = q_l;  oh = Qh; ol = Ql; }
        else if (kind == 1) { ah = k_h;  al = k_l;  oh = Kh; ol = Kl; }
        else                { ah = hs_h; al = hs_l; oh = Vh; ol = Vl; }
        gemm_core<1, 0>(ah + ao, al + ao,
                        inw_h + (long long)kind * HH, inw_l + (long long)kind * HH,
                        in_b + kind * Hd, nullptr, oh + ao, ol + ao,
                        nullptr, nullptr, blockIdx.y * 128, blockIdx.x * 128);
    } else {
        chain_work(z - 24, P1_h, P1_l, QT1_h, QT1_l, fP1,
                   P2_h, P2_l, QT2_h, QT2_l, 4, 2);
    }
}

// L3: z<8 -> out_proj batch z; z>=8 -> chain level3
__global__ __launch_bounds__(256, 2) void k_l3(
    const bf16* __restrict__ ctx_h, const bf16* __restrict__ ctx_l,
    const bf16* __restrict__ ow_h, const bf16* __restrict__ ow_l,
    const float* __restrict__ out_b,
    bf16* __restrict__ al_h, bf16* __restrict__ al_l,
    const bf16* __restrict__ P2_h, const bf16* __restrict__ P2_l,
    const bf16* __restrict__ QT2_h, const bf16* __restrict__ QT2_l,
    const unsigned char* __restrict__ fP2,
    bf16* __restrict__ M_h, bf16* __restrict__ M_l,
    bf16* __restrict__ MT_h, bf16* __restrict__ MT_l)
{
    const int z = blockIdx.z;
    if (z < 8) {
        const long long ao = (long long)z * S * Hd;
        gemm_core<1, 0>(ctx_h + ao, ctx_l + ao, ow_h, ow_l, out_b, nullptr,
                        al_h + ao, al_l + ao, nullptr, nullptr,
                        blockIdx.y * 128, blockIdx.x * 128);
    } else {
        chain_work(z - 8, P2_h, P2_l, QT2_h, QT2_l, fP2,
                   M_h, M_l, MT_h, MT_l, 2, 1);
    }
}

// plain GEMM wrapper (alignM, final)
template <int MODE, int WSEL>
__global__ __launch_bounds__(256, 2) void tc_gemm(
    const bf16* __restrict__ Ah, const bf16* __restrict__ Al, long long sAz,
    const bf16* __restrict__ Wh, const bf16* __restrict__ Wl,
    const float* __restrict__ bias, const int* __restrict__ lang,
    float* __restrict__ C, bf16* __restrict__ Ch, bf16* __restrict__ Cl,
    long long sCz)
{
    const int z = blockIdx.z;
    const bf16* wh = Wh;
    const bf16* wl = Wl;
    const float* bs = bias;
    if (WSEL) {
        const int lg = __ldg(&lang[z]);
        wh += (long long)lg * HH;
        wl += (long long)lg * HH;
        if (bias) bs += lg * Hd;
    }
    const long long ao = (long long)z * sAz;
    const long long co = (long long)z * sCz;
    gemm_core<MODE, 0>(Ah + ao, Al + ao, wh, wl, bs,
                       (MODE == 0) ? C + co : nullptr,
                       (MODE != 0) ? Ch + co : nullptr,
                       (MODE != 0) ? Cl + co : nullptr,
                       nullptr, nullptr,
                       blockIdx.y * 128, blockIdx.x * 128);
}

// ---------------------------------------------------------------------------
// Tensor-core flash attention (unchanged from round 8)
// ---------------------------------------------------------------------------
constexpr int AT_CHUNK = 64 * 80;
constexpr int AT_TILE  = 2 * AT_CHUNK;
constexpr int ATT_SMEM = 6 * AT_TILE;

__global__ __launch_bounds__(256) void k_attn_tc(
    const bf16* __restrict__ Qg_h, const bf16* __restrict__ Qg_l,
    const bf16* __restrict__ Kg_h, const bf16* __restrict__ Kg_l,
    const bf16* __restrict__ Vg_h, const bf16* __restrict__ Vg_l,
    bf16* __restrict__ Oh, bf16* __restrict__ Ol)
{
    extern __shared__ char dsm[];
    __shared__ float smax[4][2][16];
    __shared__ float larr[2][64];

    const int qt = blockIdx.x, h = blockIdx.y, b = blockIdx.z;
    const int tid = threadIdx.x;
    const int wid = tid >> 5, lane = tid & 31;
    const int wm = wid & 3, wn = wid >> 2;
    const int g = lane >> 2, t2 = (lane & 3) * 2;
    const int r_off = ((lane >> 3) & 1) * 8 + (lane & 7);
    const int c_off = (lane >> 4) * 8;

    const uint32_t sQh = smem_u32(dsm);
    const uint32_t sQl = sQh + AT_TILE;
    const uint32_t sKh = sQh + 2 * AT_TILE;
    const uint32_t sKl = sQh + 3 * AT_TILE;
    const uint32_t sVh = sQh + 4 * AT_TILE;
    const uint32_t sVl = sQh + 5 * AT_TILE;
    unsigned short* vth16 = (unsigned short*)(dsm + 4 * AT_TILE);
    unsigned short* vtl16 = (unsigned short*)(dsm + 5 * AT_TILE);

    const long long qrow0 = (long long)(b * S + qt * 64);
    const int hoff = h * 64;

#pragma unroll
    for (int i = 0; i < 2; i++) {
        const int task = i * 256 + tid;
        const int row = task >> 3, rem = task & 7;
        const int chunk = rem >> 2, sub = rem & 3;
        const uint32_t sd = chunk * AT_CHUNK + row * 80 + sub * 16;
        const long long gsrc = (qrow0 + row) * Hd + hoff + chunk * 32 + sub * 8;
        cp16(sQh + sd, Qg_h + gsrc);
        cp16(sQl + sd, Qg_l + gsrc);
    }
    cp_commit();

    float m0v = -1e30f, m1v = -1e30f, l0v = 0.f, l1v = 0.f;
    float ctx[8][4];
#pragma unroll
    for (int t = 0; t < 8; t++)
#pragma unroll
        for (int e = 0; e < 4; e++) ctx[t][e] = 0.f;

    for (int kt = 0; kt < 12; kt++) {
        __syncthreads();
        const long long krow0 = (long long)(b * S + kt * 64);
#pragma unroll
        for (int i = 0; i < 2; i++) {
            const int task = i * 256 + tid;
            const int row = task >> 3, rem = task & 7;
            const int chunk = rem >> 2, sub = rem & 3;
            const uint32_t sd = chunk * AT_CHUNK + row * 80 + sub * 16;
            const long long gsrc = (krow0 + row) * Hd + hoff + chunk * 32 + sub * 8;
            cp16(sKh + sd, Kg_h + gsrc);
            cp16(sKl + sd, Kg_l + gsrc);
        }
        cp_commit();
#pragma unroll
        for (int i = 0; i < 8; i++) {
            const int task = i * 256 + tid;
            const int r = task >> 5;
            const int c2 = (task & 31) * 2;
            const long long gsrc = (krow0 + r) * Hd + hoff + c2;
            const uint32_t vh2 = *(const uint32_t*)(Vg_h + gsrc);
            const uint32_t vl2 = *(const uint32_t*)(Vg_l + gsrc);
            const int base = (r >> 5) * 2560 + (r & 31);
            vth16[base + c2 * 40]       = (unsigned short)(vh2 & 0xffff);
            vth16[base + (c2 + 1) * 40] = (unsigned short)(vh2 >> 16);
            vtl16[base + c2 * 40]       = (unsigned short)(vl2 & 0xffff);
            vtl16[base + (c2 + 1) * 40] = (unsigned short)(vl2 >> 16);
        }
        cp_wait<0>();
        __syncthreads();

        float sacc[4][4];
#pragma unroll
        for (int t = 0; t < 4; t++)
#pragma unroll
            for (int e = 0; e < 4; e++) sacc[t][e] = 0.f;

#pragma unroll
        for (int c = 0; c < 2; c++) {
#pragma unroll
            for (int kk2 = 0; kk2 < 2; kk2++) {
                const uint32_t koff = c * AT_CHUNK + kk2 * 32;
                uint32_t qa_h[4], qa_l[4];
                ldsm4(qa_h, sQh + koff + (wm * 16 + r_off) * 80 + c_off * 2);
                ldsm4(qa_l, sQl + koff + (wm * 16 + r_off) * 80 + c_off * 2);
#pragma unroll
                for (int u = 0; u < 2; u++) {
                    const uint32_t roff2 = koff + (wn * 32 + u * 16 + r_off) * 80 + c_off * 2;
                    uint32_t kb_h[4], kb_l[4];
                    ldsm4(kb_h, sKh + roff2);
                    ldsm4(kb_l, sKl + roff2);
                    mma_bf16(sacc[u * 2],     qa_h, kb_h[0], kb_h[2]);
                    mma_bf16(sacc[u * 2 + 1], qa_h, kb_h[1], kb_h[3]);
                    mma_bf16(sacc[u * 2],     qa_l, kb_h[0], kb_h[2]);
                    mma_bf16(sacc[u * 2 + 1], qa_l, kb_h[1], kb_h[3]);
                    mma_bf16(sacc[u * 2],     qa_h, kb_l[0], kb_l[2]);
                    mma_bf16(sacc[u * 2 + 1], qa_h, kb_l[1], kb_l[3]);
                }
            }
        }
#pragma unroll
        for (int t = 0; t < 4; t++)
#pragma unroll
            for (int e = 0; e < 4; e++) sacc[t][e] *= 0.125f;

        float rm0 = -1e30f, rm1 = -1e30f;
#pragma unroll
        for (int t = 0; t < 4; t++) {
            rm0 = fmaxf(rm0, fmaxf(sacc[t][0], sacc[t][1]));
            rm1 = fmaxf(rm1, fmaxf(sacc[t][2], sacc[t][3]));
        }
        rm0 = fmaxf(rm0, __shfl_xor_sync(0xffffffffu, rm0, 1));
        rm0 = fmaxf(rm0, __shfl_xor_sync(0xffffffffu, rm0, 2));
        rm1 = fmaxf(rm1, __shfl_xor_sync(0xffffffffu, rm1, 1));
        rm1 = fmaxf(rm1, __shfl_xor_sync(0xffffffffu, rm1, 2));
        if ((lane & 3) == 0) {
            smax[wm][wn][g]     = rm0;
            smax[wm][wn][g + 8] = rm1;
        }
        __syncthreads();
        rm0 = fmaxf(rm0, smax[wm][wn ^ 1][g]);
        rm1 = fmaxf(rm1, smax[wm][wn ^ 1][g + 8]);

        const float mn0 = fmaxf(m0v, rm0);
        const float mn1 = fmaxf(m1v, rm1);
        const float a0 = __expf(m0v - mn0);
        const float a1 = __expf(m1v - mn1);
        m0v = mn0; m1v = mn1;

        float rs0 = 0.f, rs1 = 0.f;
#pragma unroll
        for (int t = 0; t < 4; t++) {
            sacc[t][0] = __expf(sacc[t][0] - mn0);
            sacc[t][1] = __expf(sacc[t][1] - mn0);
            sacc[t][2] = __expf(sacc[t][2] - mn1);
            sacc[t][3] = __expf(sacc[t][3] - mn1);
            rs0 += sacc[t][0] + sacc[t][1];
            rs1 += sacc[t][2] + sacc[t][3];
        }
        rs0 += __shfl_xor_sync(0xffffffffu, rs0, 1);
        rs0 += __shfl_xor_sync(0xffffffffu, rs0, 2);
        rs1 += __shfl_xor_sync(0xffffffffu, rs1, 1);
        rs1 += __shfl_xor_sync(0xffffffffu, rs1, 2);
        l0v = l0v * a0 + rs0;
        l1v = l1v * a1 + rs1;
#pragma unroll
        for (int t = 0; t < 8; t++) {
            ctx[t][0] *= a0; ctx[t][1] *= a0;
            ctx[t][2] *= a1; ctx[t][3] *= a1;
        }

        uint32_t pah[2][4], pal[2][4];
#pragma unroll
        for (int kk2 = 0; kk2 < 2; kk2++) {
            const int e = 2 * kk2;
#pragma unroll
            for (int half = 0; half < 2; half++) {
                const int tt = e + half;
                float v0 = sacc[tt][0], v1 = sacc[tt][1];
                float v2 = sacc[tt][2], v3 = sacc[tt][3];
                bf16 h0 = __float2bfloat16(v0), h1 = __float2bfloat16(v1);
                bf16 h2 = __float2bfloat16(v2), h3 = __float2bfloat16(v3);
                pah[kk2][half * 2 + 0] = pack_bf(h0, h1);
                pah[kk2][half * 2 + 1] = pack_bf(h2, h3);
                pal[kk2][half * 2 + 0] =
                    pack_f2(v0 - __bfloat162float(h0), v1 - __bfloat162float(h1));
                pal[kk2][half * 2 + 1] =
                    pack_f2(v2 - __bfloat162float(h2), v3 - __bfloat162float(h3));
            }
        }

#pragma unroll
        for (int kk2 = 0; kk2 < 2; kk2++) {
            const uint32_t voff = wn * AT_CHUNK + kk2 * 32;
#pragma unroll
            for (int u = 0; u < 4; u++) {
                const uint32_t roff2 = voff + (u * 16 + r_off) * 80 + c_off * 2;
                uint32_t vb_h[4], vb_l[4];
                ldsm4(vb_h, sVh + roff2);
                ldsm4(vb_l, sVl + roff2);
                mma_bf16(ctx[u * 2],     pah[kk2], vb_h[0], vb_h[2]);
                mma_bf16(ctx[u * 2 + 1], pah[kk2], vb_h[1], vb_h[3]);
                mma_bf16(ctx[u * 2],     pal[kk2], vb_h[0], vb_h[2]);
                mma_bf16(ctx[u * 2 + 1], pal[kk2], vb_h[1], vb_h[3]);
                mma_bf16(ctx[u * 2],     pah[kk2], vb_l[0], vb_l[2]);
                mma_bf16(ctx[u * 2 + 1], pah[kk2], vb_l[1], vb_l[3]);
            }
        }
    }

    __syncthreads();
    float* csum = (float*)(dsm + 2 * AT_TILE);
    if (wn == 1) {
#pragma unroll
        for (int t = 0; t < 8; t++) {
            const int u = t >> 1, v = t & 1;
            const int colb = u * 16 + v * 8 + t2;
            csum[(wm * 16 + g) * 68 + colb]         = ctx[t][0];
            csum[(wm * 16 + g) * 68 + colb + 1]     = ctx[t][1];
            csum[(wm * 16 + g + 8) * 68 + colb]     = ctx[t][2];
            csum[(wm * 16 + g + 8) * 68 + colb + 1] = ctx[t][3];
        }
    }
    if ((lane & 3) == 0) {
        larr[wn][wm * 16 + g]     = l0v;
        larr[wn][wm * 16 + g + 8] = l1v;
    }
    __syncthreads();
    if (wn == 0) {
#pragma unroll
        for (int t = 0; t < 8; t++) {
            const int u = t >> 1, v = t & 1;
            const int colb = u * 16 + v * 8 + t2;
            csum[(wm * 16 + g) * 68 + colb]         += ctx[t][0];
            csum[(wm * 16 + g) * 68 + colb + 1]     += ctx[t][1];
            csum[(wm * 16 + g + 8) * 68 + colb]     += ctx[t][2];
            csum[(wm * 16 + g + 8) * 68 + colb + 1] += ctx[t][3];
        }
    }
    __syncthreads();
#pragma unroll
    for (int i = 0; i < 4; i++) {
        const int idx = i * 256 + tid;
        const int row = idx >> 4, c4 = (idx & 15) * 4;
        const float inv = 1.f / (larr[0][row] + larr[1][row]);
        float4 v = *(float4*)&csum[row * 68 + c4];
        v.x *= inv; v.y *= inv; v.z *= inv; v.w *= inv;
        bf16 h0 = __float2bfloat16(v.x), h1 = __float2bfloat16(v.y);
        bf16 h2 = __float2bfloat16(v.z), h3 = __float2bfloat16(v.w);
        bf16 l0 = __float2bfloat16(v.x - __bfloat162float(h0));
        bf16 l1 = __float2bfloat16(v.y - __bfloat162float(h1));
        bf16 l2 = __float2bfloat16(v.z - __bfloat162float(h2));
        bf16 l3 = __float2bfloat16(v.w - __bfloat162float(h3));
        const long long off = (qrow0 + row) * Hd + hoff + c4;
        *(uint2*)(Oh + off) = make_uint2(pack_bf(h0, h1), pack_bf(h2, h3));
        *(uint2*)(Ol + off) = make_uint2(pack_bf(l0, l1), pack_bf(l2, l3));
    }
}

// ---------------------------------------------------------------------------
// conversions / chain leaves / LN
// ---------------------------------------------------------------------------
__global__ __launch_bounds__(256) void k_conv(
    const float* __restrict__ src, bf16* __restrict__ dh,
    bf16* __restrict__ dl)
{
    const long long i4 = ((long long)blockIdx.x * 256 + threadIdx.x) * 4;
    float4 v = *(const float4*)(src + i4);
    bf16 h0 = __float2bfloat16(v.x), h1 = __float2bfloat16(v.y);
    bf16 h2 = __float2bfloat16(v.z), h3 = __float2bfloat16(v.w);
    bf16 l0 = __float2bfloat16(v.x - __bfloat162float(h0));
    bf16 l1 = __float2bfloat16(v.y - __bfloat162float(h1));
    bf16 l2 = __float2bfloat16(v.z - __bfloat162float(h2));
    bf16 l3 = __float2bfloat16(v.w - __bfloat162float(h3));
    *(uint2*)(dh + i4) = make_uint2(pack_bf(h0, h1), pack_bf(h2, h3));
    *(uint2*)(dl + i4) = make_uint2(pack_bf(l0, l1), pack_bf(l2, l3));
}

__global__ void k_flags(const int* __restrict__ lang,
                        unsigned char* fF, unsigned char* fP1, unsigned char* fP2)
{
    if (threadIdx.x == 0 && blockIdx.x == 0) {
        for (int a = 0; a < NL; a++) {
            for (int j = 0; j < 8; j++) fF[a * 8 + j] = (lang[j] == a) ? 1 : 0;
            for (int p = 0; p < 4; p++)
                fP1[a * 4 + p] = fF[a * 8 + 2 * p] & fF[a * 8 + 2 * p + 1];
            for (int p = 0; p < 2; p++)
                fP2[a * 2 + p] = fP1[a * 4 + 2 * p] & fP1[a * 4 + 2 * p + 1];
        }
    }
}

__device__ __forceinline__ void split_store4(
    bf16* dh, bf16* dl, long long off, float x, float y, float z, float w)
{
    bf16 h0 = __float2bfloat16(x), h1 = __float2bfloat16(y);
    bf16 h2 = __float2bfloat16(z), h3 = __float2bfloat16(w);
    bf16 l0 = __float2bfloat16(x - __bfloat162float(h0));
    bf16 l1 = __float2bfloat16(y - __bfloat162float(h1));
    bf16 l2 = __float2bfloat16(z - __bfloat162float(h2));
    bf16 l3 = __float2bfloat16(w - __bfloat162float(h3));
    *(uint2*)(dh + off) = make_uint2(pack_bf(h0, h1), pack_bf(h2, h3));
    *(uint2*)(dl + off) = make_uint2(pack_bf(l0, l1), pack_bf(l2, l3));
}

__global__ __launch_bounds__(256) void k_factors(
    const float* __restrict__ alignT, const int* __restrict__ lang,
    bf16* __restrict__ Fh, bf16* __restrict__ Fl,
    bf16* __restrict__ FTh, bf16* __restrict__ FTl)
{
    const int node = blockIdx.y;
    const int a = node >> 3, j = node & 7;
    const int c = __ldg(&lang[j]);
    const long long nb = (long long)node * HH;
    const long long i4 = ((long long)blockIdx.x * 256 + threadIdx.x) * 4;
    const int r = (int)(i4 / Hd), col = (int)(i4 % Hd);

    if (c == a) {
        float v0 = (col + 0 == r) ? 1.f : 0.f;
        float v1 = (col + 1 == r) ? 1.f : 0.f;
        float v2 = (col + 2 == r) ? 1.f : 0.f;
        float v3 = (col + 3 == r) ? 1.f : 0.f;
        split_store4(Fh,  Fl,  nb + i4, v0, v1, v2, v3);
        split_store4(FTh, FTl, nb + i4, v0, v1, v2, v3);
    } else {
        const float* sm = alignT + (long long)(a * NL + c) * HH;
        float4 v = *(const float4*)(sm + i4);
        split_store4(Fh, Fl, nb + i4, v.x, v.y, v.z, v.w);
        float t0 = sm[(long long)(col + 0) * Hd + r];
        float t1 = sm[(long long)(col + 1) * Hd + r];
        float t2 = sm[(long long)(col + 2) * Hd + r];
        float t3 = sm[(long long)(col + 3) * Hd + r];
        split_store4(FTh, FTl, nb + i4, t0, t1, t2, t3);
    }
}

__global__ __launch_bounds__(256) void k_ln(
    const float* __restrict__ X, const float* __restrict__ Rres,
    const float* __restrict__ gam, const float* __restrict__ bet,
    float* __restrict__ out)
{
    const int row = blockIdx.x;
    const long long base = (long long)row * Hd;
    const int tid = threadIdx.x;

    float v[3];
    float s = 0.f, s2 = 0.f;
#pragma unroll
    for (int u = 0; u < 3; u++) {
        const int idx = tid + u * 256;
        const float val = X[base + idx] + Rres[base + idx];
        v[u] = val; s += val; s2 += val * val;
    }
#pragma unroll
    for (int off = 16; off >= 1; off >>= 1) {
        s  += __shfl_xor_sync(0xffffffffu, s, off);
        s2 += __shfl_xor_sync(0xffffffffu, s2, off);
    }
    __shared__ float ss[8], ss2[8], mv[2];
    const int wid = tid >> 5, lane = tid & 31;
    if (lane == 0) { ss[wid] = s; ss2[wid] = s2; }
    __syncthreads();
    if (tid == 0) {
        float S_ = 0.f, S2_ = 0.f;
        for (int w = 0; w < 8; w++) { S_ += ss[w]; S2_ += ss2[w]; }
        const float mean = S_ * (1.f / 768.f);
        const float var  = S2_ * (1.f / 768.f) - mean * mean;
        mv[0] = mean;
        mv[1] = rsqrtf(var + 1e-5f);
    }
    __syncthreads();
    const float mean = mv[0], rstd = mv[1];
#pragma unroll
    for (int u = 0; u < 3; u++) {
        const int idx = tid + u * 256;
        out[base + idx] = (v[u] - mean) * rstd * gam[idx] + bet[idx];
    }
}

// ---------------------------------------------------------------------------
// kernel_launch  (launch #5 = k_l1, the big merged GEMM, for ncu)
// ---------------------------------------------------------------------------
#define SYM(v, s) cudaGetSymbolAddress((void**)&v, s)

extern "C" void kernel_launch(void* const* d_in, const int* in_sizes, int n_in,
                              void* d_out, int out_size)
{
    const float* hs      = (const float*)d_in[0];
    const int*   lang    = (const int*)  d_in[1];
    const float* Wq_lang = (const float*)d_in[3];
    const float* bq_lang = (const float*)d_in[4];
    const float* Wk_lang = (const float*)d_in[5];
    const float* bk_lang = (const float*)d_in[6];
    const float* in_w    = (const float*)d_in[7];
    const float* in_b    = (const float*)d_in[8];
    const float* out_w   = (const float*)d_in[9];
    const float* out_b   = (const float*)d_in[10];
    const float* alignT  = (const float*)d_in[11];
    const float* proj_w  = (const float*)d_in[12];
    const float* proj_b  = (const float*)d_in[13];
    const float* ln_g    = (const float*)d_in[14];
    const float* ln_b    = (const float*)d_in[15];
    float* out = (float*)d_out;

    float* obuf;
    SYM(obuf, g_o);

    bf16 *hs_h, *hs_l, *q_h, *q_l, *k_h, *k_l;
    bf16 *Qh, *Ql, *Kh, *Kl, *Vh, *Vl, *ctx_h, *ctx_l;
    bf16 *al_h, *al_l, *al2_h, *al2_l;
    SYM(hs_h, g_hs_h);   SYM(hs_l, g_hs_l);
    SYM(q_h, g_q_h);     SYM(q_l, g_q_l);
    SYM(k_h, g_k_h);     SYM(k_l, g_k_l);
    SYM(Qh, g_Qh);       SYM(Ql, g_Ql);
    SYM(Kh, g_Kh);       SYM(Kl, g_Kl);
    SYM(Vh, g_Vh);       SYM(Vl, g_Vl);
    SYM(ctx_h, g_ctx_h); SYM(ctx_l, g_ctx_l);
    SYM(al_h, g_al_h);   SYM(al_l, g_al_l);
    SYM(al2_h, g_al2_h); SYM(al2_l, g_al2_l);

    bf16 *Wq_h, *Wq_l, *Wk_h, *Wk_l, *inw_h, *inw_l, *ow_h, *ow_l, *pw_h, *pw_l;
    SYM(Wq_h, g_Wq_h);   SYM(Wq_l, g_Wq_l);
    SYM(Wk_h, g_Wk_h);   SYM(Wk_l, g_Wk_l);
    SYM(inw_h, g_inw_h); SYM(inw_l, g_inw_l);
    SYM(ow_h, g_ow_h);   SYM(ow_l, g_ow_l);
    SYM(pw_h, g_pw_h);   SYM(pw_l, g_pw_l);

    bf16 *F_h, *F_l, *FT_h, *FT_l, *P1_h, *P1_l, *QT1_h, *QT1_l;
    bf16 *P2_h, *P2_l, *QT2_h, *QT2_l, *M_h, *M_l, *MT_h, *MT_l;
    SYM(F_h, g_F_h);   SYM(F_l, g_F_l);   SYM(FT_h, g_FT_h); SYM(FT_l, g_FT_l);
    SYM(P1_h, g_P1_h); SYM(P1_l, g_P1_l); SYM(QT1_h, g_QT1_h); SYM(QT1_l, g_QT1_l);
    SYM(P2_h, g_P2_h); SYM(P2_l, g_P2_l); SYM(QT2_h, g_QT2_h); SYM(QT2_l, g_QT2_l);
    SYM(M_h, g_M_h);   SYM(M_l, g_M_l);   SYM(MT_h, g_MT_h); SYM(MT_l, g_MT_l);

    unsigned char *fF, *fP1, *fP2;
    SYM(fF, g_fF); SYM(fP1, g_fP1); SYM(fP2, g_fP2);

    cudaFuncSetAttribute(k_l1, cudaFuncAttributeMaxDynamicSharedMemorySize, GEMM_SMEM);
    cudaFuncSetAttribute(k_l2, cudaFuncAttributeMaxDynamicSharedMemorySize, GEMM_SMEM);
    cudaFuncSetAttribute(k_l3, cudaFuncAttributeMaxDynamicSharedMemorySize, GEMM_SMEM);
    cudaFuncSetAttribute(tc_gemm<0, 0>, cudaFuncAttributeMaxDynamicSharedMemorySize, GEMM_SMEM);
    cudaFuncSetAttribute(tc_gemm<1, 1>, cudaFuncAttributeMaxDynamicSharedMemorySize, GEMM_SMEM);
    cudaFuncSetAttribute(k_attn_tc, cudaFuncAttributeMaxDynamicSharedMemorySize, ATT_SMEM);

    const long long sBH = (long long)S * Hd;
    const dim3 thr(256);

    // 0-2: conversions for L1
    k_conv<<<BS * Hd / 1024, thr>>>(hs, hs_h, hs_l);
    k_conv<<<(int)(NL * HH / 1024), thr>>>(Wq_lang, Wq_h, Wq_l);
    k_conv<<<(int)(NL * HH / 1024), thr>>>(Wk_lang, Wk_h, Wk_l);
    // 3-4: chain leaves
    k_flags<<<1, 32>>>(lang, fF, fP1, fP2);
    k_factors<<<dim3((int)(HH / 1024), NL * 8), thr>>>(alignT, lang, F_h, F_l, FT_h, FT_l);

    // 5: L1 = q/k lang projections + chain level 1  (profiled by ncu)
    k_l1<<<dim3(6, 6, 36), thr, GEMM_SMEM>>>(
        hs_h, hs_l, Wq_h, Wq_l, Wk_h, Wk_l, bq_lang, bk_lang, lang,
        q_h, q_l, k_h, k_l,
        F_h, F_l, FT_h, FT_l, fF, P1_h, P1_l, QT1_h, QT1_l);

    // remaining conversions
    k_conv<<<(int)(3 * HH / 1024), thr>>>(in_w, inw_h, inw_l);
    k_conv<<<(int)(HH / 1024), thr>>>(out_w, ow_h, ow_l);
    k_conv<<<(int)(HH / 1024), thr>>>(proj_w, pw_h, pw_l);

    // L2 = QKV + chain level 2
    k_l2<<<dim3(6, 6, 34), thr, GEMM_SMEM>>>(
        q_h, q_l, k_h, k_l, hs_h, hs_l, inw_h, inw_l, in_b,
        Qh, Ql, Kh, Kl, Vh, Vl,
        P1_h, P1_l, QT1_h, QT1_l, fP1, P2_h, P2_l, QT2_h, QT2_l);

    // attention
    k_attn_tc<<<dim3(S / 64, NH, Bsz), thr, ATT_SMEM>>>(
        Qh, Ql, Kh, Kl, Vh, Vl, ctx_h, ctx_l);

    // L3 = out_proj + chain level 3
    k_l3<<<dim3(6, 6, 13), thr, GEMM_SMEM>>>(
        ctx_h, ctx_l, ow_h, ow_l, out_b, al_h, al_l,
        P2_h, P2_l, QT2_h, QT2_l, fP2, M_h, M_l, MT_h, MT_l);

    // aligned @ M[lang[b]]
    tc_gemm<1, 1><<<dim3(6, 6, Bsz), thr, GEMM_SMEM>>>(
        al_h, al_l, sBH, MT_h, MT_l, nullptr, lang, nullptr, al2_h, al2_l, sBH);

    // final proj (fp32 out)
    tc_gemm<0, 0><<<dim3(6, 48, 1), thr, GEMM_SMEM>>>(
        al2_h, al2_l, 0, pw_h, pw_l, proj_b, nullptr, obuf, nullptr, nullptr, 0);

    // residual + LayerNorm
    k_ln<<<BS, thr>>>(obuf, hs, ln_g, ln_b, out);
}

// round 10
// speedup vs baseline: 2.6862x; 1.1540x over previous
#include <cuda_runtime.h>
#include <cuda_bf16.h>
#include <cstdint>

// ---------------------------------------------------------------------------
// Problem constants
// ---------------------------------------------------------------------------
constexpr int Bsz = 8;
constexpr int S   = 768;
constexpr int Hd  = 768;
constexpr int NH  = 12;
constexpr int NL  = 5;
constexpr int BS  = Bsz * S;
constexpr long long HH = (long long)Hd * Hd;

typedef __nv_bfloat16 bf16;

// ---------------------------------------------------------------------------
// Scratch
// ---------------------------------------------------------------------------
__device__ float g_o  [BS * Hd];

__device__ bf16 g_hs_h [BS * Hd], g_hs_l [BS * Hd];
__device__ bf16 g_q_h  [BS * Hd], g_q_l  [BS * Hd];
__device__ bf16 g_k_h  [BS * Hd], g_k_l  [BS * Hd];
__device__ bf16 g_Qh   [BS * Hd], g_Ql   [BS * Hd];
__device__ bf16 g_Kh   [BS * Hd], g_Kl   [BS * Hd];
__device__ bf16 g_Vh   [BS * Hd], g_Vl   [BS * Hd];
__device__ bf16 g_ctx_h[BS * Hd], g_ctx_l[BS * Hd];
__device__ bf16 g_al_h [BS * Hd], g_al_l [BS * Hd];
__device__ bf16 g_al2_h[BS * Hd], g_al2_l[BS * Hd];

__device__ bf16 g_Wq_h [NL * Hd * Hd], g_Wq_l [NL * Hd * Hd];
__device__ bf16 g_Wk_h [NL * Hd * Hd], g_Wk_l [NL * Hd * Hd];
__device__ bf16 g_inw_h[3 * Hd * Hd],  g_inw_l[3 * Hd * Hd];
__device__ bf16 g_ow_h [Hd * Hd],      g_ow_l [Hd * Hd];
__device__ bf16 g_pw_h [Hd * Hd],      g_pw_l [Hd * Hd];

__device__ bf16 g_F_h [NL * 8 * Hd * Hd], g_F_l [NL * 8 * Hd * Hd];
__device__ bf16 g_FT_h[NL * 8 * Hd * Hd], g_FT_l[NL * 8 * Hd * Hd];
__device__ bf16 g_P1_h[NL * 4 * Hd * Hd], g_P1_l[NL * 4 * Hd * Hd];
__device__ bf16 g_QT1_h[NL * 4 * Hd * Hd], g_QT1_l[NL * 4 * Hd * Hd];
__device__ bf16 g_P2_h[NL * 2 * Hd * Hd], g_P2_l[NL * 2 * Hd * Hd];
__device__ bf16 g_QT2_h[NL * 2 * Hd * Hd], g_QT2_l[NL * 2 * Hd * Hd];
__device__ bf16 g_M_h [NL * Hd * Hd],     g_M_l [NL * Hd * Hd];
__device__ bf16 g_MT_h[NL * Hd * Hd],     g_MT_l[NL * Hd * Hd];

__device__ unsigned char g_fF [NL * 8];
__device__ unsigned char g_fP1[NL * 4];
__device__ unsigned char g_fP2[NL * 2];

// ---------------------------------------------------------------------------
// PTX helpers
// ---------------------------------------------------------------------------
__device__ __forceinline__ uint32_t smem_u32(const void* p) {
    return (uint32_t)__cvta_generic_to_shared(p);
}
__device__ __forceinline__ void cp16(uint32_t d, const void* s) {
    asm volatile("cp.async.cg.shared.global [%0], [%1], 16;"
                 :: "r"(d), "l"(s) : "memory");
}
__device__ __forceinline__ void cp_commit() {
    asm volatile("cp.async.commit_group;" ::: "memory");
}
template <int N>
__device__ __forceinline__ void cp_wait() {
    asm volatile("cp.async.wait_group %0;" :: "n"(N) : "memory");
}
__device__ __forceinline__ void ldsm4(uint32_t* r, uint32_t addr) {
    asm volatile("ldmatrix.sync.aligned.m8n8.x4.shared.b16 {%0,%1,%2,%3}, [%4];"
                 : "=r"(r[0]), "=r"(r[1]), "=r"(r[2]), "=r"(r[3]) : "r"(addr));
}
__device__ __forceinline__ void mma_bf16(float* d, const uint32_t* a,
                                         uint32_t b0, uint32_t b1) {
    asm volatile(
        "mma.sync.aligned.m16n8k16.row.col.f32.bf16.bf16.f32 "
        "{%0,%1,%2,%3}, {%4,%5,%6,%7}, {%8,%9}, {%0,%1,%2,%3};"
        : "+f"(d[0]), "+f"(d[1]), "+f"(d[2]), "+f"(d[3])
        : "r"(a[0]), "r"(a[1]), "r"(a[2]), "r"(a[3]), "r"(b0), "r"(b1));
}
__device__ __forceinline__ uint32_t pack_bf(bf16 a, bf16 b) {
    return (uint32_t)__bfloat16_as_ushort(a) |
           ((uint32_t)__bfloat16_as_ushort(b) << 16);
}
__device__ __forceinline__ uint32_t pack_f2(float a, float b) {
    return pack_bf(__float2bfloat16(a), __float2bfloat16(b));
}

// ---------------------------------------------------------------------------
// GEMM: 128x128 tile, BLK_K=32, 8 warps, 2-stage pipeline.
// TERMS: 3 = Ah*Wh + Al*Wh + Ah*Wl; 2 = Ah*Wh + Al*Wh; 1 = Ah*Wh.
// ---------------------------------------------------------------------------
constexpr int SKP     = 40;
constexpr int TILE_B  = 128 * SKP * 2;
constexpr int STAGE_B = 4 * TILE_B;
constexpr int GEMM_SMEM = 2 * STAGE_B;       // 81920 B

__device__ __forceinline__ void gemm_issue(
    const bf16* __restrict__ base, int lw, uint32_t sdst0, int kc)
{
    const bf16* g0 = base + kc * 32;
#pragma unroll
    for (int i = 0; i < 8; i++) {
        const int chunk = i * 64 + lw;
        const int row = chunk >> 2, cs = chunk & 3;
        cp16(sdst0 + row * (SKP * 2) + cs * 16,
             g0 + (long long)row * Hd + cs * 8);
    }
}

// MODE 0: fp32 out (+bias). MODE 1: bf16 hi/lo out (+bias if non-null).
// MODE 2: bf16 hi/lo out + transposed hi/lo out (no bias).
template <int MODE, int TERMS>
__device__ void gemm_core(
    const bf16* __restrict__ Ah, const bf16* __restrict__ Al,
    const bf16* __restrict__ Wh, const bf16* __restrict__ Wl,
    const float* __restrict__ bias,
    float* __restrict__ C,
    bf16* __restrict__ Ch, bf16* __restrict__ Cl,
    bf16* __restrict__ Th, bf16* __restrict__ Tl,
    int m0, int n0)
{
    extern __shared__ char dsm[];
    const int tid = threadIdx.x;
    const int wid = tid >> 5, lane = tid & 31;
    const int m_off = (wid & 3) * 32;
    const int n_off = (wid >> 2) * 64;
    const uint32_t sbase = smem_u32(dsm);

    const int ltile = tid >> 6;
    const int lw = tid & 63;
    const bf16* gbase =
        (ltile == 0) ? Ah + (long long)m0 * Hd :
        (ltile == 1) ? Al + (long long)m0 * Hd :
        (ltile == 2) ? Wh + (long long)n0 * Hd :
                       Wl + (long long)n0 * Hd;
    const uint32_t sdst_tile = ltile * TILE_B;
    const bool do_issue =
        (ltile == 0) || (ltile == 2) ||
        (ltile == 1 && TERMS >= 2) || (ltile == 3 && TERMS == 3);

    if (do_issue) gemm_issue(gbase, lw, sbase + sdst_tile, 0);
    cp_commit();
    if (do_issue) gemm_issue(gbase, lw, sbase + STAGE_B + sdst_tile, 1);
    cp_commit();

    float acc[2][8][4];
#pragma unroll
    for (int mi = 0; mi < 2; mi++)
#pragma unroll
        for (int j = 0; j < 8; j++)
#pragma unroll
            for (int e = 0; e < 4; e++) acc[mi][j][e] = 0.f;

    const int r_off = ((lane >> 3) & 1) * 8 + (lane & 7);
    const int c_off = (lane >> 4) * 8;

    for (int kc = 0; kc < 24; kc++) {
        cp_wait<1>();
        __syncthreads();
        const uint32_t sb = sbase + (kc & 1) * STAGE_B;
        const uint32_t aAh = sb + (m_off + r_off) * (SKP * 2) + c_off * 2;
        const uint32_t aAl = aAh + TILE_B;
        const uint32_t aWh = sb + 2 * TILE_B + (n_off + r_off) * (SKP * 2) + c_off * 2;
        const uint32_t aWl = aWh + TILE_B;

#pragma unroll
        for (int kk = 0; kk < 2; kk++) {
            uint32_t ah[2][4], alr[2][4];
#pragma unroll
            for (int t = 0; t < 2; t++) {
                ldsm4(ah[t], aAh + t * 16 * (SKP * 2) + kk * 32);
                if (TERMS >= 2)
                    ldsm4(alr[t], aAl + t * 16 * (SKP * 2) + kk * 32);
            }
#pragma unroll
            for (int u = 0; u < 4; u++) {
                uint32_t bh[4];
                ldsm4(bh, aWh + u * 16 * (SKP * 2) + kk * 32);
#pragma unroll
                for (int mi = 0; mi < 2; mi++) {
                    mma_bf16(acc[mi][2 * u],     ah[mi], bh[0], bh[2]);
                    mma_bf16(acc[mi][2 * u + 1], ah[mi], bh[1], bh[3]);
                    if (TERMS >= 2) {
                        mma_bf16(acc[mi][2 * u],     alr[mi], bh[0], bh[2]);
                        mma_bf16(acc[mi][2 * u + 1], alr[mi], bh[1], bh[3]);
                    }
                }
                if (TERMS == 3) {
                    uint32_t bl[4];
                    ldsm4(bl, aWl + u * 16 * (SKP * 2) + kk * 32);
#pragma unroll
                    for (int mi = 0; mi < 2; mi++) {
                        mma_bf16(acc[mi][2 * u],     ah[mi], bl[0], bl[2]);
                        mma_bf16(acc[mi][2 * u + 1], ah[mi], bl[1], bl[3]);
                    }
                }
            }
        }
        __syncthreads();
        if (kc + 2 < 24 && do_issue)
            gemm_issue(gbase, lw, sbase + (kc & 1) * STAGE_B + sdst_tile, kc + 2);
        cp_commit();
    }

    float* sf = (float*)dsm;
    const int g = lane >> 2, t2 = (lane & 3) * 2;
#pragma unroll
    for (int mi = 0; mi < 2; mi++)
#pragma unroll
        for (int j = 0; j < 8; j++) {
            const int r = m_off + mi * 16 + g;
            const int c = n_off + j * 8 + t2;
            sf[r * 132 + c]           = acc[mi][j][0];
            sf[r * 132 + c + 1]       = acc[mi][j][1];
            sf[(r + 8) * 132 + c]     = acc[mi][j][2];
            sf[(r + 8) * 132 + c + 1] = acc[mi][j][3];
        }
    __syncthreads();

    if (MODE == 0) {
#pragma unroll 4
        for (int i = 0; i < 16; i++) {
            const int task = i * 256 + tid;
            const int row = task >> 5, c4 = (task & 31) * 4;
            float4 v = *(float4*)&sf[row * 132 + c4];
            v.x += bias[n0 + c4 + 0];
            v.y += bias[n0 + c4 + 1];
            v.z += bias[n0 + c4 + 2];
            v.w += bias[n0 + c4 + 3];
            *(float4*)(C + (long long)(m0 + row) * Hd + n0 + c4) = v;
        }
    } else {
#pragma unroll 4
        for (int i = 0; i < 16; i++) {
            const int task = i * 256 + tid;
            const int row = task >> 5, c4 = (task & 31) * 4;
            float4 v = *(float4*)&sf[row * 132 + c4];
            if (MODE == 1 && bias) {
                v.x += bias[n0 + c4 + 0];
                v.y += bias[n0 + c4 + 1];
                v.z += bias[n0 + c4 + 2];
                v.w += bias[n0 + c4 + 3];
            }
            bf16 h0 = __float2bfloat16(v.x), h1 = __float2bfloat16(v.y);
            bf16 h2 = __float2bfloat16(v.z), h3 = __float2bfloat16(v.w);
            bf16 l0 = __float2bfloat16(v.x - __bfloat162float(h0));
            bf16 l1 = __float2bfloat16(v.y - __bfloat162float(h1));
            bf16 l2 = __float2bfloat16(v.z - __bfloat162float(h2));
            bf16 l3 = __float2bfloat16(v.w - __bfloat162float(h3));
            const long long off = (long long)(m0 + row) * Hd + n0 + c4;
            *(uint2*)(Ch + off) = make_uint2(pack_bf(h0, h1), pack_bf(h2, h3));
            *(uint2*)(Cl + off) = make_uint2(pack_bf(l0, l1), pack_bf(l2, l3));
        }
        if (MODE == 2) {
            const int c = tid & 127;
            const int half = tid >> 7;
#pragma unroll 4
            for (int i = 0; i < 16; i++) {
                const int r4 = half * 64 + i * 4;
                float v0 = sf[(r4 + 0) * 132 + c];
                float v1 = sf[(r4 + 1) * 132 + c];
                float v2 = sf[(r4 + 2) * 132 + c];
                float v3 = sf[(r4 + 3) * 132 + c];
                bf16 h0 = __float2bfloat16(v0), h1 = __float2bfloat16(v1);
                bf16 h2 = __float2bfloat16(v2), h3 = __float2bfloat16(v3);
                bf16 l0 = __float2bfloat16(v0 - __bfloat162float(h0));
                bf16 l1 = __float2bfloat16(v1 - __bfloat162float(h1));
                bf16 l2 = __float2bfloat16(v2 - __bfloat162float(h2));
                bf16 l3 = __float2bfloat16(v3 - __bfloat162float(h3));
                const long long off = (long long)(n0 + c) * Hd + m0 + r4;
                *(uint2*)(Th + off) = make_uint2(pack_bf(h0, h1), pack_bf(h2, h3));
                *(uint2*)(Tl + off) = make_uint2(pack_bf(l0, l1), pack_bf(l2, l3));
            }
        }
    }
}

// ---------------------------------------------------------------------------
// Chain product block (zz = product index within level), TERMS=1 gemm.
// ---------------------------------------------------------------------------
__device__ void chain_work(
    int zz,
    const bf16* __restrict__ sN_h, const bf16* __restrict__ sN_l,
    const bf16* __restrict__ sT_h, const bf16* __restrict__ sT_l,
    const unsigned char* __restrict__ fs,
    bf16* __restrict__ dN_h, bf16* __restrict__ dN_l,
    bf16* __restrict__ dT_h, bf16* __restrict__ dT_l,
    int spa, int dpa)
{
    const int a = zz / dpa, p = zz - a * dpa;
    const int li = a * spa + 2 * p;
    const unsigned char f1 = fs[li], f2 = fs[li + 1];
    const long long zo = (long long)zz * HH;
    const int m0 = blockIdx.y * 128, n0 = blockIdx.x * 128;
    const int tid = threadIdx.x;

    if (f1 & f2) {
#pragma unroll 4
        for (int i = 0; i < 16; i++) {
            const int task = i * 256 + tid;
            const int row = task >> 5, c4 = (task & 31) * 4;
            const int gr = m0 + row, gc = n0 + c4;
            bf16 one = __float2bfloat16(1.f), zero = __float2bfloat16(0.f);
            bf16 h0 = (gc + 0 == gr) ? one : zero;
            bf16 h1 = (gc + 1 == gr) ? one : zero;
            bf16 h2 = (gc + 2 == gr) ? one : zero;
            bf16 h3 = (gc + 3 == gr) ? one : zero;
            const long long off = zo + (long long)gr * Hd + gc;
            uint2 hv = make_uint2(pack_bf(h0, h1), pack_bf(h2, h3));
            uint2 lv = make_uint2(0u, 0u);
            *(uint2*)(dN_h + off) = hv; *(uint2*)(dN_l + off) = lv;
            *(uint2*)(dT_h + off) = hv; *(uint2*)(dT_l + off) = lv;
        }
        return;
    }
    if (f1 | f2) {
        const long long so = (long long)(f1 ? li + 1 : li) * HH;
#pragma unroll 4
        for (int i = 0; i < 8; i++) {
            const int idx = i * 256 + tid;
            const int row = idx >> 4, c8 = (idx & 15) * 8;
            const long long doff = zo + (long long)(m0 + row) * Hd + n0 + c8;
            const long long soff = so + (long long)(m0 + row) * Hd + n0 + c8;
            *(uint4*)(dN_h + doff) = *(const uint4*)(sN_h + soff);
            *(uint4*)(dN_l + doff) = *(const uint4*)(sN_l + soff);
            *(uint4*)(dT_h + doff) = *(const uint4*)(sT_h + soff);
            *(uint4*)(dT_l + doff) = *(const uint4*)(sT_l + soff);
        }
        return;
    }
    gemm_core<2, 1>(sN_h + (long long)li * HH, nullptr,
                    sT_h + (long long)(li + 1) * HH, nullptr,
                    nullptr, nullptr,
                    dN_h + zo, dN_l + zo, dT_h + zo, dT_l + zo, m0, n0);
}

// ---------------------------------------------------------------------------
// Merged launches (TERMS=2 on main path)
// ---------------------------------------------------------------------------
__global__ __launch_bounds__(256, 2) void k_l1(
    const bf16* __restrict__ hs_h, const bf16* __restrict__ hs_l,
    const bf16* __restrict__ Wq_h, const bf16* __restrict__ Wq_l,
    const bf16* __restrict__ Wk_h, const bf16* __restrict__ Wk_l,
    const float* __restrict__ bq, const float* __restrict__ bk,
    const int* __restrict__ lang,
    bf16* __restrict__ q_h, bf16* __restrict__ q_l,
    bf16* __restrict__ k_h, bf16* __restrict__ k_l,
    const bf16* __restrict__ F_h, const bf16* __restrict__ F_l,
    const bf16* __restrict__ FT_h, const bf16* __restrict__ FT_l,
    const unsigned char* __restrict__ fF,
    bf16* __restrict__ P1_h, bf16* __restrict__ P1_l,
    bf16* __restrict__ QT1_h, bf16* __restrict__ QT1_l)
{
    const int z = blockIdx.z;
    if (z < 16) {
        const int fam = z >> 3, b = z & 7;
        const int lg = __ldg(&lang[b]);
        const long long ao = (long long)b * S * Hd;
        const bf16* wh = (fam ? Wk_h : Wq_h) + (long long)lg * HH;
        const bf16* wl = (fam ? Wk_l : Wq_l) + (long long)lg * HH;
        const float* bs = (fam ? bk : bq) + lg * Hd;
        bf16* oh = (fam ? k_h : q_h) + ao;
        bf16* ol = (fam ? k_l : q_l) + ao;
        gemm_core<1, 2>(hs_h + ao, hs_l + ao, wh, wl, bs, nullptr, oh, ol,
                        nullptr, nullptr, blockIdx.y * 128, blockIdx.x * 128);
    } else {
        chain_work(z - 16, F_h, F_l, FT_h, FT_l, fF,
                   P1_h, P1_l, QT1_h, QT1_l, 8, 4);
    }
}

__global__ __launch_bounds__(256, 2) void k_l2(
    const bf16* __restrict__ q_h, const bf16* __restrict__ q_l,
    const bf16* __restrict__ k_h, const bf16* __restrict__ k_l,
    const bf16* __restrict__ hs_h, const bf16* __restrict__ hs_l,
    const bf16* __restrict__ inw_h, const bf16* __restrict__ inw_l,
    const float* __restrict__ in_b,
    bf16* __restrict__ Qh, bf16* __restrict__ Ql,
    bf16* __restrict__ Kh, bf16* __restrict__ Kl,
    bf16* __restrict__ Vh, bf16* __restrict__ Vl,
    const bf16* __restrict__ P1_h, const bf16* __restrict__ P1_l,
    const bf16* __restrict__ QT1_h, const bf16* __restrict__ QT1_l,
    const unsigned char* __restrict__ fP1,
    bf16* __restrict__ P2_h, bf16* __restrict__ P2_l,
    bf16* __restrict__ QT2_h, bf16* __restrict__ QT2_l)
{
    const int z = blockIdx.z;
    if (z < 24) {
        const int kind = z >> 3, b = z & 7;
        const long long ao = (long long)b * S * Hd;
        const bf16 *ah, *al;
        bf16 *oh, *ol;
        if (kind == 0)      { ah = q_h;  al = q_l;  oh = Qh; ol = Ql; }
        else if (kind == 1) { ah = k_h;  al = k_l;  oh = Kh; ol = Kl; }
        else                { ah = hs_h; al = hs_l; oh = Vh; ol = Vl; }
        gemm_core<1, 2>(ah + ao, al + ao,
                        inw_h + (long long)kind * HH, inw_l + (long long)kind * HH,
                        in_b + kind * Hd, nullptr, oh + ao, ol + ao,
                        nullptr, nullptr, blockIdx.y * 128, blockIdx.x * 128);
    } else {
        chain_work(z - 24, P1_h, P1_l, QT1_h, QT1_l, fP1,
                   P2_h, P2_l, QT2_h, QT2_l, 4, 2);
    }
}

__global__ __launch_bounds__(256, 2) void k_l3(
    const bf16* __restrict__ ctx_h, const bf16* __restrict__ ctx_l,
    const bf16* __restrict__ ow_h, const bf16* __restrict__ ow_l,
    const float* __restrict__ out_b,
    bf16* __restrict__ al_h, bf16* __restrict__ al_l,
    const bf16* __restrict__ P2_h, const bf16* __restrict__ P2_l,
    const bf16* __restrict__ QT2_h, const bf16* __restrict__ QT2_l,
    const unsigned char* __restrict__ fP2,
    bf16* __restrict__ M_h, bf16* __restrict__ M_l,
    bf16* __restrict__ MT_h, bf16* __restrict__ MT_l)
{
    const int z = blockIdx.z;
    if (z < 8) {
        const long long ao = (long long)z * S * Hd;
        gemm_core<1, 2>(ctx_h + ao, ctx_l + ao, ow_h, ow_l, out_b, nullptr,
                        al_h + ao, al_l + ao, nullptr, nullptr,
                        blockIdx.y * 128, blockIdx.x * 128);
    } else {
        chain_work(z - 8, P2_h, P2_l, QT2_h, QT2_l, fP2,
                   M_h, M_l, MT_h, MT_l, 2, 1);
    }
}

template <int MODE, int WSEL>
__global__ __launch_bounds__(256, 2) void tc_gemm(
    const bf16* __restrict__ Ah, const bf16* __restrict__ Al, long long sAz,
    const bf16* __restrict__ Wh, const bf16* __restrict__ Wl,
    const float* __restrict__ bias, const int* __restrict__ lang,
    float* __restrict__ C, bf16* __restrict__ Ch, bf16* __restrict__ Cl,
    long long sCz)
{
    const int z = blockIdx.z;
    const bf16* wh = Wh;
    const bf16* wl = Wl;
    const float* bs = bias;
    if (WSEL) {
        const int lg = __ldg(&lang[z]);
        wh += (long long)lg * HH;
        wl += (long long)lg * HH;
        if (bias) bs += lg * Hd;
    }
    const long long ao = (long long)z * sAz;
    const long long co = (long long)z * sCz;
    gemm_core<MODE, 2>(Ah + ao, Al + ao, wh, wl, bs,
                       (MODE == 0) ? C + co : nullptr,
                       (MODE != 0) ? Ch + co : nullptr,
                       (MODE != 0) ? Cl + co : nullptr,
                       nullptr, nullptr,
                       blockIdx.y * 128, blockIdx.x * 128);
}

// ---------------------------------------------------------------------------
// Tensor-core flash attention (unchanged: 3-term)
// ---------------------------------------------------------------------------
constexpr int AT_CHUNK = 64 * 80;
constexpr int AT_TILE  = 2 * AT_CHUNK;
constexpr int ATT_SMEM = 6 * AT_TILE;

__global__ __launch_bounds__(256) void k_attn_tc(
    const bf16* __restrict__ Qg_h, const bf16* __restrict__ Qg_l,
    const bf16* __restrict__ Kg_h, const bf16* __restrict__ Kg_l,
    const bf16* __restrict__ Vg_h, const bf16* __restrict__ Vg_l,
    bf16* __restrict__ Oh, bf16* __restrict__ Ol)
{
    extern __shared__ char dsm[];
    __shared__ float smax[4][2][16];
    __shared__ float larr[2][64];

    const int qt = blockIdx.x, h = blockIdx.y, b = blockIdx.z;
    const int tid = threadIdx.x;
    const int wid = tid >> 5, lane = tid & 31;
    const int wm = wid & 3, wn = wid >> 2;
    const int g = lane >> 2, t2 = (lane & 3) * 2;
    const int r_off = ((lane >> 3) & 1) * 8 + (lane & 7);
    const int c_off = (lane >> 4) * 8;

    const uint32_t sQh = smem_u32(dsm);
    const uint32_t sQl = sQh + AT_TILE;
    const uint32_t sKh = sQh + 2 * AT_TILE;
    const uint32_t sKl = sQh + 3 * AT_TILE;
    const uint32_t sVh = sQh + 4 * AT_TILE;
    const uint32_t sVl = sQh + 5 * AT_TILE;
    unsigned short* vth16 = (unsigned short*)(dsm + 4 * AT_TILE);
    unsigned short* vtl16 = (unsigned short*)(dsm + 5 * AT_TILE);

    const long long qrow0 = (long long)(b * S + qt * 64);
    const int hoff = h * 64;

#pragma unroll
    for (int i = 0; i < 2; i++) {
        const int task = i * 256 + tid;
        const int row = task >> 3, rem = task & 7;
        const int chunk = rem >> 2, sub = rem & 3;
        const uint32_t sd = chunk * AT_CHUNK + row * 80 + sub * 16;
        const long long gsrc = (qrow0 + row) * Hd + hoff + chunk * 32 + sub * 8;
        cp16(sQh + sd, Qg_h + gsrc);
        cp16(sQl + sd, Qg_l + gsrc);
    }
    cp_commit();

    float m0v = -1e30f, m1v = -1e30f, l0v = 0.f, l1v = 0.f;
    float ctx[8][4];
#pragma unroll
    for (int t = 0; t < 8; t++)
#pragma unroll
        for (int e = 0; e < 4; e++) ctx[t][e] = 0.f;

    for (int kt = 0; kt < 12; kt++) {
        __syncthreads();
        const long long krow0 = (long long)(b * S + kt * 64);
#pragma unroll
        for (int i = 0; i < 2; i++) {
            const int task = i * 256 + tid;
            const int row = task >> 3, rem = task & 7;
            const int chunk = rem >> 2, sub = rem & 3;
            const uint32_t sd = chunk * AT_CHUNK + row * 80 + sub * 16;
            const long long gsrc = (krow0 + row) * Hd + hoff + chunk * 32 + sub * 8;
            cp16(sKh + sd, Kg_h + gsrc);
            cp16(sKl + sd, Kg_l + gsrc);
        }
        cp_commit();
#pragma unroll
        for (int i = 0; i < 8; i++) {
            const int task = i * 256 + tid;
            const int r = task >> 5;
            const int c2 = (task & 31) * 2;
            const long long gsrc = (krow0 + r) * Hd + hoff + c2;
            const uint32_t vh2 = *(const uint32_t*)(Vg_h + gsrc);
            const uint32_t vl2 = *(const uint32_t*)(Vg_l + gsrc);
            const int base = (r >> 5) * 2560 + (r & 31);
            vth16[base + c2 * 40]       = (unsigned short)(vh2 & 0xffff);
            vth16[base + (c2 + 1) * 40] = (unsigned short)(vh2 >> 16);
            vtl16[base + c2 * 40]       = (unsigned short)(vl2 & 0xffff);
            vtl16[base + (c2 + 1) * 40] = (unsigned short)(vl2 >> 16);
        }
        cp_wait<0>();
        __syncthreads();

        float sacc[4][4];
#pragma unroll
        for (int t = 0; t < 4; t++)
#pragma unroll
            for (int e = 0; e < 4; e++) sacc[t][e] = 0.f;

#pragma unroll
        for (int c = 0; c < 2; c++) {
#pragma unroll
            for (int kk2 = 0; kk2 < 2; kk2++) {
                const uint32_t koff = c * AT_CHUNK + kk2 * 32;
                uint32_t qa_h[4], qa_l[4];
                ldsm4(qa_h, sQh + koff + (wm * 16 + r_off) * 80 + c_off * 2);
                ldsm4(qa_l, sQl + koff + (wm * 16 + r_off) * 80 + c_off * 2);
#pragma unroll
                for (int u = 0; u < 2; u++) {
                    const uint32_t roff2 = koff + (wn * 32 + u * 16 + r_off) * 80 + c_off * 2;
                    uint32_t kb_h[4], kb_l[4];
                    ldsm4(kb_h, sKh + roff2);
                    ldsm4(kb_l, sKl + roff2);
                    mma_bf16(sacc[u * 2],     qa_h, kb_h[0], kb_h[2]);
                    mma_bf16(sacc[u * 2 + 1], qa_h, kb_h[1], kb_h[3]);
                    mma_bf16(sacc[u * 2],     qa_l, kb_h[0], kb_h[2]);
                    mma_bf16(sacc[u * 2 + 1], qa_l, kb_h[1], kb_h[3]);
                    mma_bf16(sacc[u * 2],     qa_h, kb_l[0], kb_l[2]);
                    mma_bf16(sacc[u * 2 + 1], qa_h, kb_l[1], kb_l[3]);
                }
            }
        }
#pragma unroll
        for (int t = 0; t < 4; t++)
#pragma unroll
            for (int e = 0; e < 4; e++) sacc[t][e] *= 0.125f;

        float rm0 = -1e30f, rm1 = -1e30f;
#pragma unroll
        for (int t = 0; t < 4; t++) {
            rm0 = fmaxf(rm0, fmaxf(sacc[t][0], sacc[t][1]));
            rm1 = fmaxf(rm1, fmaxf(sacc[t][2], sacc[t][3]));
        }
        rm0 = fmaxf(rm0, __shfl_xor_sync(0xffffffffu, rm0, 1));
        rm0 = fmaxf(rm0, __shfl_xor_sync(0xffffffffu, rm0, 2));
        rm1 = fmaxf(rm1, __shfl_xor_sync(0xffffffffu, rm1, 1));
        rm1 = fmaxf(rm1, __shfl_xor_sync(0xffffffffu, rm1, 2));
        if ((lane & 3) == 0) {
            smax[wm][wn][g]     = rm0;
            smax[wm][wn][g + 8] = rm1;
        }
        __syncthreads();
        rm0 = fmaxf(rm0, smax[wm][wn ^ 1][g]);
        rm1 = fmaxf(rm1, smax[wm][wn ^ 1][g + 8]);

        const float mn0 = fmaxf(m0v, rm0);
        const float mn1 = fmaxf(m1v, rm1);
        const float a0 = __expf(m0v - mn0);
        const float a1 = __expf(m1v - mn1);
        m0v = mn0; m1v = mn1;

        float rs0 = 0.f, rs1 = 0.f;
#pragma unroll
        for (int t = 0; t < 4; t++) {
            sacc[t][0] = __expf(sacc[t][0] - mn0);
            sacc[t][1] = __expf(sacc[t][1] - mn0);
            sacc[t][2] = __expf(sacc[t][2] - mn1);
            sacc[t][3] = __expf(sacc[t][3] - mn1);
            rs0 += sacc[t][0] + sacc[t][1];
            rs1 += sacc[t][2] + sacc[t][3];
        }
        rs0 += __shfl_xor_sync(0xffffffffu, rs0, 1);
        rs0 += __shfl_xor_sync(0xffffffffu, rs0, 2);
        rs1 += __shfl_xor_sync(0xffffffffu, rs1, 1);
        rs1 += __shfl_xor_sync(0xffffffffu, rs1, 2);
        l0v = l0v * a0 + rs0;
        l1v = l1v * a1 + rs1;
#pragma unroll
        for (int t = 0; t < 8; t++) {
            ctx[t][0] *= a0; ctx[t][1] *= a0;
            ctx[t][2] *= a1; ctx[t][3] *= a1;
        }

        uint32_t pah[2][4], pal[2][4];
#pragma unroll
        for (int kk2 = 0; kk2 < 2; kk2++) {
            const int e = 2 * kk2;
#pragma unroll
            for (int half = 0; half < 2; half++) {
                const int tt = e + half;
                float v0 = sacc[tt][0], v1 = sacc[tt][1];
                float v2 = sacc[tt][2], v3 = sacc[tt][3];
                bf16 h0 = __float2bfloat16(v0), h1 = __float2bfloat16(v1);
                bf16 h2 = __float2bfloat16(v2), h3 = __float2bfloat16(v3);
                pah[kk2][half * 2 + 0] = pack_bf(h0, h1);
                pah[kk2][half * 2 + 1] = pack_bf(h2, h3);
                pal[kk2][half * 2 + 0] =
                    pack_f2(v0 - __bfloat162float(h0), v1 - __bfloat162float(h1));
                pal[kk2][half * 2 + 1] =
                    pack_f2(v2 - __bfloat162float(h2), v3 - __bfloat162float(h3));
            }
        }

#pragma unroll
        for (int kk2 = 0; kk2 < 2; kk2++) {
            const uint32_t voff = wn * AT_CHUNK + kk2 * 32;
#pragma unroll
            for (int u = 0; u < 4; u++) {
                const uint32_t roff2 = voff + (u * 16 + r_off) * 80 + c_off * 2;
                uint32_t vb_h[4], vb_l[4];
                ldsm4(vb_h, sVh + roff2);
                ldsm4(vb_l, sVl + roff2);
                mma_bf16(ctx[u * 2],     pah[kk2], vb_h[0], vb_h[2]);
                mma_bf16(ctx[u * 2 + 1], pah[kk2], vb_h[1], vb_h[3]);
                mma_bf16(ctx[u * 2],     pal[kk2], vb_h[0], vb_h[2]);
                mma_bf16(ctx[u * 2 + 1], pal[kk2], vb_h[1], vb_h[3]);
                mma_bf16(ctx[u * 2],     pah[kk2], vb_l[0], vb_l[2]);
                mma_bf16(ctx[u * 2 + 1], pah[kk2], vb_l[1], vb_l[3]);
            }
        }
    }

    __syncthreads();
    float* csum = (float*)(dsm + 2 * AT_TILE);
    if (wn == 1) {
#pragma unroll
        for (int t = 0; t < 8; t++) {
            const int u = t >> 1, v = t & 1;
            const int colb = u * 16 + v * 8 + t2;
            csum[(wm * 16 + g) * 68 + colb]         = ctx[t][0];
            csum[(wm * 16 + g) * 68 + colb + 1]     = ctx[t][1];
            csum[(wm * 16 + g + 8) * 68 + colb]     = ctx[t][2];
            csum[(wm * 16 + g + 8) * 68 + colb + 1] = ctx[t][3];
        }
    }
    if ((lane & 3) == 0) {
        larr[wn][wm * 16 + g]     = l0v;
        larr[wn][wm * 16 + g + 8] = l1v;
    }
    __syncthreads();
    if (wn == 0) {
#pragma unroll
        for (int t = 0; t < 8; t++) {
            const int u = t >> 1, v = t & 1;
            const int colb = u * 16 + v * 8 + t2;
            csum[(wm * 16 + g) * 68 + colb]         += ctx[t][0];
            csum[(wm * 16 + g) * 68 + colb + 1]     += ctx[t][1];
            csum[(wm * 16 + g + 8) * 68 + colb]     += ctx[t][2];
            csum[(wm * 16 + g + 8) * 68 + colb + 1] += ctx[t][3];
        }
    }
    __syncthreads();
#pragma unroll
    for (int i = 0; i < 4; i++) {
        const int idx = i * 256 + tid;
        const int row = idx >> 4, c4 = (idx & 15) * 4;
        const float inv = 1.f / (larr[0][row] + larr[1][row]);
        float4 v = *(float4*)&csum[row * 68 + c4];
        v.x *= inv; v.y *= inv; v.z *= inv; v.w *= inv;
        bf16 h0 = __float2bfloat16(v.x), h1 = __float2bfloat16(v.y);
        bf16 h2 = __float2bfloat16(v.z), h3 = __float2bfloat16(v.w);
        bf16 l0 = __float2bfloat16(v.x - __bfloat162float(h0));
        bf16 l1 = __float2bfloat16(v.y - __bfloat162float(h1));
        bf16 l2 = __float2bfloat16(v.z - __bfloat162float(h2));
        bf16 l3 = __float2bfloat16(v.w - __bfloat162float(h3));
        const long long off = (qrow0 + row) * Hd + hoff + c4;
        *(uint2*)(Oh + off) = make_uint2(pack_bf(h0, h1), pack_bf(h2, h3));
        *(uint2*)(Ol + off) = make_uint2(pack_bf(l0, l1), pack_bf(l2, l3));
    }
}

// ---------------------------------------------------------------------------
// conversions / chain leaves / LN
// ---------------------------------------------------------------------------
__global__ __launch_bounds__(256) void k_conv(
    const float* __restrict__ src, bf16* __restrict__ dh,
    bf16* __restrict__ dl)
{
    const long long i4 = ((long long)blockIdx.x * 256 + threadIdx.x) * 4;
    float4 v = *(const float4*)(src + i4);
    bf16 h0 = __float2bfloat16(v.x), h1 = __float2bfloat16(v.y);
    bf16 h2 = __float2bfloat16(v.z), h3 = __float2bfloat16(v.w);
    bf16 l0 = __float2bfloat16(v.x - __bfloat162float(h0));
    bf16 l1 = __float2bfloat16(v.y - __bfloat162float(h1));
    bf16 l2 = __float2bfloat16(v.z - __bfloat162float(h2));
    bf16 l3 = __float2bfloat16(v.w - __bfloat162float(h3));
    *(uint2*)(dh + i4) = make_uint2(pack_bf(h0, h1), pack_bf(h2, h3));
    *(uint2*)(dl + i4) = make_uint2(pack_bf(l0, l1), pack_bf(l2, l3));
}

__global__ void k_flags(const int* __restrict__ lang,
                        unsigned char* fF, unsigned char* fP1, unsigned char* fP2)
{
    if (threadIdx.x == 0 && blockIdx.x == 0) {
        for (int a = 0; a < NL; a++) {
            for (int j = 0; j < 8; j++) fF[a * 8 + j] = (lang[j] == a) ? 1 : 0;
            for (int p = 0; p < 4; p++)
                fP1[a * 4 + p] = fF[a * 8 + 2 * p] & fF[a * 8 + 2 * p + 1];
            for (int p = 0; p < 2; p++)
                fP2[a * 2 + p] = fP1[a * 4 + 2 * p] & fP1[a * 4 + 2 * p + 1];
        }
    }
}

__device__ __forceinline__ void split_store4(
    bf16* dh, bf16* dl, long long off, float x, float y, float z, float w)
{
    bf16 h0 = __float2bfloat16(x), h1 = __float2bfloat16(y);
    bf16 h2 = __float2bfloat16(z), h3 = __float2bfloat16(w);
    bf16 l0 = __float2bfloat16(x - __bfloat162float(h0));
    bf16 l1 = __float2bfloat16(y - __bfloat162float(h1));
    bf16 l2 = __float2bfloat16(z - __bfloat162float(h2));
    bf16 l3 = __float2bfloat16(w - __bfloat162float(h3));
    *(uint2*)(dh + off) = make_uint2(pack_bf(h0, h1), pack_bf(h2, h3));
    *(uint2*)(dl + off) = make_uint2(pack_bf(l0, l1), pack_bf(l2, l3));
}

__global__ __launch_bounds__(256) void k_factors(
    const float* __restrict__ alignT, const int* __restrict__ lang,
    bf16* __restrict__ Fh, bf16* __restrict__ Fl,
    bf16* __restrict__ FTh, bf16* __restrict__ FTl)
{
    const int node = blockIdx.y;
    const int a = node >> 3, j = node & 7;
    const int c = __ldg(&lang[j]);
    const long long nb = (long long)node * HH;
    const long long i4 = ((long long)blockIdx.x * 256 + threadIdx.x) * 4;
    const int r = (int)(i4 / Hd), col = (int)(i4 % Hd);

    if (c == a) {
        float v0 = (col + 0 == r) ? 1.f : 0.f;
        float v1 = (col + 1 == r) ? 1.f : 0.f;
        float v2 = (col + 2 == r) ? 1.f : 0.f;
        float v3 = (col + 3 == r) ? 1.f : 0.f;
        split_store4(Fh,  Fl,  nb + i4, v0, v1, v2, v3);
        split_store4(FTh, FTl, nb + i4, v0, v1, v2, v3);
    } else {
        const float* sm = alignT + (long long)(a * NL + c) * HH;
        float4 v = *(const float4*)(sm + i4);
        split_store4(Fh, Fl, nb + i4, v.x, v.y, v.z, v.w);
        float t0 = sm[(long long)(col + 0) * Hd + r];
        float t1 = sm[(long long)(col + 1) * Hd + r];
        float t2 = sm[(long long)(col + 2) * Hd + r];
        float t3 = sm[(long long)(col + 3) * Hd + r];
        split_store4(FTh, FTl, nb + i4, t0, t1, t2, t3);
    }
}

__global__ __launch_bounds__(256) void k_ln(
    const float* __restrict__ X, const float* __restrict__ Rres,
    const float* __restrict__ gam, const float* __restrict__ bet,
    float* __restrict__ out)
{
    const int row = blockIdx.x;
    const long long base = (long long)row * Hd;
    const int tid = threadIdx.x;

    float v[3];
    float s = 0.f, s2 = 0.f;
#pragma unroll
    for (int u = 0; u < 3; u++) {
        const int idx = tid + u * 256;
        const float val = X[base + idx] + Rres[base + idx];
        v[u] = val; s += val; s2 += val * val;
    }
#pragma unroll
    for (int off = 16; off >= 1; off >>= 1) {
        s  += __shfl_xor_sync(0xffffffffu, s, off);
        s2 += __shfl_xor_sync(0xffffffffu, s2, off);
    }
    __shared__ float ss[8], ss2[8], mv[2];
    const int wid = tid >> 5, lane = tid & 31;
    if (lane == 0) { ss[wid] = s; ss2[wid] = s2; }
    __syncthreads();
    if (tid == 0) {
        float S_ = 0.f, S2_ = 0.f;
        for (int w = 0; w < 8; w++) { S_ += ss[w]; S2_ += ss2[w]; }
        const float mean = S_ * (1.f / 768.f);
        const float var  = S2_ * (1.f / 768.f) - mean * mean;
        mv[0] = mean;
        mv[1] = rsqrtf(var + 1e-5f);
    }
    __syncthreads();
    const float mean = mv[0], rstd = mv[1];
#pragma unroll
    for (int u = 0; u < 3; u++) {
        const int idx = tid + u * 256;
        out[base + idx] = (v[u] - mean) * rstd * gam[idx] + bet[idx];
    }
}

// ---------------------------------------------------------------------------
// kernel_launch (structure identical to R9)
// ---------------------------------------------------------------------------
#define SYM(v, s) cudaGetSymbolAddress((void**)&v, s)

extern "C" void kernel_launch(void* const* d_in, const int* in_sizes, int n_in,
                              void* d_out, int out_size)
{
    const float* hs      = (const float*)d_in[0];
    const int*   lang    = (const int*)  d_in[1];
    const float* Wq_lang = (const float*)d_in[3];
    const float* bq_lang = (const float*)d_in[4];
    const float* Wk_lang = (const float*)d_in[5];
    const float* bk_lang = (const float*)d_in[6];
    const float* in_w    = (const float*)d_in[7];
    const float* in_b    = (const float*)d_in[8];
    const float* out_w   = (const float*)d_in[9];
    const float* out_b   = (const float*)d_in[10];
    const float* alignT  = (const float*)d_in[11];
    const float* proj_w  = (const float*)d_in[12];
    const float* proj_b  = (const float*)d_in[13];
    const float* ln_g    = (const float*)d_in[14];
    const float* ln_b    = (const float*)d_in[15];
    float* out = (float*)d_out;

    float* obuf;
    SYM(obuf, g_o);

    bf16 *hs_h, *hs_l, *q_h, *q_l, *k_h, *k_l;
    bf16 *Qh, *Ql, *Kh, *Kl, *Vh, *Vl, *ctx_h, *ctx_l;
    bf16 *al_h, *al_l, *al2_h, *al2_l;
    SYM(hs_h, g_hs_h);   SYM(hs_l, g_hs_l);
    SYM(q_h, g_q_h);     SYM(q_l, g_q_l);
    SYM(k_h, g_k_h);     SYM(k_l, g_k_l);
    SYM(Qh, g_Qh);       SYM(Ql, g_Ql);
    SYM(Kh, g_Kh);       SYM(Kl, g_Kl);
    SYM(Vh, g_Vh);       SYM(Vl, g_Vl);
    SYM(ctx_h, g_ctx_h); SYM(ctx_l, g_ctx_l);
    SYM(al_h, g_al_h);   SYM(al_l, g_al_l);
    SYM(al2_h, g_al2_h); SYM(al2_l, g_al2_l);

    bf16 *Wq_h, *Wq_l, *Wk_h, *Wk_l, *inw_h, *inw_l, *ow_h, *ow_l, *pw_h, *pw_l;
    SYM(Wq_h, g_Wq_h);   SYM(Wq_l, g_Wq_l);
    SYM(Wk_h, g_Wk_h);   SYM(Wk_l, g_Wk_l);
    SYM(inw_h, g_inw_h); SYM(inw_l, g_inw_l);
    SYM(ow_h, g_ow_h);   SYM(ow_l, g_ow_l);
    SYM(pw_h, g_pw_h);   SYM(pw_l, g_pw_l);

    bf16 *F_h, *F_l, *FT_h, *FT_l, *P1_h, *P1_l, *QT1_h, *QT1_l;
    bf16 *P2_h, *P2_l, *QT2_h, *QT2_l, *M_h, *M_l, *MT_h, *MT_l;
    SYM(F_h, g_F_h);   SYM(F_l, g_F_l);   SYM(FT_h, g_FT_h); SYM(FT_l, g_FT_l);
    SYM(P1_h, g_P1_h); SYM(P1_l, g_P1_l); SYM(QT1_h, g_QT1_h); SYM(QT1_l, g_QT1_l);
    SYM(P2_h, g_P2_h); SYM(P2_l, g_P2_l); SYM(QT2_h, g_QT2_h); SYM(QT2_l, g_QT2_l);
    SYM(M_h, g_M_h);   SYM(M_l, g_M_l);   SYM(MT_h, g_MT_h); SYM(MT_l, g_MT_l);

    unsigned char *fF, *fP1, *fP2;
    SYM(fF, g_fF); SYM(fP1, g_fP1); SYM(fP2, g_fP2);

    cudaFuncSetAttribute(k_l1, cudaFuncAttributeMaxDynamicSharedMemorySize, GEMM_SMEM);
    cudaFuncSetAttribute(k_l2, cudaFuncAttributeMaxDynamicSharedMemorySize, GEMM_SMEM);
    cudaFuncSetAttribute(k_l3, cudaFuncAttributeMaxDynamicSharedMemorySize, GEMM_SMEM);
    cudaFuncSetAttribute(tc_gemm<0, 0>, cudaFuncAttributeMaxDynamicSharedMemorySize, GEMM_SMEM);
    cudaFuncSetAttribute(tc_gemm<1, 1>, cudaFuncAttributeMaxDynamicSharedMemorySize, GEMM_SMEM);
    cudaFuncSetAttribute(k_attn_tc, cudaFuncAttributeMaxDynamicSharedMemorySize, ATT_SMEM);

    const long long sBH = (long long)S * Hd;
    const dim3 thr(256);

    // conversions for L1
    k_conv<<<BS * Hd / 1024, thr>>>(hs, hs_h, hs_l);
    k_conv<<<(int)(NL * HH / 1024), thr>>>(Wq_lang, Wq_h, Wq_l);
    k_conv<<<(int)(NL * HH / 1024), thr>>>(Wk_lang, Wk_h, Wk_l);
    // chain leaves
    k_flags<<<1, 32>>>(lang, fF, fP1, fP2);
    k_factors<<<dim3((int)(HH / 1024), NL * 8), thr>>>(alignT, lang, F_h, F_l, FT_h, FT_l);

    // L1 = q/k lang projections + chain level 1
    k_l1<<<dim3(6, 6, 36), thr, GEMM_SMEM>>>(
        hs_h, hs_l, Wq_h, Wq_l, Wk_h, Wk_l, bq_lang, bk_lang, lang,
        q_h, q_l, k_h, k_l,
        F_h, F_l, FT_h, FT_l, fF, P1_h, P1_l, QT1_h, QT1_l);

    // remaining conversions
    k_conv<<<(int)(3 * HH / 1024), thr>>>(in_w, inw_h, inw_l);
    k_conv<<<(int)(HH / 1024), thr>>>(out_w, ow_h, ow_l);
    k_conv<<<(int)(HH / 1024), thr>>>(proj_w, pw_h, pw_l);

    // L2 = QKV + chain level 2
    k_l2<<<dim3(6, 6, 34), thr, GEMM_SMEM>>>(
        q_h, q_l, k_h, k_l, hs_h, hs_l, inw_h, inw_l, in_b,
        Qh, Ql, Kh, Kl, Vh, Vl,
        P1_h, P1_l, QT1_h, QT1_l, fP1, P2_h, P2_l, QT2_h, QT2_l);

    // attention
    k_attn_tc<<<dim3(S / 64, NH, Bsz), thr, ATT_SMEM>>>(
        Qh, Ql, Kh, Kl, Vh, Vl, ctx_h, ctx_l);

    // L3 = out_proj + chain level 3
    k_l3<<<dim3(6, 6, 13), thr, GEMM_SMEM>>>(
        ctx_h, ctx_l, ow_h, ow_l, out_b, al_h, al_l,
        P2_h, P2_l, QT2_h, QT2_l, fP2, M_h, M_l, MT_h, MT_l);

    // aligned @ M[lang[b]]
    tc_gemm<1, 1><<<dim3(6, 6, Bsz), thr, GEMM_SMEM>>>(
        al_h, al_l, sBH, MT_h, MT_l, nullptr, lang, nullptr, al2_h, al2_l, sBH);

    // final proj (fp32 out)
    tc_gemm<0, 0><<<dim3(6, 48, 1), thr, GEMM_SMEM>>>(
        al2_h, al2_l, 0, pw_h, pw_l, proj_b, nullptr, obuf, nullptr, nullptr, 0);

    // residual + LayerNorm
    k_ln<<<BS, thr>>>(obuf, hs, ln_g, ln_b, out);
}

// round 11
// speedup vs baseline: 4.1767x; 1.5549x over previous
#include <cuda_runtime.h>
#include <cuda_bf16.h>
#include <cstdint>

// ---------------------------------------------------------------------------
// Problem constants
// ---------------------------------------------------------------------------
constexpr int Bsz = 8;
constexpr int S   = 768;
constexpr int Hd  = 768;
constexpr int NH  = 12;
constexpr int NL  = 5;
constexpr int BS  = Bsz * S;
constexpr long long HH = (long long)Hd * Hd;

typedef __nv_bfloat16 bf16;

// ---------------------------------------------------------------------------
// Scratch (hi-only)
// ---------------------------------------------------------------------------
__device__ float g_o  [BS * Hd];

__device__ bf16 g_hs_h [BS * Hd];
__device__ bf16 g_q_h  [BS * Hd];
__device__ bf16 g_k_h  [BS * Hd];
__device__ bf16 g_Qh   [BS * Hd];
__device__ bf16 g_Kh   [BS * Hd];
__device__ bf16 g_Vh   [BS * Hd];
__device__ bf16 g_ctx_h[BS * Hd];
__device__ bf16 g_al_h [BS * Hd];
__device__ bf16 g_al2_h[BS * Hd];

__device__ bf16 g_Wq_h [NL * Hd * Hd];
__device__ bf16 g_Wk_h [NL * Hd * Hd];
__device__ bf16 g_inw_h[3 * Hd * Hd];
__device__ bf16 g_ow_h [Hd * Hd];
__device__ bf16 g_pw_h [Hd * Hd];

__device__ bf16 g_F_h [NL * 8 * Hd * Hd];
__device__ bf16 g_FT_h[NL * 8 * Hd * Hd];
__device__ bf16 g_P1_h[NL * 4 * Hd * Hd];
__device__ bf16 g_QT1_h[NL * 4 * Hd * Hd];
__device__ bf16 g_P2_h[NL * 2 * Hd * Hd];
__device__ bf16 g_QT2_h[NL * 2 * Hd * Hd];
__device__ bf16 g_M_h [NL * Hd * Hd];
__device__ bf16 g_MT_h[NL * Hd * Hd];

__device__ unsigned char g_fF [NL * 8];
__device__ unsigned char g_fP1[NL * 4];
__device__ unsigned char g_fP2[NL * 2];

// ---------------------------------------------------------------------------
// PTX helpers
// ---------------------------------------------------------------------------
__device__ __forceinline__ uint32_t smem_u32(const void* p) {
    return (uint32_t)__cvta_generic_to_shared(p);
}
__device__ __forceinline__ void cp16(uint32_t d, const void* s) {
    asm volatile("cp.async.cg.shared.global [%0], [%1], 16;"
                 :: "r"(d), "l"(s) : "memory");
}
__device__ __forceinline__ void cp_commit() {
    asm volatile("cp.async.commit_group;" ::: "memory");
}
template <int N>
__device__ __forceinline__ void cp_wait() {
    asm volatile("cp.async.wait_group %0;" :: "n"(N) : "memory");
}
__device__ __forceinline__ void ldsm4(uint32_t* r, uint32_t addr) {
    asm volatile("ldmatrix.sync.aligned.m8n8.x4.shared.b16 {%0,%1,%2,%3}, [%4];"
                 : "=r"(r[0]), "=r"(r[1]), "=r"(r[2]), "=r"(r[3]) : "r"(addr));
}
__device__ __forceinline__ void mma_bf16(float* d, const uint32_t* a,
                                         uint32_t b0, uint32_t b1) {
    asm volatile(
        "mma.sync.aligned.m16n8k16.row.col.f32.bf16.bf16.f32 "
        "{%0,%1,%2,%3}, {%4,%5,%6,%7}, {%8,%9}, {%0,%1,%2,%3};"
        : "+f"(d[0]), "+f"(d[1]), "+f"(d[2]), "+f"(d[3])
        : "r"(a[0]), "r"(a[1]), "r"(a[2]), "r"(a[3]), "r"(b0), "r"(b1));
}
__device__ __forceinline__ uint32_t pack_bf(bf16 a, bf16 b) {
    return (uint32_t)__bfloat16_as_ushort(a) |
           ((uint32_t)__bfloat16_as_ushort(b) << 16);
}
__device__ __forceinline__ uint32_t pack_f2(float a, float b) {
    return pack_bf(__float2bfloat16(a), __float2bfloat16(b));
}

// ---------------------------------------------------------------------------
// GEMM: 128x128 tile, BLK_K=32, 8 warps, 2-stage pipeline, hi-only operands.
// ---------------------------------------------------------------------------
constexpr int SKP     = 40;
constexpr int TILE_B  = 128 * SKP * 2;       // 10240 B
constexpr int STAGE_B = 2 * TILE_B;          // 20480 B (A, W)
constexpr int GEMM_SMEM = 2 * STAGE_B;       // 40960 B

__device__ __forceinline__ void gemm_issue(
    const bf16* __restrict__ base, int lw, uint32_t sdst0, int kc)
{
    const bf16* g0 = base + kc * 32;
#pragma unroll
    for (int i = 0; i < 4; i++) {
        const int chunk = i * 128 + lw;
        const int row = chunk >> 2, cs = chunk & 3;
        cp16(sdst0 + row * (SKP * 2) + cs * 16,
             g0 + (long long)row * Hd + cs * 8);
    }
}

// MODE 0: fp32 out (+bias). MODE 1: bf16 out (+bias if non-null).
// MODE 2: bf16 out + transposed bf16 out (no bias).
template <int MODE>
__device__ void gemm_core(
    const bf16* __restrict__ A, const bf16* __restrict__ W,
    const float* __restrict__ bias,
    float* __restrict__ C, bf16* __restrict__ Ch, bf16* __restrict__ Th,
    int m0, int n0)
{
    extern __shared__ char dsm[];
    const int tid = threadIdx.x;
    const int wid = tid >> 5, lane = tid & 31;
    const int m_off = (wid & 3) * 32;
    const int n_off = (wid >> 2) * 64;
    const uint32_t sbase = smem_u32(dsm);

    const int ltile = tid >> 7;          // 0 = A, 1 = W
    const int lw = tid & 127;
    const bf16* gbase = (ltile == 0) ? A + (long long)m0 * Hd
                                     : W + (long long)n0 * Hd;
    const uint32_t sdst_tile = ltile * TILE_B;

    gemm_issue(gbase, lw, sbase + sdst_tile, 0);             cp_commit();
    gemm_issue(gbase, lw, sbase + STAGE_B + sdst_tile, 1);   cp_commit();

    float acc[2][8][4];
#pragma unroll
    for (int mi = 0; mi < 2; mi++)
#pragma unroll
        for (int j = 0; j < 8; j++)
#pragma unroll
            for (int e = 0; e < 4; e++) acc[mi][j][e] = 0.f;

    const int r_off = ((lane >> 3) & 1) * 8 + (lane & 7);
    const int c_off = (lane >> 4) * 8;

    for (int kc = 0; kc < 24; kc++) {
        cp_wait<1>();
        __syncthreads();
        const uint32_t sb = sbase + (kc & 1) * STAGE_B;
        const uint32_t aA = sb + (m_off + r_off) * (SKP * 2) + c_off * 2;
        const uint32_t aW = sb + TILE_B + (n_off + r_off) * (SKP * 2) + c_off * 2;

#pragma unroll
        for (int kk = 0; kk < 2; kk++) {
            uint32_t ah[2][4];
#pragma unroll
            for (int t = 0; t < 2; t++)
                ldsm4(ah[t], aA + t * 16 * (SKP * 2) + kk * 32);
#pragma unroll
            for (int u = 0; u < 4; u++) {
                uint32_t bh[4];
                ldsm4(bh, aW + u * 16 * (SKP * 2) + kk * 32);
#pragma unroll
                for (int mi = 0; mi < 2; mi++) {
                    mma_bf16(acc[mi][2 * u],     ah[mi], bh[0], bh[2]);
                    mma_bf16(acc[mi][2 * u + 1], ah[mi], bh[1], bh[3]);
                }
            }
        }
        __syncthreads();
        if (kc + 2 < 24)
            gemm_issue(gbase, lw, sbase + (kc & 1) * STAGE_B + sdst_tile, kc + 2);
        cp_commit();
    }

    // stage accumulators through SMEM (f32 [128][132]); needs 67584 B > 40960,
    // so reuse dynamic smem only if sized: bump GEMM_SMEM via epilogue region.
    float* sf = (float*)dsm;
    const int g = lane >> 2, t2 = (lane & 3) * 2;
#pragma unroll
    for (int mi = 0; mi < 2; mi++)
#pragma unroll
        for (int j = 0; j < 8; j++) {
            const int r = m_off + mi * 16 + g;
            const int c = n_off + j * 8 + t2;
            sf[r * 132 + c]           = acc[mi][j][0];
            sf[r * 132 + c + 1]       = acc[mi][j][1];
            sf[(r + 8) * 132 + c]     = acc[mi][j][2];
            sf[(r + 8) * 132 + c + 1] = acc[mi][j][3];
        }
    __syncthreads();

    if (MODE == 0) {
#pragma unroll 4
        for (int i = 0; i < 16; i++) {
            const int task = i * 256 + tid;
            const int row = task >> 5, c4 = (task & 31) * 4;
            float4 v = *(float4*)&sf[row * 132 + c4];
            v.x += bias[n0 + c4 + 0];
            v.y += bias[n0 + c4 + 1];
            v.z += bias[n0 + c4 + 2];
            v.w += bias[n0 + c4 + 3];
            *(float4*)(C + (long long)(m0 + row) * Hd + n0 + c4) = v;
        }
    } else {
#pragma unroll 4
        for (int i = 0; i < 16; i++) {
            const int task = i * 256 + tid;
            const int row = task >> 5, c4 = (task & 31) * 4;
            float4 v = *(float4*)&sf[row * 132 + c4];
            if (MODE == 1 && bias) {
                v.x += bias[n0 + c4 + 0];
                v.y += bias[n0 + c4 + 1];
                v.z += bias[n0 + c4 + 2];
                v.w += bias[n0 + c4 + 3];
            }
            *(uint2*)(Ch + (long long)(m0 + row) * Hd + n0 + c4) =
                make_uint2(pack_f2(v.x, v.y), pack_f2(v.z, v.w));
        }
        if (MODE == 2) {
            const int c = tid & 127;
            const int half = tid >> 7;
#pragma unroll 4
            for (int i = 0; i < 16; i++) {
                const int r4 = half * 64 + i * 4;
                float v0 = sf[(r4 + 0) * 132 + c];
                float v1 = sf[(r4 + 1) * 132 + c];
                float v2 = sf[(r4 + 2) * 132 + c];
                float v3 = sf[(r4 + 3) * 132 + c];
                *(uint2*)(Th + (long long)(n0 + c) * Hd + m0 + r4) =
                    make_uint2(pack_f2(v0, v1), pack_f2(v2, v3));
            }
        }
    }
}

// epilogue needs 128*132*4 = 67584 B of smem; allocate the max of both uses.
constexpr int GEMM_SMEM_FULL = 128 * 132 * 4;   // 67584 > 40960

// ---------------------------------------------------------------------------
// Chain product block
// ---------------------------------------------------------------------------
__device__ void chain_work(
    int zz,
    const bf16* __restrict__ sN_h, const bf16* __restrict__ sT_h,
    const unsigned char* __restrict__ fs,
    bf16* __restrict__ dN_h, bf16* __restrict__ dT_h,
    int spa, int dpa)
{
    const int a = zz / dpa, p = zz - a * dpa;
    const int li = a * spa + 2 * p;
    const unsigned char f1 = fs[li], f2 = fs[li + 1];
    const long long zo = (long long)zz * HH;
    const int m0 = blockIdx.y * 128, n0 = blockIdx.x * 128;
    const int tid = threadIdx.x;

    if (f1 & f2) {
#pragma unroll 4
        for (int i = 0; i < 16; i++) {
            const int task = i * 256 + tid;
            const int row = task >> 5, c4 = (task & 31) * 4;
            const int gr = m0 + row, gc = n0 + c4;
            float v0 = (gc + 0 == gr) ? 1.f : 0.f;
            float v1 = (gc + 1 == gr) ? 1.f : 0.f;
            float v2 = (gc + 2 == gr) ? 1.f : 0.f;
            float v3 = (gc + 3 == gr) ? 1.f : 0.f;
            const long long off = zo + (long long)gr * Hd + gc;
            uint2 hv = make_uint2(pack_f2(v0, v1), pack_f2(v2, v3));
            *(uint2*)(dN_h + off) = hv;
            *(uint2*)(dT_h + off) = hv;
        }
        return;
    }
    if (f1 | f2) {
        const long long so = (long long)(f1 ? li + 1 : li) * HH;
#pragma unroll 4
        for (int i = 0; i < 8; i++) {
            const int idx = i * 256 + tid;
            const int row = idx >> 4, c8 = (idx & 15) * 8;
            const long long doff = zo + (long long)(m0 + row) * Hd + n0 + c8;
            const long long soff = so + (long long)(m0 + row) * Hd + n0 + c8;
            *(uint4*)(dN_h + doff) = *(const uint4*)(sN_h + soff);
            *(uint4*)(dT_h + doff) = *(const uint4*)(sT_h + soff);
        }
        return;
    }
    gemm_core<2>(sN_h + (long long)li * HH, sT_h + (long long)(li + 1) * HH,
                 nullptr, nullptr, dN_h + zo, dT_h + zo, m0, n0);
}

// ---------------------------------------------------------------------------
// Merged launches
// ---------------------------------------------------------------------------
__global__ __launch_bounds__(256, 2) void k_l1(
    const bf16* __restrict__ hs_h,
    const bf16* __restrict__ Wq_h, const bf16* __restrict__ Wk_h,
    const float* __restrict__ bq, const float* __restrict__ bk,
    const int* __restrict__ lang,
    bf16* __restrict__ q_h, bf16* __restrict__ k_h,
    const bf16* __restrict__ F_h, const bf16* __restrict__ FT_h,
    const unsigned char* __restrict__ fF,
    bf16* __restrict__ P1_h, bf16* __restrict__ QT1_h)
{
    const int z = blockIdx.z;
    if (z < 16) {
        const int fam = z >> 3, b = z & 7;
        const int lg = __ldg(&lang[b]);
        const long long ao = (long long)b * S * Hd;
        const bf16* wh = (fam ? Wk_h : Wq_h) + (long long)lg * HH;
        const float* bs = (fam ? bk : bq) + lg * Hd;
        bf16* oh = (fam ? k_h : q_h) + ao;
        gemm_core<1>(hs_h + ao, wh, bs, nullptr, oh, nullptr,
                     blockIdx.y * 128, blockIdx.x * 128);
    } else {
        chain_work(z - 16, F_h, FT_h, fF, P1_h, QT1_h, 8, 4);
    }
}

__global__ __launch_bounds__(256, 2) void k_l2(
    const bf16* __restrict__ q_h, const bf16* __restrict__ k_h,
    const bf16* __restrict__ hs_h,
    const bf16* __restrict__ inw_h, const float* __restrict__ in_b,
    bf16* __restrict__ Qh, bf16* __restrict__ Kh, bf16* __restrict__ Vh,
    const bf16* __restrict__ P1_h, const bf16* __restrict__ QT1_h,
    const unsigned char* __restrict__ fP1,
    bf16* __restrict__ P2_h, bf16* __restrict__ QT2_h)
{
    const int z = blockIdx.z;
    if (z < 24) {
        const int kind = z >> 3, b = z & 7;
        const long long ao = (long long)b * S * Hd;
        const bf16* ah;
        bf16* oh;
        if (kind == 0)      { ah = q_h;  oh = Qh; }
        else if (kind == 1) { ah = k_h;  oh = Kh; }
        else                { ah = hs_h; oh = Vh; }
        gemm_core<1>(ah + ao, inw_h + (long long)kind * HH, in_b + kind * Hd,
                     nullptr, oh + ao, nullptr,
                     blockIdx.y * 128, blockIdx.x * 128);
    } else {
        chain_work(z - 24, P1_h, QT1_h, fP1, P2_h, QT2_h, 4, 2);
    }
}

__global__ __launch_bounds__(256, 2) void k_l3(
    const bf16* __restrict__ ctx_h,
    const bf16* __restrict__ ow_h, const float* __restrict__ out_b,
    bf16* __restrict__ al_h,
    const bf16* __restrict__ P2_h, const bf16* __restrict__ QT2_h,
    const unsigned char* __restrict__ fP2,
    bf16* __restrict__ M_h, bf16* __restrict__ MT_h)
{
    const int z = blockIdx.z;
    if (z < 8) {
        const long long ao = (long long)z * S * Hd;
        gemm_core<1>(ctx_h + ao, ow_h, out_b, nullptr, al_h + ao, nullptr,
                     blockIdx.y * 128, blockIdx.x * 128);
    } else {
        chain_work(z - 8, P2_h, QT2_h, fP2, M_h, MT_h, 2, 1);
    }
}

template <int MODE, int WSEL>
__global__ __launch_bounds__(256, 2) void tc_gemm(
    const bf16* __restrict__ A, long long sAz,
    const bf16* __restrict__ W,
    const float* __restrict__ bias, const int* __restrict__ lang,
    float* __restrict__ C, bf16* __restrict__ Ch, long long sCz)
{
    const int z = blockIdx.z;
    const bf16* wh = W;
    const float* bs = bias;
    if (WSEL) {
        const int lg = __ldg(&lang[z]);
        wh += (long long)lg * HH;
        if (bias) bs += lg * Hd;
    }
    const long long ao = (long long)z * sAz;
    const long long co = (long long)z * sCz;
    gemm_core<MODE>(A + ao, wh, bs,
                    (MODE == 0) ? C + co : nullptr,
                    (MODE != 0) ? Ch + co : nullptr,
                    nullptr, blockIdx.y * 128, blockIdx.x * 128);
}

// ---------------------------------------------------------------------------
// Tensor-core flash attention, hi-only (1-term QK^T and PV).
// ---------------------------------------------------------------------------
constexpr int AT_CHUNK = 64 * 80;
constexpr int AT_TILE  = 2 * AT_CHUNK;       // 10240 B
// Q, K, VT tiles + csum(64*68*4=17408 aliased over K..VT region)
constexpr int ATT_SMEM = 3 * AT_TILE;        // 30720 B

__global__ __launch_bounds__(256) void k_attn_tc(
    const bf16* __restrict__ Qg, const bf16* __restrict__ Kg,
    const bf16* __restrict__ Vg, bf16* __restrict__ Oh)
{
    extern __shared__ char dsm[];
    __shared__ float smax[4][2][16];
    __shared__ float larr[2][64];

    const int qt = blockIdx.x, h = blockIdx.y, b = blockIdx.z;
    const int tid = threadIdx.x;
    const int wid = tid >> 5, lane = tid & 31;
    const int wm = wid & 3, wn = wid >> 2;
    const int g = lane >> 2, t2 = (lane & 3) * 2;
    const int r_off = ((lane >> 3) & 1) * 8 + (lane & 7);
    const int c_off = (lane >> 4) * 8;

    const uint32_t sQ = smem_u32(dsm);
    const uint32_t sK = sQ + AT_TILE;
    const uint32_t sV = sQ + 2 * AT_TILE;
    unsigned short* vt16 = (unsigned short*)(dsm + 2 * AT_TILE);

    const long long qrow0 = (long long)(b * S + qt * 64);
    const int hoff = h * 64;

    // load Q (512 cp16 tasks)
#pragma unroll
    for (int i = 0; i < 2; i++) {
        const int task = i * 256 + tid;
        const int row = task >> 3, rem = task & 7;
        const int chunk = rem >> 2, sub = rem & 3;
        cp16(sQ + chunk * AT_CHUNK + row * 80 + sub * 16,
             Qg + (qrow0 + row) * Hd + hoff + chunk * 32 + sub * 8);
    }
    cp_commit();

    float m0v = -1e30f, m1v = -1e30f, l0v = 0.f, l1v = 0.f;
    float ctx[8][4];
#pragma unroll
    for (int t = 0; t < 8; t++)
#pragma unroll
        for (int e = 0; e < 4; e++) ctx[t][e] = 0.f;

    for (int kt = 0; kt < 12; kt++) {
        __syncthreads();
        const long long krow0 = (long long)(b * S + kt * 64);
#pragma unroll
        for (int i = 0; i < 2; i++) {
            const int task = i * 256 + tid;
            const int row = task >> 3, rem = task & 7;
            const int chunk = rem >> 2, sub = rem & 3;
            cp16(sK + chunk * AT_CHUNK + row * 80 + sub * 16,
                 Kg + (krow0 + row) * Hd + hoff + chunk * 32 + sub * 8);
        }
        cp_commit();
        // V transposed into smem (scalar, hi only)
#pragma unroll
        for (int i = 0; i < 8; i++) {
            const int task = i * 256 + tid;
            const int r = task >> 5;
            const int c2 = (task & 31) * 2;
            const uint32_t v2 = *(const uint32_t*)(Vg + (krow0 + r) * Hd + hoff + c2);
            const int base = (r >> 5) * 2560 + (r & 31);
            vt16[base + c2 * 40]       = (unsigned short)(v2 & 0xffff);
            vt16[base + (c2 + 1) * 40] = (unsigned short)(v2 >> 16);
        }
        cp_wait<0>();
        __syncthreads();

        // QK^T (hi only)
        float sacc[4][4];
#pragma unroll
        for (int t = 0; t < 4; t++)
#pragma unroll
            for (int e = 0; e < 4; e++) sacc[t][e] = 0.f;

#pragma unroll
        for (int c = 0; c < 2; c++) {
#pragma unroll
            for (int kk2 = 0; kk2 < 2; kk2++) {
                const uint32_t koff = c * AT_CHUNK + kk2 * 32;
                uint32_t qa[4];
                ldsm4(qa, sQ + koff + (wm * 16 + r_off) * 80 + c_off * 2);
#pragma unroll
                for (int u = 0; u < 2; u++) {
                    uint32_t kb[4];
                    ldsm4(kb, sK + koff + (wn * 32 + u * 16 + r_off) * 80 + c_off * 2);
                    mma_bf16(sacc[u * 2],     qa, kb[0], kb[2]);
                    mma_bf16(sacc[u * 2 + 1], qa, kb[1], kb[3]);
                }
            }
        }
#pragma unroll
        for (int t = 0; t < 4; t++)
#pragma unroll
            for (int e = 0; e < 4; e++) sacc[t][e] *= 0.125f;

        // softmax (fp32)
        float rm0 = -1e30f, rm1 = -1e30f;
#pragma unroll
        for (int t = 0; t < 4; t++) {
            rm0 = fmaxf(rm0, fmaxf(sacc[t][0], sacc[t][1]));
            rm1 = fmaxf(rm1, fmaxf(sacc[t][2], sacc[t][3]));
        }
        rm0 = fmaxf(rm0, __shfl_xor_sync(0xffffffffu, rm0, 1));
        rm0 = fmaxf(rm0, __shfl_xor_sync(0xffffffffu, rm0, 2));
        rm1 = fmaxf(rm1, __shfl_xor_sync(0xffffffffu, rm1, 1));
        rm1 = fmaxf(rm1, __shfl_xor_sync(0xffffffffu, rm1, 2));
        if ((lane & 3) == 0) {
            smax[wm][wn][g]     = rm0;
            smax[wm][wn][g + 8] = rm1;
        }
        __syncthreads();
        rm0 = fmaxf(rm0, smax[wm][wn ^ 1][g]);
        rm1 = fmaxf(rm1, smax[wm][wn ^ 1][g + 8]);

        const float mn0 = fmaxf(m0v, rm0);
        const float mn1 = fmaxf(m1v, rm1);
        const float a0 = __expf(m0v - mn0);
        const float a1 = __expf(m1v - mn1);
        m0v = mn0; m1v = mn1;

        float rs0 = 0.f, rs1 = 0.f;
#pragma unroll
        for (int t = 0; t < 4; t++) {
            sacc[t][0] = __expf(sacc[t][0] - mn0);
            sacc[t][1] = __expf(sacc[t][1] - mn0);
            sacc[t][2] = __expf(sacc[t][2] - mn1);
            sacc[t][3] = __expf(sacc[t][3] - mn1);
            rs0 += sacc[t][0] + sacc[t][1];
            rs1 += sacc[t][2] + sacc[t][3];
        }
        rs0 += __shfl_xor_sync(0xffffffffu, rs0, 1);
        rs0 += __shfl_xor_sync(0xffffffffu, rs0, 2);
        rs1 += __shfl_xor_sync(0xffffffffu, rs1, 1);
        rs1 += __shfl_xor_sync(0xffffffffu, rs1, 2);
        l0v = l0v * a0 + rs0;
        l1v = l1v * a1 + rs1;
#pragma unroll
        for (int t = 0; t < 8; t++) {
            ctx[t][0] *= a0; ctx[t][1] *= a0;
            ctx[t][2] *= a1; ctx[t][3] *= a1;
        }

        // pack P (hi only)
        uint32_t pah[2][4];
#pragma unroll
        for (int kk2 = 0; kk2 < 2; kk2++) {
#pragma unroll
            for (int half = 0; half < 2; half++) {
                const int tt = 2 * kk2 + half;
                pah[kk2][half * 2 + 0] = pack_f2(sacc[tt][0], sacc[tt][1]);
                pah[kk2][half * 2 + 1] = pack_f2(sacc[tt][2], sacc[tt][3]);
            }
        }

        // PV (hi only)
#pragma unroll
        for (int kk2 = 0; kk2 < 2; kk2++) {
            const uint32_t voff = wn * AT_CHUNK + kk2 * 32;
#pragma unroll
            for (int u = 0; u < 4; u++) {
                uint32_t vb[4];
                ldsm4(vb, sV + voff + (u * 16 + r_off) * 80 + c_off * 2);
                mma_bf16(ctx[u * 2],     pah[kk2], vb[0], vb[2]);
                mma_bf16(ctx[u * 2 + 1], pah[kk2], vb[1], vb[3]);
            }
        }
    }

    // merge kv-half partials; csum aliases K..VT region
    __syncthreads();
    float* csum = (float*)(dsm + AT_TILE);
    if (wn == 1) {
#pragma unroll
        for (int t = 0; t < 8; t++) {
            const int u = t >> 1, v = t & 1;
            const int colb = u * 16 + v * 8 + t2;
            csum[(wm * 16 + g) * 68 + colb]         = ctx[t][0];
            csum[(wm * 16 + g) * 68 + colb + 1]     = ctx[t][1];
            csum[(wm * 16 + g + 8) * 68 + colb]     = ctx[t][2];
            csum[(wm * 16 + g + 8) * 68 + colb + 1] = ctx[t][3];
        }
    }
    if ((lane & 3) == 0) {
        larr[wn][wm * 16 + g]     = l0v;
        larr[wn][wm * 16 + g + 8] = l1v;
    }
    __syncthreads();
    if (wn == 0) {
#pragma unroll
        for (int t = 0; t < 8; t++) {
            const int u = t >> 1, v = t & 1;
            const int colb = u * 16 + v * 8 + t2;
            csum[(wm * 16 + g) * 68 + colb]         += ctx[t][0];
            csum[(wm * 16 + g) * 68 + colb + 1]     += ctx[t][1];
            csum[(wm * 16 + g + 8) * 68 + colb]     += ctx[t][2];
            csum[(wm * 16 + g + 8) * 68 + colb + 1] += ctx[t][3];
        }
    }
    __syncthreads();
#pragma unroll
    for (int i = 0; i < 4; i++) {
        const int idx = i * 256 + tid;
        const int row = idx >> 4, c4 = (idx & 15) * 4;
        const float inv = 1.f / (larr[0][row] + larr[1][row]);
        float4 v = *(float4*)&csum[row * 68 + c4];
        *(uint2*)(Oh + (qrow0 + row) * Hd + hoff + c4) =
            make_uint2(pack_f2(v.x * inv, v.y * inv),
                       pack_f2(v.z * inv, v.w * inv));
    }
}

// ---------------------------------------------------------------------------
// conversions / chain leaves / LN
// ---------------------------------------------------------------------------
__global__ __launch_bounds__(256) void k_conv(
    const float* __restrict__ src, bf16* __restrict__ dh)
{
    const long long i4 = ((long long)blockIdx.x * 256 + threadIdx.x) * 4;
    float4 v = *(const float4*)(src + i4);
    *(uint2*)(dh + i4) = make_uint2(pack_f2(v.x, v.y), pack_f2(v.z, v.w));
}

__global__ void k_flags(const int* __restrict__ lang,
                        unsigned char* fF, unsigned char* fP1, unsigned char* fP2)
{
    if (threadIdx.x == 0 && blockIdx.x == 0) {
        for (int a = 0; a < NL; a++) {
            for (int j = 0; j < 8; j++) fF[a * 8 + j] = (lang[j] == a) ? 1 : 0;
            for (int p = 0; p < 4; p++)
                fP1[a * 4 + p] = fF[a * 8 + 2 * p] & fF[a * 8 + 2 * p + 1];
            for (int p = 0; p < 2; p++)
                fP2[a * 2 + p] = fP1[a * 4 + 2 * p] & fP1[a * 4 + 2 * p + 1];
        }
    }
}

__global__ __launch_bounds__(256) void k_factors(
    const float* __restrict__ alignT, const int* __restrict__ lang,
    bf16* __restrict__ Fh, bf16* __restrict__ FTh)
{
    const int node = blockIdx.y;
    const int a = node >> 3, j = node & 7;
    const int c = __ldg(&lang[j]);
    const long long nb = (long long)node * HH;
    const long long i4 = ((long long)blockIdx.x * 256 + threadIdx.x) * 4;
    const int r = (int)(i4 / Hd), col = (int)(i4 % Hd);

    if (c == a) {
        float v0 = (col + 0 == r) ? 1.f : 0.f;
        float v1 = (col + 1 == r) ? 1.f : 0.f;
        float v2 = (col + 2 == r) ? 1.f : 0.f;
        float v3 = (col + 3 == r) ? 1.f : 0.f;
        uint2 hv = make_uint2(pack_f2(v0, v1), pack_f2(v2, v3));
        *(uint2*)(Fh + nb + i4)  = hv;
        *(uint2*)(FTh + nb + i4) = hv;
    } else {
        const float* sm = alignT + (long long)(a * NL + c) * HH;
        float4 v = *(const float4*)(sm + i4);
        *(uint2*)(Fh + nb + i4) =
            make_uint2(pack_f2(v.x, v.y), pack_f2(v.z, v.w));
        float t0 = sm[(long long)(col + 0) * Hd + r];
        float t1 = sm[(long long)(col + 1) * Hd + r];
        float t2 = sm[(long long)(col + 2) * Hd + r];
        float t3 = sm[(long long)(col + 3) * Hd + r];
        *(uint2*)(FTh + nb + i4) =
            make_uint2(pack_f2(t0, t1), pack_f2(t2, t3));
    }
}

__global__ __launch_bounds__(256) void k_ln(
    const float* __restrict__ X, const float* __restrict__ Rres,
    const float* __restrict__ gam, const float* __restrict__ bet,
    float* __restrict__ out)
{
    const int row = blockIdx.x;
    const long long base = (long long)row * Hd;
    const int tid = threadIdx.x;

    float v[3];
    float s = 0.f, s2 = 0.f;
#pragma unroll
    for (int u = 0; u < 3; u++) {
        const int idx = tid + u * 256;
        const float val = X[base + idx] + Rres[base + idx];
        v[u] = val; s += val; s2 += val * val;
    }
#pragma unroll
    for (int off = 16; off >= 1; off >>= 1) {
        s  += __shfl_xor_sync(0xffffffffu, s, off);
        s2 += __shfl_xor_sync(0xffffffffu, s2, off);
    }
    __shared__ float ss[8], ss2[8], mv[2];
    const int wid = tid >> 5, lane = tid & 31;
    if (lane == 0) { ss[wid] = s; ss2[wid] = s2; }
    __syncthreads();
    if (tid == 0) {
        float S_ = 0.f, S2_ = 0.f;
        for (int w = 0; w < 8; w++) { S_ += ss[w]; S2_ += ss2[w]; }
        const float mean = S_ * (1.f / 768.f);
        const float var  = S2_ * (1.f / 768.f) - mean * mean;
        mv[0] = mean;
        mv[1] = rsqrtf(var + 1e-5f);
    }
    __syncthreads();
    const float mean = mv[0], rstd = mv[1];
#pragma unroll
    for (int u = 0; u < 3; u++) {
        const int idx = tid + u * 256;
        out[base + idx] = (v[u] - mean) * rstd * gam[idx] + bet[idx];
    }
}

// ---------------------------------------------------------------------------
// kernel_launch
// ---------------------------------------------------------------------------
#define SYM(v, s) cudaGetSymbolAddress((void**)&v, s)

extern "C" void kernel_launch(void* const* d_in, const int* in_sizes, int n_in,
                              void* d_out, int out_size)
{
    const float* hs      = (const float*)d_in[0];
    const int*   lang    = (const int*)  d_in[1];
    const float* Wq_lang = (const float*)d_in[3];
    const float* bq_lang = (const float*)d_in[4];
    const float* Wk_lang = (const float*)d_in[5];
    const float* bk_lang = (const float*)d_in[6];
    const float* in_w    = (const float*)d_in[7];
    const float* in_b    = (const float*)d_in[8];
    const float* out_w   = (const float*)d_in[9];
    const float* out_b   = (const float*)d_in[10];
    const float* alignT  = (const float*)d_in[11];
    const float* proj_w  = (const float*)d_in[12];
    const float* proj_b  = (const float*)d_in[13];
    const float* ln_g    = (const float*)d_in[14];
    const float* ln_b    = (const float*)d_in[15];
    float* out = (float*)d_out;

    float* obuf;
    SYM(obuf, g_o);

    bf16 *hs_h, *q_h, *k_h, *Qh, *Kh, *Vh, *ctx_h, *al_h, *al2_h;
    SYM(hs_h, g_hs_h); SYM(q_h, g_q_h); SYM(k_h, g_k_h);
    SYM(Qh, g_Qh); SYM(Kh, g_Kh); SYM(Vh, g_Vh);
    SYM(ctx_h, g_ctx_h); SYM(al_h, g_al_h); SYM(al2_h, g_al2_h);

    bf16 *Wq_h, *Wk_h, *inw_h, *ow_h, *pw_h;
    SYM(Wq_h, g_Wq_h); SYM(Wk_h, g_Wk_h);
    SYM(inw_h, g_inw_h); SYM(ow_h, g_ow_h); SYM(pw_h, g_pw_h);

    bf16 *F_h, *FT_h, *P1_h, *QT1_h, *P2_h, *QT2_h, *M_h, *MT_h;
    SYM(F_h, g_F_h);   SYM(FT_h, g_FT_h);
    SYM(P1_h, g_P1_h); SYM(QT1_h, g_QT1_h);
    SYM(P2_h, g_P2_h); SYM(QT2_h, g_QT2_h);
    SYM(M_h, g_M_h);   SYM(MT_h, g_MT_h);

    unsigned char *fF, *fP1, *fP2;
    SYM(fF, g_fF); SYM(fP1, g_fP1); SYM(fP2, g_fP2);

    cudaFuncSetAttribute(k_l1, cudaFuncAttributeMaxDynamicSharedMemorySize, GEMM_SMEM_FULL);
    cudaFuncSetAttribute(k_l2, cudaFuncAttributeMaxDynamicSharedMemorySize, GEMM_SMEM_FULL);
    cudaFuncSetAttribute(k_l3, cudaFuncAttributeMaxDynamicSharedMemorySize, GEMM_SMEM_FULL);
    cudaFuncSetAttribute(tc_gemm<0, 0>, cudaFuncAttributeMaxDynamicSharedMemorySize, GEMM_SMEM_FULL);
    cudaFuncSetAttribute(tc_gemm<1, 1>, cudaFuncAttributeMaxDynamicSharedMemorySize, GEMM_SMEM_FULL);
    cudaFuncSetAttribute(k_attn_tc, cudaFuncAttributeMaxDynamicSharedMemorySize, ATT_SMEM);

    const long long sBH = (long long)S * Hd;
    const dim3 thr(256);

    // conversions for L1
    k_conv<<<BS * Hd / 1024, thr>>>(hs, hs_h);
    k_conv<<<(int)(NL * HH / 1024), thr>>>(Wq_lang, Wq_h);
    k_conv<<<(int)(NL * HH / 1024), thr>>>(Wk_lang, Wk_h);
    // chain leaves
    k_flags<<<1, 32>>>(lang, fF, fP1, fP2);
    k_factors<<<dim3((int)(HH / 1024), NL * 8), thr>>>(alignT, lang, F_h, FT_h);

    // L1 = q/k lang projections + chain level 1
    k_l1<<<dim3(6, 6, 36), thr, GEMM_SMEM_FULL>>>(
        hs_h, Wq_h, Wk_h, bq_lang, bk_lang, lang, q_h, k_h,
        F_h, FT_h, fF, P1_h, QT1_h);

    // remaining conversions
    k_conv<<<(int)(3 * HH / 1024), thr>>>(in_w, inw_h);
    k_conv<<<(int)(HH / 1024), thr>>>(out_w, ow_h);
    k_conv<<<(int)(HH / 1024), thr>>>(proj_w, pw_h);

    // L2 = QKV + chain level 2
    k_l2<<<dim3(6, 6, 34), thr, GEMM_SMEM_FULL>>>(
        q_h, k_h, hs_h, inw_h, in_b, Qh, Kh, Vh,
        P1_h, QT1_h, fP1, P2_h, QT2_h);

    // attention
    k_attn_tc<<<dim3(S / 64, NH, Bsz), thr, ATT_SMEM>>>(Qh, Kh, Vh, ctx_h);

    // L3 = out_proj + chain level 3
    k_l3<<<dim3(6, 6, 13), thr, GEMM_SMEM_FULL>>>(
        ctx_h, ow_h, out_b, al_h, P2_h, QT2_h, fP2, M_h, MT_h);

    // aligned @ M[lang[b]]
    tc_gemm<1, 1><<<dim3(6, 6, Bsz), thr, GEMM_SMEM_FULL>>>(
        al_h, sBH, MT_h, nullptr, lang, nullptr, al2_h, sBH);

    // final proj (fp32 out)
    tc_gemm<0, 0><<<dim3(6, 48, 1), thr, GEMM_SMEM_FULL>>>(
        al2_h, 0, pw_h, proj_b, nullptr, obuf, nullptr, 0);

    // residual + LayerNorm
    k_ln<<<BS, thr>>>(obuf, hs, ln_g, ln_b, out);
}

// round 12
// speedup vs baseline: 4.2035x; 1.0064x over previous
#include <cuda_runtime.h>
#include <cuda_bf16.h>
#include <cstdint>

// ---------------------------------------------------------------------------
// Problem constants
// ---------------------------------------------------------------------------
constexpr int Bsz = 8;
constexpr int S   = 768;
constexpr int Hd  = 768;
constexpr int NH  = 12;
constexpr int NL  = 5;
constexpr int BS  = Bsz * S;
constexpr long long HH = (long long)Hd * Hd;

typedef __nv_bfloat16 bf16;

// ---------------------------------------------------------------------------
// Scratch (hi-only)
// ---------------------------------------------------------------------------
__device__ float g_o  [BS * Hd];

__device__ bf16 g_hs_h [BS * Hd];
__device__ bf16 g_q_h  [BS * Hd];
__device__ bf16 g_k_h  [BS * Hd];
__device__ bf16 g_Qh   [BS * Hd];
__device__ bf16 g_Kh   [BS * Hd];
__device__ bf16 g_Vh   [BS * Hd];
__device__ bf16 g_ctx_h[BS * Hd];
__device__ bf16 g_al_h [BS * Hd];

__device__ bf16 g_Wq_h [NL * Hd * Hd];
__device__ bf16 g_Wk_h [NL * Hd * Hd];
__device__ bf16 g_inw_h[3 * Hd * Hd];
__device__ bf16 g_ow_h [Hd * Hd];
__device__ bf16 g_pw_h [Hd * Hd];

__device__ bf16 g_F_h [NL * 8 * Hd * Hd];
__device__ bf16 g_FT_h[NL * 8 * Hd * Hd];
__device__ bf16 g_P1_h[NL * 4 * Hd * Hd];
__device__ bf16 g_QT1_h[NL * 4 * Hd * Hd];
__device__ bf16 g_P2_h[NL * 2 * Hd * Hd];
__device__ bf16 g_QT2_h[NL * 2 * Hd * Hd];
__device__ bf16 g_M_h [NL * Hd * Hd];
__device__ bf16 g_MT_h[NL * Hd * Hd];
__device__ bf16 g_GT_h[NL * Hd * Hd];

__device__ unsigned char g_fF [NL * 8];
__device__ unsigned char g_fP1[NL * 4];
__device__ unsigned char g_fP2[NL * 2];

// ---------------------------------------------------------------------------
// PTX helpers
// ---------------------------------------------------------------------------
__device__ __forceinline__ uint32_t smem_u32(const void* p) {
    return (uint32_t)__cvta_generic_to_shared(p);
}
__device__ __forceinline__ void cp16(uint32_t d, const void* s) {
    asm volatile("cp.async.cg.shared.global [%0], [%1], 16;"
                 :: "r"(d), "l"(s) : "memory");
}
__device__ __forceinline__ void cp_commit() {
    asm volatile("cp.async.commit_group;" ::: "memory");
}
template <int N>
__device__ __forceinline__ void cp_wait() {
    asm volatile("cp.async.wait_group %0;" :: "n"(N) : "memory");
}
__device__ __forceinline__ void ldsm4(uint32_t* r, uint32_t addr) {
    asm volatile("ldmatrix.sync.aligned.m8n8.x4.shared.b16 {%0,%1,%2,%3}, [%4];"
                 : "=r"(r[0]), "=r"(r[1]), "=r"(r[2]), "=r"(r[3]) : "r"(addr));
}
__device__ __forceinline__ void mma_bf16(float* d, const uint32_t* a,
                                         uint32_t b0, uint32_t b1) {
    asm volatile(
        "mma.sync.aligned.m16n8k16.row.col.f32.bf16.bf16.f32 "
        "{%0,%1,%2,%3}, {%4,%5,%6,%7}, {%8,%9}, {%0,%1,%2,%3};"
        : "+f"(d[0]), "+f"(d[1]), "+f"(d[2]), "+f"(d[3])
        : "r"(a[0]), "r"(a[1]), "r"(a[2]), "r"(a[3]), "r"(b0), "r"(b1));
}
__device__ __forceinline__ uint32_t pack_bf(bf16 a, bf16 b) {
    return (uint32_t)__bfloat16_as_ushort(a) |
           ((uint32_t)__bfloat16_as_ushort(b) << 16);
}
__device__ __forceinline__ uint32_t pack_f2(float a, float b) {
    return pack_bf(__float2bfloat16(a), __float2bfloat16(b));
}

// ---------------------------------------------------------------------------
// GEMM: 128x128 tile, BLK_K=32, 8 warps, 4-stage cp.async pipeline, hi-only.
// 4 stages x 20480 B = 81920 B/CTA -> still 2 CTAs/SM.
// ---------------------------------------------------------------------------
constexpr int SKP     = 40;
constexpr int TILE_B  = 128 * SKP * 2;       // 10240 B
constexpr int STAGE_B = 2 * TILE_B;          // 20480 B (A, W)
constexpr int NSTAGE  = 4;
constexpr int GEMM_SMEM_FULL = NSTAGE * STAGE_B;   // 81920 B (> epilogue 67584)

__device__ __forceinline__ void gemm_issue(
    const bf16* __restrict__ base, int lw, uint32_t sdst0, int kc)
{
    const bf16* g0 = base + kc * 32;
#pragma unroll
    for (int i = 0; i < 4; i++) {
        const int chunk = i * 128 + lw;
        const int row = chunk >> 2, cs = chunk & 3;
        cp16(sdst0 + row * (SKP * 2) + cs * 16,
             g0 + (long long)row * Hd + cs * 8);
    }
}

// MODE 0: fp32 out (+bias). MODE 1: bf16 out (+bias if non-null).
// MODE 2: bf16 out + transposed bf16 out (no bias).
template <int MODE>
__device__ void gemm_core(
    const bf16* __restrict__ A, const bf16* __restrict__ W,
    const float* __restrict__ bias,
    float* __restrict__ C, bf16* __restrict__ Ch, bf16* __restrict__ Th,
    int m0, int n0)
{
    extern __shared__ char dsm[];
    const int tid = threadIdx.x;
    const int wid = tid >> 5, lane = tid & 31;
    const int m_off = (wid & 3) * 32;
    const int n_off = (wid >> 2) * 64;
    const uint32_t sbase = smem_u32(dsm);

    const int ltile = tid >> 7;          // 0 = A, 1 = W
    const int lw = tid & 127;
    const bf16* gbase = (ltile == 0) ? A + (long long)m0 * Hd
                                     : W + (long long)n0 * Hd;
    const uint32_t sdst_tile = ltile * TILE_B;

    // prologue: chunks 0..2 into stages 0..2
#pragma unroll
    for (int p = 0; p < NSTAGE - 1; p++) {
        gemm_issue(gbase, lw, sbase + p * STAGE_B + sdst_tile, p);
        cp_commit();
    }

    float acc[2][8][4];
#pragma unroll
    for (int mi = 0; mi < 2; mi++)
#pragma unroll
        for (int j = 0; j < 8; j++)
#pragma unroll
            for (int e = 0; e < 4; e++) acc[mi][j][e] = 0.f;

    const int r_off = ((lane >> 3) & 1) * 8 + (lane & 7);
    const int c_off = (lane >> 4) * 8;

    for (int kc = 0; kc < 24; kc++) {
        cp_wait<NSTAGE - 2>();           // chunk kc ready (uniform commits)
        __syncthreads();
        const uint32_t sb = sbase + (kc & (NSTAGE - 1)) * STAGE_B;
        const uint32_t aA = sb + (m_off + r_off) * (SKP * 2) + c_off * 2;
        const uint32_t aW = sb + TILE_B + (n_off + r_off) * (SKP * 2) + c_off * 2;

#pragma unroll
        for (int kk = 0; kk < 2; kk++) {
            uint32_t ah[2][4];
#pragma unroll
            for (int t = 0; t < 2; t++)
                ldsm4(ah[t], aA + t * 16 * (SKP * 2) + kk * 32);
#pragma unroll
            for (int u = 0; u < 4; u++) {
                uint32_t bh[4];
                ldsm4(bh, aW + u * 16 * (SKP * 2) + kk * 32);
#pragma unroll
                for (int mi = 0; mi < 2; mi++) {
                    mma_bf16(acc[mi][2 * u],     ah[mi], bh[0], bh[2]);
                    mma_bf16(acc[mi][2 * u + 1], ah[mi], bh[1], bh[3]);
                }
            }
        }
        // issue chunk kc+3 into stage (kc+3)%4: its readers finished before
        // this iteration's top barrier.
        if (kc + NSTAGE - 1 < 24)
            gemm_issue(gbase, lw,
                       sbase + ((kc + NSTAGE - 1) & (NSTAGE - 1)) * STAGE_B + sdst_tile,
                       kc + NSTAGE - 1);
        cp_commit();                     // uniform commit keeps group count exact
    }
    __syncthreads();                     // all chunks consumed; tail groups empty

    // stage accumulators through SMEM (f32 [128][132] = 67584 B <= 81920)
    float* sf = (float*)dsm;
    const int g = lane >> 2, t2 = (lane & 3) * 2;
#pragma unroll
    for (int mi = 0; mi < 2; mi++)
#pragma unroll
        for (int j = 0; j < 8; j++) {
            const int r = m_off + mi * 16 + g;
            const int c = n_off + j * 8 + t2;
            sf[r * 132 + c]           = acc[mi][j][0];
            sf[r * 132 + c + 1]       = acc[mi][j][1];
            sf[(r + 8) * 132 + c]     = acc[mi][j][2];
            sf[(r + 8) * 132 + c + 1] = acc[mi][j][3];
        }
    __syncthreads();

    if (MODE == 0) {
#pragma unroll 4
        for (int i = 0; i < 16; i++) {
            const int task = i * 256 + tid;
            const int row = task >> 5, c4 = (task & 31) * 4;
            float4 v = *(float4*)&sf[row * 132 + c4];
            v.x += bias[n0 + c4 + 0];
            v.y += bias[n0 + c4 + 1];
            v.z += bias[n0 + c4 + 2];
            v.w += bias[n0 + c4 + 3];
            *(float4*)(C + (long long)(m0 + row) * Hd + n0 + c4) = v;
        }
    } else {
#pragma unroll 4
        for (int i = 0; i < 16; i++) {
            const int task = i * 256 + tid;
            const int row = task >> 5, c4 = (task & 31) * 4;
            float4 v = *(float4*)&sf[row * 132 + c4];
            if (MODE == 1 && bias) {
                v.x += bias[n0 + c4 + 0];
                v.y += bias[n0 + c4 + 1];
                v.z += bias[n0 + c4 + 2];
                v.w += bias[n0 + c4 + 3];
            }
            *(uint2*)(Ch + (long long)(m0 + row) * Hd + n0 + c4) =
                make_uint2(pack_f2(v.x, v.y), pack_f2(v.z, v.w));
        }
        if (MODE == 2) {
            const int c = tid & 127;
            const int half = tid >> 7;
#pragma unroll 4
            for (int i = 0; i < 16; i++) {
                const int r4 = half * 64 + i * 4;
                float v0 = sf[(r4 + 0) * 132 + c];
                float v1 = sf[(r4 + 1) * 132 + c];
                float v2 = sf[(r4 + 2) * 132 + c];
                float v3 = sf[(r4 + 3) * 132 + c];
                *(uint2*)(Th + (long long)(n0 + c) * Hd + m0 + r4) =
                    make_uint2(pack_f2(v0, v1), pack_f2(v2, v3));
            }
        }
    }
}

// ---------------------------------------------------------------------------
// Chain product block
// ---------------------------------------------------------------------------
__device__ void chain_work(
    int zz,
    const bf16* __restrict__ sN_h, const bf16* __restrict__ sT_h,
    const unsigned char* __restrict__ fs,
    bf16* __restrict__ dN_h, bf16* __restrict__ dT_h,
    int spa, int dpa)
{
    const int a = zz / dpa, p = zz - a * dpa;
    const int li = a * spa + 2 * p;
    const unsigned char f1 = fs[li], f2 = fs[li + 1];
    const long long zo = (long long)zz * HH;
    const int m0 = blockIdx.y * 128, n0 = blockIdx.x * 128;
    const int tid = threadIdx.x;

    if (f1 & f2) {
#pragma unroll 4
        for (int i = 0; i < 16; i++) {
            const int task = i * 256 + tid;
            const int row = task >> 5, c4 = (task & 31) * 4;
            const int gr = m0 + row, gc = n0 + c4;
            float v0 = (gc + 0 == gr) ? 1.f : 0.f;
            float v1 = (gc + 1 == gr) ? 1.f : 0.f;
            float v2 = (gc + 2 == gr) ? 1.f : 0.f;
            float v3 = (gc + 3 == gr) ? 1.f : 0.f;
            const long long off = zo + (long long)gr * Hd + gc;
            uint2 hv = make_uint2(pack_f2(v0, v1), pack_f2(v2, v3));
            *(uint2*)(dN_h + off) = hv;
            *(uint2*)(dT_h + off) = hv;
        }
        return;
    }
    if (f1 | f2) {
        const long long so = (long long)(f1 ? li + 1 : li) * HH;
#pragma unroll 4
        for (int i = 0; i < 8; i++) {
            const int idx = i * 256 + tid;
            const int row = idx >> 4, c8 = (idx & 15) * 8;
            const long long doff = zo + (long long)(m0 + row) * Hd + n0 + c8;
            const long long soff = so + (long long)(m0 + row) * Hd + n0 + c8;
            *(uint4*)(dN_h + doff) = *(const uint4*)(sN_h + soff);
            *(uint4*)(dT_h + doff) = *(const uint4*)(sT_h + soff);
        }
        return;
    }
    gemm_core<2>(sN_h + (long long)li * HH, sT_h + (long long)(li + 1) * HH,
                 nullptr, nullptr, dN_h + zo, dT_h + zo, m0, n0);
}

// ---------------------------------------------------------------------------
// Merged launches
// ---------------------------------------------------------------------------
__global__ __launch_bounds__(256, 2) void k_l1(
    const bf16* __restrict__ hs_h,
    const bf16* __restrict__ Wq_h, const bf16* __restrict__ Wk_h,
    const float* __restrict__ bq, const float* __restrict__ bk,
    const int* __restrict__ lang,
    bf16* __restrict__ q_h, bf16* __restrict__ k_h,
    const bf16* __restrict__ F_h, const bf16* __restrict__ FT_h,
    const unsigned char* __restrict__ fF,
    bf16* __restrict__ P1_h, bf16* __restrict__ QT1_h)
{
    const int z = blockIdx.z;
    if (z < 16) {
        const int fam = z >> 3, b = z & 7;
        const int lg = __ldg(&lang[b]);
        const long long ao = (long long)b * S * Hd;
        const bf16* wh = (fam ? Wk_h : Wq_h) + (long long)lg * HH;
        const float* bs = (fam ? bk : bq) + lg * Hd;
        bf16* oh = (fam ? k_h : q_h) + ao;
        gemm_core<1>(hs_h + ao, wh, bs, nullptr, oh, nullptr,
                     blockIdx.y * 128, blockIdx.x * 128);
    } else {
        chain_work(z - 16, F_h, FT_h, fF, P1_h, QT1_h, 8, 4);
    }
}

__global__ __launch_bounds__(256, 2) void k_l2(
    const bf16* __restrict__ q_h, const bf16* __restrict__ k_h,
    const bf16* __restrict__ hs_h,
    const bf16* __restrict__ inw_h, const float* __restrict__ in_b,
    bf16* __restrict__ Qh, bf16* __restrict__ Kh, bf16* __restrict__ Vh,
    const bf16* __restrict__ P1_h, const bf16* __restrict__ QT1_h,
    const unsigned char* __restrict__ fP1,
    bf16* __restrict__ P2_h, bf16* __restrict__ QT2_h)
{
    const int z = blockIdx.z;
    if (z < 24) {
        const int kind = z >> 3, b = z & 7;
        const long long ao = (long long)b * S * Hd;
        const bf16* ah;
        bf16* oh;
        if (kind == 0)      { ah = q_h;  oh = Qh; }
        else if (kind == 1) { ah = k_h;  oh = Kh; }
        else                { ah = hs_h; oh = Vh; }
        gemm_core<1>(ah + ao, inw_h + (long long)kind * HH, in_b + kind * Hd,
                     nullptr, oh + ao, nullptr,
                     blockIdx.y * 128, blockIdx.x * 128);
    } else {
        chain_work(z - 24, P1_h, QT1_h, fP1, P2_h, QT2_h, 4, 2);
    }
}

__global__ __launch_bounds__(256, 2) void k_l3(
    const bf16* __restrict__ ctx_h,
    const bf16* __restrict__ ow_h, const float* __restrict__ out_b,
    bf16* __restrict__ al_h,
    const bf16* __restrict__ P2_h, const bf16* __restrict__ QT2_h,
    const unsigned char* __restrict__ fP2,
    bf16* __restrict__ M_h, bf16* __restrict__ MT_h)
{
    const int z = blockIdx.z;
    if (z < 8) {
        const long long ao = (long long)z * S * Hd;
        gemm_core<1>(ctx_h + ao, ow_h, out_b, nullptr, al_h + ao, nullptr,
                     blockIdx.y * 128, blockIdx.x * 128);
    } else {
        chain_work(z - 8, P2_h, QT2_h, fP2, M_h, MT_h, 2, 1);
    }
}

// GT[l] = proj_w @ M[l]^T  (NT form: A=pw, W=M[l])   grid (6,6,NL)
__global__ __launch_bounds__(256, 2) void k_GT(
    const bf16* __restrict__ pw_h, const bf16* __restrict__ M_h,
    bf16* __restrict__ GT_h)
{
    const long long lo = (long long)blockIdx.z * HH;
    gemm_core<1>(pw_h, M_h + lo, nullptr, nullptr, GT_h + lo, nullptr,
                 blockIdx.y * 128, blockIdx.x * 128);
}

// final: out[b] = al[b] @ G[lang[b]] + proj_b   (W = GT[lang[b]])
__global__ __launch_bounds__(256, 2) void k_final(
    const bf16* __restrict__ al_h, const bf16* __restrict__ GT_h,
    const float* __restrict__ proj_b, const int* __restrict__ lang,
    float* __restrict__ C)
{
    const int z = blockIdx.z;
    const int lg = __ldg(&lang[z]);
    const long long ao = (long long)z * S * Hd;
    gemm_core<0>(al_h + ao, GT_h + (long long)lg * HH, proj_b,
                 C + ao, nullptr, nullptr,
                 blockIdx.y * 128, blockIdx.x * 128);
}

// ---------------------------------------------------------------------------
// Tensor-core flash attention, hi-only (unchanged from R11)
// ---------------------------------------------------------------------------
constexpr int AT_CHUNK = 64 * 80;
constexpr int AT_TILE  = 2 * AT_CHUNK;
constexpr int ATT_SMEM = 3 * AT_TILE;        // 30720 B

__global__ __launch_bounds__(256) void k_attn_tc(
    const bf16* __restrict__ Qg, const bf16* __restrict__ Kg,
    const bf16* __restrict__ Vg, bf16* __restrict__ Oh)
{
    extern __shared__ char dsm[];
    __shared__ float smax[4][2][16];
    __shared__ float larr[2][64];

    const int qt = blockIdx.x, h = blockIdx.y, b = blockIdx.z;
    const int tid = threadIdx.x;
    const int wid = tid >> 5, lane = tid & 31;
    const int wm = wid & 3, wn = wid >> 2;
    const int g = lane >> 2, t2 = (lane & 3) * 2;
    const int r_off = ((lane >> 3) & 1) * 8 + (lane & 7);
    const int c_off = (lane >> 4) * 8;

    const uint32_t sQ = smem_u32(dsm);
    const uint32_t sK = sQ + AT_TILE;
    const uint32_t sV = sQ + 2 * AT_TILE;
    unsigned short* vt16 = (unsigned short*)(dsm + 2 * AT_TILE);

    const long long qrow0 = (long long)(b * S + qt * 64);
    const int hoff = h * 64;

#pragma unroll
    for (int i = 0; i < 2; i++) {
        const int task = i * 256 + tid;
        const int row = task >> 3, rem = task & 7;
        const int chunk = rem >> 2, sub = rem & 3;
        cp16(sQ + chunk * AT_CHUNK + row * 80 + sub * 16,
             Qg + (qrow0 + row) * Hd + hoff + chunk * 32 + sub * 8);
    }
    cp_commit();

    float m0v = -1e30f, m1v = -1e30f, l0v = 0.f, l1v = 0.f;
    float ctx[8][4];
#pragma unroll
    for (int t = 0; t < 8; t++)
#pragma unroll
        for (int e = 0; e < 4; e++) ctx[t][e] = 0.f;

    for (int kt = 0; kt < 12; kt++) {
        __syncthreads();
        const long long krow0 = (long long)(b * S + kt * 64);
#pragma unroll
        for (int i = 0; i < 2; i++) {
            const int task = i * 256 + tid;
            const int row = task >> 3, rem = task & 7;
            const int chunk = rem >> 2, sub = rem & 3;
            cp16(sK + chunk * AT_CHUNK + row * 80 + sub * 16,
                 Kg + (krow0 + row) * Hd + hoff + chunk * 32 + sub * 8);
        }
        cp_commit();
#pragma unroll
        for (int i = 0; i < 8; i++) {
            const int task = i * 256 + tid;
            const int r = task >> 5;
            const int c2 = (task & 31) * 2;
            const uint32_t v2 = *(const uint32_t*)(Vg + (krow0 + r) * Hd + hoff + c2);
            const int base = (r >> 5) * 2560 + (r & 31);
            vt16[base + c2 * 40]       = (unsigned short)(v2 & 0xffff);
            vt16[base + (c2 + 1) * 40] = (unsigned short)(v2 >> 16);
        }
        cp_wait<0>();
        __syncthreads();

        float sacc[4][4];
#pragma unroll
        for (int t = 0; t < 4; t++)
#pragma unroll
            for (int e = 0; e < 4; e++) sacc[t][e] = 0.f;

#pragma unroll
        for (int c = 0; c < 2; c++) {
#pragma unroll
            for (int kk2 = 0; kk2 < 2; kk2++) {
                const uint32_t koff = c * AT_CHUNK + kk2 * 32;
                uint32_t qa[4];
                ldsm4(qa, sQ + koff + (wm * 16 + r_off) * 80 + c_off * 2);
#pragma unroll
                for (int u = 0; u < 2; u++) {
                    uint32_t kb[4];
                    ldsm4(kb, sK + koff + (wn * 32 + u * 16 + r_off) * 80 + c_off * 2);
                    mma_bf16(sacc[u * 2],     qa, kb[0], kb[2]);
                    mma_bf16(sacc[u * 2 + 1], qa, kb[1], kb[3]);
                }
            }
        }
#pragma unroll
        for (int t = 0; t < 4; t++)
#pragma unroll
            for (int e = 0; e < 4; e++) sacc[t][e] *= 0.125f;

        float rm0 = -1e30f, rm1 = -1e30f;
#pragma unroll
        for (int t = 0; t < 4; t++) {
            rm0 = fmaxf(rm0, fmaxf(sacc[t][0], sacc[t][1]));
            rm1 = fmaxf(rm1, fmaxf(sacc[t][2], sacc[t][3]));
        }
        rm0 = fmaxf(rm0, __shfl_xor_sync(0xffffffffu, rm0, 1));
        rm0 = fmaxf(rm0, __shfl_xor_sync(0xffffffffu, rm0, 2));
        rm1 = fmaxf(rm1, __shfl_xor_sync(0xffffffffu, rm1, 1));
        rm1 = fmaxf(rm1, __shfl_xor_sync(0xffffffffu, rm1, 2));
        if ((lane & 3) == 0) {
            smax[wm][wn][g]     = rm0;
            smax[wm][wn][g + 8] = rm1;
        }
        __syncthreads();
        rm0 = fmaxf(rm0, smax[wm][wn ^ 1][g]);
        rm1 = fmaxf(rm1, smax[wm][wn ^ 1][g + 8]);

        const float mn0 = fmaxf(m0v, rm0);
        const float mn1 = fmaxf(m1v, rm1);
        const float a0 = __expf(m0v - mn0);
        const float a1 = __expf(m1v - mn1);
        m0v = mn0; m1v = mn1;

        float rs0 = 0.f, rs1 = 0.f;
#pragma unroll
        for (int t = 0; t < 4; t++) {
            sacc[t][0] = __expf(sacc[t][0] - mn0);
            sacc[t][1] = __expf(sacc[t][1] - mn0);
            sacc[t][2] = __expf(sacc[t][2] - mn1);
            sacc[t][3] = __expf(sacc[t][3] - mn1);
            rs0 += sacc[t][0] + sacc[t][1];
            rs1 += sacc[t][2] + sacc[t][3];
        }
        rs0 += __shfl_xor_sync(0xffffffffu, rs0, 1);
        rs0 += __shfl_xor_sync(0xffffffffu, rs0, 2);
        rs1 += __shfl_xor_sync(0xffffffffu, rs1, 1);
        rs1 += __shfl_xor_sync(0xffffffffu, rs1, 2);
        l0v = l0v * a0 + rs0;
        l1v = l1v * a1 + rs1;
#pragma unroll
        for (int t = 0; t < 8; t++) {
            ctx[t][0] *= a0; ctx[t][1] *= a0;
            ctx[t][2] *= a1; ctx[t][3] *= a1;
        }

        uint32_t pah[2][4];
#pragma unroll
        for (int kk2 = 0; kk2 < 2; kk2++) {
#pragma unroll
            for (int half = 0; half < 2; half++) {
                const int tt = 2 * kk2 + half;
                pah[kk2][half * 2 + 0] = pack_f2(sacc[tt][0], sacc[tt][1]);
                pah[kk2][half * 2 + 1] = pack_f2(sacc[tt][2], sacc[tt][3]);
            }
        }

#pragma unroll
        for (int kk2 = 0; kk2 < 2; kk2++) {
            const uint32_t voff = wn * AT_CHUNK + kk2 * 32;
#pragma unroll
            for (int u = 0; u < 4; u++) {
                uint32_t vb[4];
                ldsm4(vb, sV + voff + (u * 16 + r_off) * 80 + c_off * 2);
                mma_bf16(ctx[u * 2],     pah[kk2], vb[0], vb[2]);
                mma_bf16(ctx[u * 2 + 1], pah[kk2], vb[1], vb[3]);
            }
        }
    }

    __syncthreads();
    float* csum = (float*)(dsm + AT_TILE);
    if (wn == 1) {
#pragma unroll
        for (int t = 0; t < 8; t++) {
            const int u = t >> 1, v = t & 1;
            const int colb = u * 16 + v * 8 + t2;
            csum[(wm * 16 + g) * 68 + colb]         = ctx[t][0];
            csum[(wm * 16 + g) * 68 + colb + 1]     = ctx[t][1];
            csum[(wm * 16 + g + 8) * 68 + colb]     = ctx[t][2];
            csum[(wm * 16 + g + 8) * 68 + colb + 1] = ctx[t][3];
        }
    }
    if ((lane & 3) == 0) {
        larr[wn][wm * 16 + g]     = l0v;
        larr[wn][wm * 16 + g + 8] = l1v;
    }
    __syncthreads();
    if (wn == 0) {
#pragma unroll
        for (int t = 0; t < 8; t++) {
            const int u = t >> 1, v = t & 1;
            const int colb = u * 16 + v * 8 + t2;
            csum[(wm * 16 + g) * 68 + colb]         += ctx[t][0];
            csum[(wm * 16 + g) * 68 + colb + 1]     += ctx[t][1];
            csum[(wm * 16 + g + 8) * 68 + colb]     += ctx[t][2];
            csum[(wm * 16 + g + 8) * 68 + colb + 1] += ctx[t][3];
        }
    }
    __syncthreads();
#pragma unroll
    for (int i = 0; i < 4; i++) {
        const int idx = i * 256 + tid;
        const int row = idx >> 4, c4 = (idx & 15) * 4;
        const float inv = 1.f / (larr[0][row] + larr[1][row]);
        float4 v = *(float4*)&csum[row * 68 + c4];
        *(uint2*)(Oh + (qrow0 + row) * Hd + hoff + c4) =
            make_uint2(pack_f2(v.x * inv, v.y * inv),
                       pack_f2(v.z * inv, v.w * inv));
    }
}

// ---------------------------------------------------------------------------
// conversions / chain leaves / LN
// ---------------------------------------------------------------------------
__global__ __launch_bounds__(256) void k_conv(
    const float* __restrict__ src, bf16* __restrict__ dh)
{
    const long long i4 = ((long long)blockIdx.x * 256 + threadIdx.x) * 4;
    float4 v = *(const float4*)(src + i4);
    *(uint2*)(dh + i4) = make_uint2(pack_f2(v.x, v.y), pack_f2(v.z, v.w));
}

__global__ void k_flags(const int* __restrict__ lang,
                        unsigned char* fF, unsigned char* fP1, unsigned char* fP2)
{
    if (threadIdx.x == 0 && blockIdx.x == 0) {
        for (int a = 0; a < NL; a++) {
            for (int j = 0; j < 8; j++) fF[a * 8 + j] = (lang[j] == a) ? 1 : 0;
            for (int p = 0; p < 4; p++)
                fP1[a * 4 + p] = fF[a * 8 + 2 * p] & fF[a * 8 + 2 * p + 1];
            for (int p = 0; p < 2; p++)
                fP2[a * 2 + p] = fP1[a * 4 + 2 * p] & fP1[a * 4 + 2 * p + 1];
        }
    }
}

__global__ __launch_bounds__(256) void k_factors(
    const float* __restrict__ alignT, const int* __restrict__ lang,
    bf16* __restrict__ Fh, bf16* __restrict__ FTh)
{
    const int node = blockIdx.y;
    const int a = node >> 3, j = node & 7;
    const int c = __ldg(&lang[j]);
    const long long nb = (long long)node * HH;
    const long long i4 = ((long long)blockIdx.x * 256 + threadIdx.x) * 4;
    const int r = (int)(i4 / Hd), col = (int)(i4 % Hd);

    if (c == a) {
        float v0 = (col + 0 == r) ? 1.f : 0.f;
        float v1 = (col + 1 == r) ? 1.f : 0.f;
        float v2 = (col + 2 == r) ? 1.f : 0.f;
        float v3 = (col + 3 == r) ? 1.f : 0.f;
        uint2 hv = make_uint2(pack_f2(v0, v1), pack_f2(v2, v3));
        *(uint2*)(Fh + nb + i4)  = hv;
        *(uint2*)(FTh + nb + i4) = hv;
    } else {
        const float* sm = alignT + (long long)(a * NL + c) * HH;
        float4 v = *(const float4*)(sm + i4);
        *(uint2*)(Fh + nb + i4) =
            make_uint2(pack_f2(v.x, v.y), pack_f2(v.z, v.w));
        float t0 = sm[(long long)(col + 0) * Hd + r];
        float t1 = sm[(long long)(col + 1) * Hd + r];
        float t2 = sm[(long long)(col + 2) * Hd + r];
        float t3 = sm[(long long)(col + 3) * Hd + r];
        *(uint2*)(FTh + nb + i4) =
            make_uint2(pack_f2(t0, t1), pack_f2(t2, t3));
    }
}

__global__ __launch_bounds__(256) void k_ln(
    const float* __restrict__ X, const float* __restrict__ Rres,
    const float* __restrict__ gam, const float* __restrict__ bet,
    float* __restrict__ out)
{
    const int row = blockIdx.x;
    const long long base = (long long)row * Hd;
    const int tid = threadIdx.x;

    float v[3];
    float s = 0.f, s2 = 0.f;
#pragma unroll
    for (int u = 0; u < 3; u++) {
        const int idx = tid + u * 256;
        const float val = X[base + idx] + Rres[base + idx];
        v[u] = val; s += val; s2 += val * val;
    }
#pragma unroll
    for (int off = 16; off >= 1; off >>= 1) {
        s  += __shfl_xor_sync(0xffffffffu, s, off);
        s2 += __shfl_xor_sync(0xffffffffu, s2, off);
    }
    __shared__ float ss[8], ss2[8], mv[2];
    const int wid = tid >> 5, lane = tid & 31;
    if (lane == 0) { ss[wid] = s; ss2[wid] = s2; }
    __syncthreads();
    if (tid == 0) {
        float S_ = 0.f, S2_ = 0.f;
        for (int w = 0; w < 8; w++) { S_ += ss[w]; S2_ += ss2[w]; }
        const float mean = S_ * (1.f / 768.f);
        const float var  = S2_ * (1.f / 768.f) - mean * mean;
        mv[0] = mean;
        mv[1] = rsqrtf(var + 1e-5f);
    }
    __syncthreads();
    const float mean = mv[0], rstd = mv[1];
#pragma unroll
    for (int u = 0; u < 3; u++) {
        const int idx = tid + u * 256;
        out[base + idx] = (v[u] - mean) * rstd * gam[idx] + bet[idx];
    }
}

// ---------------------------------------------------------------------------
// kernel_launch
// ---------------------------------------------------------------------------
#define SYM(v, s) cudaGetSymbolAddress((void**)&v, s)

extern "C" void kernel_launch(void* const* d_in, const int* in_sizes, int n_in,
                              void* d_out, int out_size)
{
    const float* hs      = (const float*)d_in[0];
    const int*   lang    = (const int*)  d_in[1];
    const float* Wq_lang = (const float*)d_in[3];
    const float* bq_lang = (const float*)d_in[4];
    const float* Wk_lang = (const float*)d_in[5];
    const float* bk_lang = (const float*)d_in[6];
    const float* in_w    = (const float*)d_in[7];
    const float* in_b    = (const float*)d_in[8];
    const float* out_w   = (const float*)d_in[9];
    const float* out_b   = (const float*)d_in[10];
    const float* alignT  = (const float*)d_in[11];
    const float* proj_w  = (const float*)d_in[12];
    const float* proj_b  = (const float*)d_in[13];
    const float* ln_g    = (const float*)d_in[14];
    const float* ln_b    = (const float*)d_in[15];
    float* out = (float*)d_out;

    float* obuf;
    SYM(obuf, g_o);

    bf16 *hs_h, *q_h, *k_h, *Qh, *Kh, *Vh, *ctx_h, *al_h;
    SYM(hs_h, g_hs_h); SYM(q_h, g_q_h); SYM(k_h, g_k_h);
    SYM(Qh, g_Qh); SYM(Kh, g_Kh); SYM(Vh, g_Vh);
    SYM(ctx_h, g_ctx_h); SYM(al_h, g_al_h);

    bf16 *Wq_h, *Wk_h, *inw_h, *ow_h, *pw_h;
    SYM(Wq_h, g_Wq_h); SYM(Wk_h, g_Wk_h);
    SYM(inw_h, g_inw_h); SYM(ow_h, g_ow_h); SYM(pw_h, g_pw_h);

    bf16 *F_h, *FT_h, *P1_h, *QT1_h, *P2_h, *QT2_h, *M_h, *MT_h, *GT_h;
    SYM(F_h, g_F_h);   SYM(FT_h, g_FT_h);
    SYM(P1_h, g_P1_h); SYM(QT1_h, g_QT1_h);
    SYM(P2_h, g_P2_h); SYM(QT2_h, g_QT2_h);
    SYM(M_h, g_M_h);   SYM(MT_h, g_MT_h);
    SYM(GT_h, g_GT_h);

    unsigned char *fF, *fP1, *fP2;
    SYM(fF, g_fF); SYM(fP1, g_fP1); SYM(fP2, g_fP2);

    cudaFuncSetAttribute(k_l1,    cudaFuncAttributeMaxDynamicSharedMemorySize, GEMM_SMEM_FULL);
    cudaFuncSetAttribute(k_l2,    cudaFuncAttributeMaxDynamicSharedMemorySize, GEMM_SMEM_FULL);
    cudaFuncSetAttribute(k_l3,    cudaFuncAttributeMaxDynamicSharedMemorySize, GEMM_SMEM_FULL);
    cudaFuncSetAttribute(k_GT,    cudaFuncAttributeMaxDynamicSharedMemorySize, GEMM_SMEM_FULL);
    cudaFuncSetAttribute(k_final, cudaFuncAttributeMaxDynamicSharedMemorySize, GEMM_SMEM_FULL);
    cudaFuncSetAttribute(k_attn_tc, cudaFuncAttributeMaxDynamicSharedMemorySize, ATT_SMEM);

    const dim3 thr(256);

    // conversions for L1
    k_conv<<<BS * Hd / 1024, thr>>>(hs, hs_h);
    k_conv<<<(int)(NL * HH / 1024), thr>>>(Wq_lang, Wq_h);
    k_conv<<<(int)(NL * HH / 1024), thr>>>(Wk_lang, Wk_h);
    // chain leaves
    k_flags<<<1, 32>>>(lang, fF, fP1, fP2);
    k_factors<<<dim3((int)(HH / 1024), NL * 8), thr>>>(alignT, lang, F_h, FT_h);

    // L1 = q/k lang projections + chain level 1
    k_l1<<<dim3(6, 6, 36), thr, GEMM_SMEM_FULL>>>(
        hs_h, Wq_h, Wk_h, bq_lang, bk_lang, lang, q_h, k_h,
        F_h, FT_h, fF, P1_h, QT1_h);

    // remaining conversions
    k_conv<<<(int)(3 * HH / 1024), thr>>>(in_w, inw_h);
    k_conv<<<(int)(HH / 1024), thr>>>(out_w, ow_h);
    k_conv<<<(int)(HH / 1024), thr>>>(proj_w, pw_h);

    // L2 = QKV + chain level 2
    k_l2<<<dim3(6, 6, 34), thr, GEMM_SMEM_FULL>>>(
        q_h, k_h, hs_h, inw_h, in_b, Qh, Kh, Vh,
        P1_h, QT1_h, fP1, P2_h, QT2_h);

    // attention
    k_attn_tc<<<dim3(S / 64, NH, Bsz), thr, ATT_SMEM>>>(Qh, Kh, Vh, ctx_h);

    // L3 = out_proj + chain level 3
    k_l3<<<dim3(6, 6, 13), thr, GEMM_SMEM_FULL>>>(
        ctx_h, ow_h, out_b, al_h, P2_h, QT2_h, fP2, M_h, MT_h);

    // GT[l] = proj_w @ M[l]^T
    k_GT<<<dim3(6, 6, NL), thr, GEMM_SMEM_FULL>>>(pw_h, M_h, GT_h);

    // fused final: out = al @ G[lang] + proj_b  (fp32)
    k_final<<<dim3(6, 6, Bsz), thr, GEMM_SMEM_FULL>>>(al_h, GT_h, proj_b, lang, obuf);

    // residual + LayerNorm
    k_ln<<<BS, thr>>>(obuf, hs, ln_g, ln_b, out);
}